// round 5
// baseline (speedup 1.0000x reference)
#include <cuda_runtime.h>
#include <cuda_bf16.h>
#include <math.h>

// ---------------- problem constants ----------------
#define NIMG 4        // (map m, batch b) -> img = m*2+b
#define LTOK 9216     // 96*96
#define D 256
#define NH 8
#define HD 32
#define WGRID 12      // 96/8
#define NWIN 144
#define WTOK 64
#define KSEL 8
#define CN 16

// ---------------- scratch (device globals; no allocation allowed) ----------
__device__ float g_phi_q[NIMG*LTOK*D];
__device__ float g_phi_k[NIMG*LTOK*D];
__device__ float g_v    [NIMG*LTOK*D];
__device__ float g_msg  [NIMG*LTOK*D];
__device__ float g_msg2 [NIMG*LTOK*D];
__device__ float g_hcat [NIMG*LTOK*2*D];
__device__ float g_hid  [NIMG*LTOK*2*D];
__device__ float g_rep  [NIMG*NWIN*D];
__device__ float g_repn [NIMG*NWIN*D];
__device__ float g_phikr[NIMG*NWIN*D];
__device__ float g_vr   [NIMG*NWIN*D];
__device__ float g_sim  [NIMG*NWIN*NWIN];
__device__ int   g_sel  [NIMG*NWIN*KSEL];
__device__ float g_KVwin[NIMG*NWIN*NH*HD*HD];
__device__ float g_kswin[NIMG*NWIN*D];
__device__ float g_KVtot[NIMG*NH*HD*HD];
__device__ float g_kstot[NIMG*D];

// ---------------- helpers ----------------
__device__ __forceinline__ float phi(float x){ return x > 0.f ? x + 1.f : expf(x); }

__device__ __forceinline__ float blockReduceSum(float val, float* sbuf){
  __syncthreads();
  int lane = threadIdx.x & 31, wid = threadIdx.x >> 5;
  #pragma unroll
  for (int o = 16; o; o >>= 1) val += __shfl_down_sync(0xffffffffu, val, o);
  if (lane == 0) sbuf[wid] = val;
  __syncthreads();
  float r = (threadIdx.x < (blockDim.x >> 5)) ? sbuf[threadIdx.x] : 0.f;
  if (wid == 0){
    #pragma unroll
    for (int o = 16; o; o >>= 1) r += __shfl_down_sync(0xffffffffu, r, o);
    if (lane == 0) sbuf[0] = r;
  }
  __syncthreads();
  return sbuf[0];
}

__device__ __forceinline__ int spatial_l(int win, int t){
  int wy = win / WGRID, wx = win % WGRID;
  return (wy*8 + (t >> 3))*96 + wx*8 + (t & 7);
}

// ---------------- 1) per-window rep (sim->softmax->avg->rep, + normalized) --
__global__ void __launch_bounds__(256) k_rep(const float* __restrict__ f0,
                                             const float* __restrict__ f1,
                                             const float* __restrict__ conv_w){
  int img = blockIdx.x / NWIN, win = blockIdx.x % NWIN;
  int m = img >> 1, b = img & 1;
  const float* F = (m ? f1 : f0) + (size_t)b*LTOK*D;
  __shared__ float cw[CN*D];          // 16KB
  __shared__ float simall[WTOK*CN];   // 4KB
  __shared__ float avg[CN];
  __shared__ float red[32];
  int tid = threadIdx.x;
  for (int i = tid; i < CN*D; i += 256) cw[i] = conv_w[i];
  __syncthreads();
  int warp = tid >> 5, lane = tid & 31;
  // each warp handles 8 tokens; computes 16 dot products of length 256
  for (int p = 0; p < 8; p++){
    int t = warp + p*8;
    int l = spatial_l(win, t);
    const float* fr = F + (size_t)l*D;
    float fv[8];
    #pragma unroll
    for (int i = 0; i < 8; i++) fv[i] = fr[lane + 32*i];
    for (int c = 0; c < CN; c++){
      float s = 0.f;
      #pragma unroll
      for (int i = 0; i < 8; i++) s += fv[i]*cw[c*D + lane + 32*i];
      #pragma unroll
      for (int o = 16; o; o >>= 1) s += __shfl_down_sync(0xffffffffu, s, o);
      if (lane == 0) simall[t*CN + c] = s;
    }
  }
  __syncthreads();
  if (tid < WTOK){ // softmax over channels per token
    float mx = -1e30f;
    for (int c = 0; c < CN; c++) mx = fmaxf(mx, simall[tid*CN + c]);
    float s = 0.f, e[CN];
    for (int c = 0; c < CN; c++){ e[c] = expf(simall[tid*CN + c] - mx); s += e[c]; }
    float inv = 1.f/s;
    for (int c = 0; c < CN; c++) simall[tid*CN + c] = e[c]*inv;
  }
  __syncthreads();
  if (tid < CN){
    float s = 0.f;
    for (int t = 0; t < WTOK; t++) s += simall[t*CN + tid];
    avg[tid] = s * (1.f/WTOK);
  }
  __syncthreads();
  float r = 0.f;
  for (int c = 0; c < CN; c++) r += avg[c]*cw[c*D + tid];
  g_rep[(size_t)(img*NWIN + win)*D + tid] = r;
  float n2 = blockReduceSum(r*r, red);
  float nrm = fmaxf(sqrtf(n2), 1e-8f);
  g_repn[(size_t)(img*NWIN + win)*D + tid] = r / nrm;
}

// ---------------- 2) cosine sim matrices ----------------
__global__ void k_cossim(int npairs, int self){
  long total = (long)npairs*NWIN*NWIN;
  for (long idx = (long)blockIdx.x*blockDim.x + threadIdx.x; idx < total;
       idx += (long)gridDim.x*blockDim.x){
    int p = (int)(idx/(NWIN*NWIN)); int rem = (int)(idx%(NWIN*NWIN));
    int q = rem/NWIN, s = rem%NWIN;
    const float* a = &g_repn[((size_t)p*NWIN + q)*D];
    const float* bb = self ? &g_repn[((size_t)p*NWIN + s)*D]
                           : &g_repn[(((size_t)(2+p))*NWIN + s)*D];
    float acc = 0.f;
    #pragma unroll 4
    for (int k = 0; k < D; k += 4){
      float4 av = *(const float4*)&a[k];
      float4 bv = *(const float4*)&bb[k];
      acc += av.x*bv.x + av.y*bv.y + av.z*bv.z + av.w*bv.w;
    }
    g_sim[idx] = acc;
  }
}

// ---------------- 3) top-K (stable, lower index first on ties) --------------
__global__ void k_topk(int self){
  int idx = blockIdx.x*blockDim.x + threadIdx.x;
  if (idx >= NIMG*NWIN) return;
  int img = idx/NWIN, q = idx%NWIN;
  size_t base; int sq, ss;
  if (self){ base = (size_t)img*NWIN*NWIN; sq = NWIN; ss = 1; }
  else {
    int b = img & 1, m = img >> 1;
    base = (size_t)b*NWIN*NWIN;
    if (m == 0){ sq = NWIN; ss = 1; } else { sq = 1; ss = NWIN; }
  }
  const float* S = g_sim + base + (size_t)q*sq;
  float vals[NWIN];
  for (int s = 0; s < NWIN; s++) vals[s] = S[(size_t)s*ss];
  for (int k = 0; k < KSEL; k++){
    float best = -1e30f; int bi = 0;
    for (int s = 0; s < NWIN; s++) if (vals[s] > best){ best = vals[s]; bi = s; }
    g_sel[idx*KSEL + k] = bi;
    vals[bi] = -1e30f;
  }
}

// ---------------- 4) rep k/v projection (+phi on k) ----------------
__global__ void __launch_bounds__(256) k_repproj(const float* __restrict__ kW,
                                                 const float* __restrict__ vW){
  int rr = blockIdx.x;
  __shared__ float rrow[D];
  int tid = threadIdx.x;
  rrow[tid] = g_rep[(size_t)rr*D + tid];
  __syncthreads();
  const float* kwr = kW + (size_t)tid*D;
  const float* vwr = vW + (size_t)tid*D;
  float ka = 0.f, va = 0.f;
  #pragma unroll 4
  for (int i = 0; i < D; i += 4){
    float4 rv = *(float4*)&rrow[i];
    float4 kv = *(const float4*)&kwr[i];
    float4 vv = *(const float4*)&vwr[i];
    ka += rv.x*kv.x + rv.y*kv.y + rv.z*kv.z + rv.w*kv.w;
    va += rv.x*vv.x + rv.y*vv.y + rv.z*vv.z + rv.w*vv.w;
  }
  g_phikr[(size_t)rr*D + tid] = phi(ka);
  g_vr[(size_t)rr*D + tid] = va;
}

// ---------------- 5) totals over all 144 rep rows ----------------
__global__ void __launch_bounds__(256) k_reptot(){
  int img = blockIdx.x >> 3, h = blockIdx.x & 7;
  __shared__ float pk[NWIN*HD]; // 18KB
  __shared__ float vv[NWIN*HD]; // 18KB
  int tid = threadIdx.x;
  for (int i = tid; i < NWIN*HD; i += 256){
    int r = i/HD, d = i%HD;
    size_t off = ((size_t)img*NWIN + r)*D + h*HD + d;
    pk[i] = g_phikr[off]; vv[i] = g_vr[off];
  }
  __syncthreads();
  for (int o = tid; o < HD*HD; o += 256){
    int d = o/HD, j = o%HD;
    float s = 0.f;
    for (int r = 0; r < NWIN; r++) s += pk[r*HD + d]*vv[r*HD + j];
    g_KVtot[((size_t)img*NH + h)*HD*HD + o] = s;
  }
  if (tid < HD){
    float s = 0.f;
    for (int r = 0; r < NWIN; r++) s += pk[r*HD + tid];
    g_kstot[(size_t)img*D + h*HD + tid] = s;
  }
}

// ---------------- generic SGEMM: C = act(A[MxK] @ B[NxK]^T) -----------------
template<int ACT>
__device__ __forceinline__ float actf(float x){
  if (ACT == 1) return x > 0.f ? x + 1.f : expf(x); // phi = elu + 1
  if (ACT == 2) return fmaxf(x, 0.f);               // relu
  return x;
}

template<int ACT>
__global__ void __launch_bounds__(256) sgemm_nt(const float* __restrict__ A,
                                                const float* __restrict__ B,
                                                float* __restrict__ C,
                                                int M, int N, int K){
  __shared__ float As[8][128];
  __shared__ float Bs[8][128];
  int bm = blockIdx.y*128, bn = blockIdx.x*128;
  int tid = threadIdx.x;
  int ty = tid >> 4, tx = tid & 15;
  int lr = tid >> 1, lk = (tid & 1)*4;
  float acc[8][8];
  #pragma unroll
  for (int i = 0; i < 8; i++)
    #pragma unroll
    for (int j = 0; j < 8; j++) acc[i][j] = 0.f;
  bool aval = (bm + lr) < M;
  const float* Aptr = A + (size_t)(bm + lr)*K + lk;
  const float* Bptr = B + (size_t)(bn + lr)*K + lk;
  for (int k0 = 0; k0 < K; k0 += 8){
    float4 av = aval ? *(const float4*)(Aptr + k0) : make_float4(0,0,0,0);
    float4 bv = *(const float4*)(Bptr + k0);
    As[lk+0][lr] = av.x; As[lk+1][lr] = av.y; As[lk+2][lr] = av.z; As[lk+3][lr] = av.w;
    Bs[lk+0][lr] = bv.x; Bs[lk+1][lr] = bv.y; Bs[lk+2][lr] = bv.z; Bs[lk+3][lr] = bv.w;
    __syncthreads();
    #pragma unroll
    for (int kk = 0; kk < 8; kk++){
      float ar[8], br[8];
      #pragma unroll
      for (int i = 0; i < 8; i++) ar[i] = As[kk][ty*8 + i];
      #pragma unroll
      for (int j = 0; j < 8; j++) br[j] = Bs[kk][tx*8 + j];
      #pragma unroll
      for (int i = 0; i < 8; i++)
        #pragma unroll
        for (int j = 0; j < 8; j++) acc[i][j] += ar[i]*br[j];
    }
    __syncthreads();
  }
  #pragma unroll
  for (int i = 0; i < 8; i++){
    int mrow = bm + ty*8 + i;
    if (mrow < M){
      #pragma unroll
      for (int j = 0; j < 8; j++)
        C[(size_t)mrow*N + bn + tx*8 + j] = actf<ACT>(acc[i][j]);
    }
  }
}

// ---------------- 6) per-window KV/ksum aggregates ----------------
__global__ void __launch_bounds__(256) k_winagg(){
  int bid = blockIdx.x;
  int h = bid & 7; int wv = bid >> 3;
  int win = wv % NWIN, img = wv / NWIN;
  __shared__ float pk[WTOK*HD]; // 8KB
  __shared__ float vv[WTOK*HD]; // 8KB
  int tid = threadIdx.x;
  for (int i = tid; i < WTOK*HD; i += 256){
    int t = i/HD, d = i%HD;
    int l = spatial_l(win, t);
    size_t off = ((size_t)img*LTOK + l)*D + h*HD + d;
    pk[i] = g_phi_k[off]; vv[i] = g_v[off];
  }
  __syncthreads();
  for (int o = tid; o < HD*HD; o += 256){
    int d = o/HD, j = o%HD;
    float s = 0.f;
    #pragma unroll 8
    for (int t = 0; t < WTOK; t++) s += pk[t*HD + d]*vv[t*HD + j];
    g_KVwin[(((size_t)(img*NWIN + win))*NH + h)*HD*HD + o] = s;
  }
  if (tid < HD){
    float s = 0.f;
    for (int t = 0; t < WTOK; t++) s += pk[t*HD + tid];
    g_kswin[((size_t)img*NWIN + win)*D + h*HD + tid] = s;
  }
}

// ---------------- 7) attention: build per-query-window KV, apply ------------
__global__ void __launch_bounds__(256) k_attn(int layer){
  int img = blockIdx.x / NWIN, q = blockIdx.x % NWIN;
  int src = (layer == 0) ? img : (img ^ 2); // cross: flip map, keep batch
  __shared__ float KV[NH*HD*HD]; // 32KB
  __shared__ float ks[D];
  __shared__ float buf[2*D];
  __shared__ float pq[D];
  int tid = threadIdx.x;
  for (int i = tid; i < NH*HD*HD; i += 256) KV[i] = g_KVtot[(size_t)src*NH*HD*HD + i];
  ks[tid] = g_kstot[(size_t)src*D + tid];
  __syncthreads();
  for (int k = 0; k < KSEL; k++){
    int w = g_sel[(img*NWIN + q)*KSEL + k];
    buf[tid]     = g_phikr[((size_t)src*NWIN + w)*D + tid];
    buf[D + tid] = g_vr   [((size_t)src*NWIN + w)*D + tid];
    __syncthreads();
    const float* KVW = &g_KVwin[((size_t)(src*NWIN + w))*NH*HD*HD];
    for (int i = tid; i < NH*HD*HD; i += 256){
      int h = i >> 10, d = (i >> 5) & 31, j = i & 31;
      KV[i] += KVW[i] - buf[h*HD + d]*buf[D + h*HD + j];
    }
    ks[tid] += g_kswin[((size_t)src*NWIN + w)*D + tid] - buf[tid];
    __syncthreads();
  }
  int h = tid >> 5, j = tid & 31;
  const float* kvh = &KV[h*HD*HD];
  for (int t = 0; t < WTOK; t++){
    int l = spatial_l(q, t);
    pq[tid] = g_phi_q[((size_t)img*LTOK + l)*D + tid];
    __syncthreads();
    float num = 0.f, den = 0.f;
    #pragma unroll
    for (int d = 0; d < HD; d++){
      float qd = pq[h*HD + d];
      num += qd*kvh[d*HD + j];
      den += qd*ks[h*HD + d];
    }
    g_msg[((size_t)img*LTOK + l)*D + tid] = num / (den + 1e-6f);
    __syncthreads();
  }
}

// ---------------- 8) layernorm (in place) ----------------
__global__ void __launch_bounds__(256) k_ln(float* __restrict__ X,
                                            const float* __restrict__ g,
                                            const float* __restrict__ b){
  size_t row = blockIdx.x;
  int tid = threadIdx.x;
  __shared__ float red[32];
  float x = X[row*D + tid];
  float mu = blockReduceSum(x, red) * (1.f/D);
  float d = x - mu;
  float var = blockReduceSum(d*d, red) * (1.f/D);
  X[row*D + tid] = d*rsqrtf(var + 1e-5f)*g[tid] + b[tid];
}

// ---------------- 9) hcat = [x, msg2] ----------------
__global__ void k_hcat(const float* __restrict__ f0, const float* __restrict__ f1){
  size_t total4 = (size_t)NIMG*LTOK*128;
  for (size_t i = (size_t)blockIdx.x*blockDim.x + threadIdx.x; i < total4;
       i += (size_t)gridDim.x*blockDim.x){
    size_t row = i >> 7; int c4 = (int)(i & 127);
    int img = (int)(row / LTOK); size_t l = row % LTOK;
    float4 v;
    if (c4 < 64){
      const float* F = ((img >> 1) ? f1 : f0) + (((size_t)(img & 1))*LTOK + l)*D;
      v = *(const float4*)&F[c4*4];
    } else {
      v = *(const float4*)&g_msg2[row*D + (size_t)(c4 - 64)*4];
    }
    ((float4*)g_hcat)[i] = v;
  }
}

// ---------------- 10) final: out = x + LN(m2) ----------------
__global__ void __launch_bounds__(256) k_final(const float* __restrict__ f0,
                                               const float* __restrict__ f1,
                                               float* __restrict__ out,
                                               const float* __restrict__ g,
                                               const float* __restrict__ b){
  size_t row = blockIdx.x;
  int tid = threadIdx.x;
  int img = (int)(row / LTOK); size_t l = row % LTOK;
  int m = img >> 1, bb = img & 1;
  __shared__ float red[32];
  float x = g_msg[row*D + tid];
  float mu = blockReduceSum(x, red) * (1.f/D);
  float d = x - mu;
  float var = blockReduceSum(d*d, red) * (1.f/D);
  float msg3 = d*rsqrtf(var + 1e-5f)*g[tid] + b[tid];
  const float* F = (m ? f1 : f0) + ((size_t)bb*LTOK + l)*D;
  out[(size_t)m*2*LTOK*D + ((size_t)bb*LTOK + l)*D + tid] = F[tid] + msg3;
}

// ---------------- host ----------------
extern "C" void kernel_launch(void* const* d_in, const int* in_sizes, int n_in,
                              void* d_out, int out_size){
  (void)in_sizes; (void)n_in; (void)out_size;
  const float* feat0 = (const float*)d_in[0];
  const float* feat1 = (const float*)d_in[1];
  const float* qW    = (const float*)d_in[8];
  const float* kW    = (const float*)d_in[9];
  const float* vW    = (const float*)d_in[10];
  const float* mW    = (const float*)d_in[11];
  const float* mlpW1 = (const float*)d_in[12];
  const float* mlpW2 = (const float*)d_in[13];
  const float* n1g   = (const float*)d_in[14];
  const float* n1b   = (const float*)d_in[15];
  const float* n2g   = (const float*)d_in[16];
  const float* n2b   = (const float*)d_in[17];
  const float* conv_w= (const float*)d_in[18];
  float* out = (float*)d_out;

  float *p_phiq, *p_phik, *p_v, *p_msg, *p_msg2, *p_hcat, *p_hid;
  cudaGetSymbolAddress((void**)&p_phiq, g_phi_q);
  cudaGetSymbolAddress((void**)&p_phik, g_phi_k);
  cudaGetSymbolAddress((void**)&p_v,    g_v);
  cudaGetSymbolAddress((void**)&p_msg,  g_msg);
  cudaGetSymbolAddress((void**)&p_msg2, g_msg2);
  cudaGetSymbolAddress((void**)&p_hcat, g_hcat);
  cudaGetSymbolAddress((void**)&p_hid,  g_hid);

  const int Mall = NIMG*LTOK;   // 36864
  const int Mmap = 2*LTOK;      // 18432 (both batches of one map are contiguous)

  for (int layer = 0; layer < 2; layer++){
    const float* F0 = layer ? out : feat0;
    const float* F1 = layer ? out + (size_t)2*LTOK*D : feat1;
    const float* qWl = qW + (size_t)layer*D*D;
    const float* kWl = kW + (size_t)layer*D*D;
    const float* vWl = vW + (size_t)layer*D*D;
    const float* mWl = mW + (size_t)layer*D*D;
    const float* W1l = mlpW1 + (size_t)layer*2*D*2*D;
    const float* W2l = mlpW2 + (size_t)layer*D*2*D;
    int self = (layer == 0);
    int npairs = self ? NIMG : 2;

    k_rep<<<NIMG*NWIN, 256>>>(F0, F1, conv_w);
    {
      int total = npairs*NWIN*NWIN;
      k_cossim<<<(total + 255)/256, 256>>>(npairs, self);
    }
    k_topk<<<(NIMG*NWIN + 255)/256, 256>>>(self);
    k_repproj<<<NIMG*NWIN, 256>>>(kWl, vWl);
    k_reptot<<<NIMG*NH, 256>>>();

    for (int mm = 0; mm < 2; mm++){
      const float* Fm = mm ? F1 : F0;
      size_t ofs = (size_t)mm*2*LTOK*D;
      dim3 gq(D/128, Mmap/128);
      sgemm_nt<1><<<gq, 256>>>(Fm, qWl, p_phiq + ofs, Mmap, D, D); // phi(q)
      sgemm_nt<1><<<gq, 256>>>(Fm, kWl, p_phik + ofs, Mmap, D, D); // phi(k)
      sgemm_nt<0><<<gq, 256>>>(Fm, vWl, p_v    + ofs, Mmap, D, D); // v
    }

    k_winagg<<<NIMG*NWIN*NH, 256>>>();
    k_attn<<<NIMG*NWIN, 256>>>(layer);

    { dim3 g(D/128, Mall/128);
      sgemm_nt<0><<<g, 256>>>(p_msg, mWl, p_msg2, Mall, D, D); }
    k_ln<<<Mall, 256>>>(p_msg2, n1g + layer*D, n1b + layer*D);

    k_hcat<<<4096, 256>>>(F0, F1);
    { dim3 g1(2*D/128, Mall/128);
      sgemm_nt<2><<<g1, 256>>>(p_hcat, W1l, p_hid, Mall, 2*D, 2*D); } // relu
    { dim3 g2(D/128, Mall/128);
      sgemm_nt<0><<<g2, 256>>>(p_hid, W2l, p_msg, Mall, D, 2*D); }

    k_final<<<Mall, 256>>>(F0, F1, out, n2g + layer*D, n2b + layer*D);
  }
}

// round 8
// speedup vs baseline: 1.3903x; 1.3903x over previous
#include <cuda_runtime.h>
#include <cuda_bf16.h>
#include <math.h>
#include <stdint.h>

// ---------------- problem constants ----------------
#define NIMG 4        // (map m, batch b) -> img = m*2+b
#define LTOK 9216     // 96*96
#define D 256
#define NH 8
#define HD 32
#define WGRID 12      // 96/8
#define NWIN 144
#define WTOK 64
#define KSEL 8
#define CN 16

// ---------------- scratch (device globals; no allocation allowed) ----------
__device__ float g_phi_q[NIMG*LTOK*D];
__device__ float g_phi_k[NIMG*LTOK*D];
__device__ float g_v    [NIMG*LTOK*D];
__device__ float g_msg  [NIMG*LTOK*D];
__device__ float g_msg2 [NIMG*LTOK*D];
__device__ float g_hcat [NIMG*LTOK*2*D];
__device__ float g_hid  [NIMG*LTOK*2*D];
__device__ float g_rep  [NIMG*NWIN*D];
__device__ float g_repn [NIMG*NWIN*D];
__device__ float g_phikr[NIMG*NWIN*D];
__device__ float g_vr   [NIMG*NWIN*D];
__device__ float g_sim  [NIMG*NWIN*NWIN];
__device__ int   g_sel  [NIMG*NWIN*KSEL];
__device__ float g_KVwin[NIMG*NWIN*NH*HD*HD];
__device__ float g_kswin[NIMG*NWIN*D];
__device__ float g_KVtot[NIMG*NH*HD*HD];
__device__ float g_kstot[NIMG*D];

// ---------------- helpers ----------------
__device__ __forceinline__ float phi(float x){ return x > 0.f ? x + 1.f : expf(x); }

__device__ __forceinline__ float blockReduceSum(float val, float* sbuf){
  __syncthreads();
  int lane = threadIdx.x & 31, wid = threadIdx.x >> 5;
  #pragma unroll
  for (int o = 16; o; o >>= 1) val += __shfl_down_sync(0xffffffffu, val, o);
  if (lane == 0) sbuf[wid] = val;
  __syncthreads();
  float r = (threadIdx.x < (blockDim.x >> 5)) ? sbuf[threadIdx.x] : 0.f;
  if (wid == 0){
    #pragma unroll
    for (int o = 16; o; o >>= 1) r += __shfl_down_sync(0xffffffffu, r, o);
    if (lane == 0) sbuf[0] = r;
  }
  __syncthreads();
  return sbuf[0];
}

__device__ __forceinline__ int spatial_l(int win, int t){
  int wy = win / WGRID, wx = win % WGRID;
  return (wy*8 + (t >> 3))*96 + wx*8 + (t & 7);
}

// ---------------- 1) per-window rep (sim->softmax->avg->rep, + normalized) --
__global__ void __launch_bounds__(256) k_rep(const float* __restrict__ f0,
                                             const float* __restrict__ f1,
                                             const float* __restrict__ conv_w){
  int img = blockIdx.x / NWIN, win = blockIdx.x % NWIN;
  int m = img >> 1, b = img & 1;
  const float* F = (m ? f1 : f0) + (size_t)b*LTOK*D;
  __shared__ float cw[CN*D];          // 16KB
  __shared__ float simall[WTOK*CN];   // 4KB
  __shared__ float avg[CN];
  __shared__ float red[32];
  int tid = threadIdx.x;
  for (int i = tid; i < CN*D; i += 256) cw[i] = conv_w[i];
  __syncthreads();
  int warp = tid >> 5, lane = tid & 31;
  for (int p = 0; p < 8; p++){
    int t = warp + p*8;
    int l = spatial_l(win, t);
    const float* fr = F + (size_t)l*D;
    float fv[8];
    #pragma unroll
    for (int i = 0; i < 8; i++) fv[i] = fr[lane + 32*i];
    for (int c = 0; c < CN; c++){
      float s = 0.f;
      #pragma unroll
      for (int i = 0; i < 8; i++) s += fv[i]*cw[c*D + lane + 32*i];
      #pragma unroll
      for (int o = 16; o; o >>= 1) s += __shfl_down_sync(0xffffffffu, s, o);
      if (lane == 0) simall[t*CN + c] = s;
    }
  }
  __syncthreads();
  if (tid < WTOK){
    float mx = -1e30f;
    for (int c = 0; c < CN; c++) mx = fmaxf(mx, simall[tid*CN + c]);
    float s = 0.f, e[CN];
    for (int c = 0; c < CN; c++){ e[c] = expf(simall[tid*CN + c] - mx); s += e[c]; }
    float inv = 1.f/s;
    for (int c = 0; c < CN; c++) simall[tid*CN + c] = e[c]*inv;
  }
  __syncthreads();
  if (tid < CN){
    float s = 0.f;
    for (int t = 0; t < WTOK; t++) s += simall[t*CN + tid];
    avg[tid] = s * (1.f/WTOK);
  }
  __syncthreads();
  float r = 0.f;
  for (int c = 0; c < CN; c++) r += avg[c]*cw[c*D + tid];
  g_rep[(size_t)(img*NWIN + win)*D + tid] = r;
  float n2 = blockReduceSum(r*r, red);
  float nrm = fmaxf(sqrtf(n2), 1e-8f);
  g_repn[(size_t)(img*NWIN + win)*D + tid] = r / nrm;
}

// ---------------- 2) cosine sim matrices ----------------
__global__ void k_cossim(int npairs, int self){
  long total = (long)npairs*NWIN*NWIN;
  for (long idx = (long)blockIdx.x*blockDim.x + threadIdx.x; idx < total;
       idx += (long)gridDim.x*blockDim.x){
    int p = (int)(idx/(NWIN*NWIN)); int rem = (int)(idx%(NWIN*NWIN));
    int q = rem/NWIN, s = rem%NWIN;
    const float* a = &g_repn[((size_t)p*NWIN + q)*D];
    const float* bb = self ? &g_repn[((size_t)p*NWIN + s)*D]
                           : &g_repn[(((size_t)(2+p))*NWIN + s)*D];
    float acc = 0.f;
    #pragma unroll 4
    for (int k = 0; k < D; k += 4){
      float4 av = *(const float4*)&a[k];
      float4 bv = *(const float4*)&bb[k];
      acc += av.x*bv.x + av.y*bv.y + av.z*bv.z + av.w*bv.w;
    }
    g_sim[idx] = acc;
  }
}

// ---------------- 3) top-K (stable, lower index first on ties) --------------
__global__ void k_topk(int self){
  int idx = blockIdx.x*blockDim.x + threadIdx.x;
  if (idx >= NIMG*NWIN) return;
  int img = idx/NWIN, q = idx%NWIN;
  size_t base; int sq, ss;
  if (self){ base = (size_t)img*NWIN*NWIN; sq = NWIN; ss = 1; }
  else {
    int b = img & 1, m = img >> 1;
    base = (size_t)b*NWIN*NWIN;
    if (m == 0){ sq = NWIN; ss = 1; } else { sq = 1; ss = NWIN; }
  }
  const float* S = g_sim + base + (size_t)q*sq;
  float vals[NWIN];
  for (int s = 0; s < NWIN; s++) vals[s] = S[(size_t)s*ss];
  for (int k = 0; k < KSEL; k++){
    float best = -1e30f; int bi = 0;
    for (int s = 0; s < NWIN; s++) if (vals[s] > best){ best = vals[s]; bi = s; }
    g_sel[idx*KSEL + k] = bi;
    vals[bi] = -1e30f;
  }
}

// ---------------- 5) totals over all 144 rep rows ----------------
__global__ void __launch_bounds__(256) k_reptot(){
  int img = blockIdx.x >> 3, h = blockIdx.x & 7;
  __shared__ float pk[NWIN*HD]; // 18KB
  __shared__ float vv[NWIN*HD]; // 18KB
  int tid = threadIdx.x;
  for (int i = tid; i < NWIN*HD; i += 256){
    int r = i/HD, d = i%HD;
    size_t off = ((size_t)img*NWIN + r)*D + h*HD + d;
    pk[i] = g_phikr[off]; vv[i] = g_vr[off];
  }
  __syncthreads();
  for (int o = tid; o < HD*HD; o += 256){
    int d = o/HD, j = o%HD;
    float s = 0.f;
    for (int r = 0; r < NWIN; r++) s += pk[r*HD + d]*vv[r*HD + j];
    g_KVtot[((size_t)img*NH + h)*HD*HD + o] = s;
  }
  if (tid < HD){
    float s = 0.f;
    for (int r = 0; r < NWIN; r++) s += pk[r*HD + tid];
    g_kstot[(size_t)img*D + h*HD + tid] = s;
  }
}

// ============ 3xTF32 tensor-core GEMM: C = act(A[MxK] @ B[NxK]^T) ===========
template<int ACT>
__device__ __forceinline__ float actf(float x){
  if (ACT == 1) return x > 0.f ? x + 1.f : expf(x); // phi = elu + 1
  if (ACT == 2) return fmaxf(x, 0.f);               // relu
  return x;
}

// tf32 destination must be a .b32 register.
__device__ __forceinline__ uint32_t tf32r(float x){
  uint32_t y;
  asm("cvt.rna.tf32.f32 %0, %1;" : "=r"(y) : "f"(x));
  return y;
}

__device__ __forceinline__ void mma_tf32(float* d, const uint32_t* a, const uint32_t* b){
  asm volatile(
    "mma.sync.aligned.m16n8k8.row.col.f32.tf32.tf32.f32 "
    "{%0,%1,%2,%3}, {%4,%5,%6,%7}, {%8,%9}, {%0,%1,%2,%3};"
    : "+f"(d[0]), "+f"(d[1]), "+f"(d[2]), "+f"(d[3])
    : "r"(a[0]), "r"(a[1]), "r"(a[2]), "r"(a[3]), "r"(b[0]), "r"(b[1]));
}

#define TBM 128
#define TBN 128
#define TBK 16
#define TST (TBK + 4)   // smem row stride (words)

// 256 threads = 8 warps; warp grid 4(M) x 2(N); warp tile 32x64.
// hi/lo split tiles: As/Bs [2][128][20] u32 = 40 KB static smem.
template<int ACT>
__global__ void __launch_bounds__(256, 2) tgemm_nt(const float* __restrict__ A,
                                                   const float* __restrict__ B,
                                                   float* __restrict__ C,
                                                   int M, int N, int K){
  __shared__ uint32_t As[2][TBM][TST];
  __shared__ uint32_t Bs[2][TBN][TST];
  int tid = threadIdx.x;
  int bm = blockIdx.y*TBM, bn = blockIdx.x*TBN;
  int warp = tid >> 5, lane = tid & 31;
  int wm = (warp >> 1)*32, wn = (warp & 1)*64;
  int grp = lane >> 2, tig = lane & 3;

  float acc[16][4];
  #pragma unroll
  for (int f = 0; f < 16; f++)
    #pragma unroll
    for (int r = 0; r < 4; r++) acc[f][r] = 0.f;

  // load mapping: 128 rows x 4 float4-groups = 512 float4 per tile; 2/thread.
  float4 ra[2], rb[2];
  #pragma unroll
  for (int i = 0; i < 2; i++){
    int idx = tid + i*256; int row = idx >> 2, c4 = idx & 3;
    ra[i] = (bm + row < M) ? *(const float4*)&A[(size_t)(bm + row)*K + c4*4]
                           : make_float4(0.f,0.f,0.f,0.f);
    rb[i] = (bn + row < N) ? *(const float4*)&B[(size_t)(bn + row)*K + c4*4]
                           : make_float4(0.f,0.f,0.f,0.f);
  }

  for (int k0 = 0; k0 < K; k0 += TBK){
    __syncthreads();
    #pragma unroll
    for (int i = 0; i < 2; i++){
      int idx = tid + i*256; int row = idx >> 2, c4 = idx & 3;
      float av[4] = {ra[i].x, ra[i].y, ra[i].z, ra[i].w};
      float bv[4] = {rb[i].x, rb[i].y, rb[i].z, rb[i].w};
      uint32_t ah[4], al[4], bh[4], bl[4];
      #pragma unroll
      for (int e = 0; e < 4; e++){
        ah[e] = tf32r(av[e]); al[e] = tf32r(av[e] - __uint_as_float(ah[e]));
        bh[e] = tf32r(bv[e]); bl[e] = tf32r(bv[e] - __uint_as_float(bh[e]));
      }
      *(uint4*)&As[0][row][c4*4] = make_uint4(ah[0],ah[1],ah[2],ah[3]);
      *(uint4*)&As[1][row][c4*4] = make_uint4(al[0],al[1],al[2],al[3]);
      *(uint4*)&Bs[0][row][c4*4] = make_uint4(bh[0],bh[1],bh[2],bh[3]);
      *(uint4*)&Bs[1][row][c4*4] = make_uint4(bl[0],bl[1],bl[2],bl[3]);
    }
    __syncthreads();
    if (k0 + TBK < K){
      #pragma unroll
      for (int i = 0; i < 2; i++){
        int idx = tid + i*256; int row = idx >> 2, c4 = idx & 3;
        ra[i] = (bm + row < M) ? *(const float4*)&A[(size_t)(bm + row)*K + k0 + TBK + c4*4]
                               : make_float4(0.f,0.f,0.f,0.f);
        rb[i] = (bn + row < N) ? *(const float4*)&B[(size_t)(bn + row)*K + k0 + TBK + c4*4]
                               : make_float4(0.f,0.f,0.f,0.f);
      }
    }
    #pragma unroll
    for (int kk = 0; kk < 2; kk++){
      int kb = kk*8;
      uint32_t afh[2][4], afl[2][4];
      #pragma unroll
      for (int i = 0; i < 2; i++){
        int r = wm + i*16 + grp;
        afh[i][0] = As[0][r    ][kb + tig    ];
        afh[i][1] = As[0][r + 8][kb + tig    ];
        afh[i][2] = As[0][r    ][kb + tig + 4];
        afh[i][3] = As[0][r + 8][kb + tig + 4];
        afl[i][0] = As[1][r    ][kb + tig    ];
        afl[i][1] = As[1][r + 8][kb + tig    ];
        afl[i][2] = As[1][r    ][kb + tig + 4];
        afl[i][3] = As[1][r + 8][kb + tig + 4];
      }
      #pragma unroll
      for (int j = 0; j < 8; j++){
        int n = wn + j*8 + grp;
        uint32_t bfh[2], bfl[2];
        bfh[0] = Bs[0][n][kb + tig    ];
        bfh[1] = Bs[0][n][kb + tig + 4];
        bfl[0] = Bs[1][n][kb + tig    ];
        bfl[1] = Bs[1][n][kb + tig + 4];
        #pragma unroll
        for (int i = 0; i < 2; i++){
          mma_tf32(acc[i*8 + j], afh[i], bfl);  // hi*lo
          mma_tf32(acc[i*8 + j], afl[i], bfh);  // lo*hi
          mma_tf32(acc[i*8 + j], afh[i], bfh);  // hi*hi
        }
      }
    }
  }

  #pragma unroll
  for (int i = 0; i < 2; i++){
    int r0 = bm + wm + i*16 + grp;
    #pragma unroll
    for (int j = 0; j < 8; j++){
      int c = bn + wn + j*8 + tig*2;
      const float* dd = acc[i*8 + j];
      if (r0 < M){
        C[(size_t)r0*N + c    ] = actf<ACT>(dd[0]);
        C[(size_t)r0*N + c + 1] = actf<ACT>(dd[1]);
      }
      if (r0 + 8 < M){
        C[(size_t)(r0+8)*N + c    ] = actf<ACT>(dd[2]);
        C[(size_t)(r0+8)*N + c + 1] = actf<ACT>(dd[3]);
      }
    }
  }
}

// ---------------- 6) per-window KV/ksum aggregates ----------------
__global__ void __launch_bounds__(256) k_winagg(){
  int bid = blockIdx.x;
  int h = bid & 7; int wv = bid >> 3;
  int win = wv % NWIN, img = wv / NWIN;
  __shared__ float pk[WTOK*HD]; // 8KB
  __shared__ float vv[WTOK*HD]; // 8KB
  int tid = threadIdx.x;
  for (int i = tid; i < WTOK*HD; i += 256){
    int t = i/HD, d = i%HD;
    int l = spatial_l(win, t);
    size_t off = ((size_t)img*LTOK + l)*D + h*HD + d;
    pk[i] = g_phi_k[off]; vv[i] = g_v[off];
  }
  __syncthreads();
  for (int o = tid; o < HD*HD; o += 256){
    int d = o/HD, j = o%HD;
    float s = 0.f;
    #pragma unroll 8
    for (int t = 0; t < WTOK; t++) s += pk[t*HD + d]*vv[t*HD + j];
    g_KVwin[(((size_t)(img*NWIN + win))*NH + h)*HD*HD + o] = s;
  }
  if (tid < HD){
    float s = 0.f;
    for (int t = 0; t < WTOK; t++) s += pk[t*HD + tid];
    g_kswin[((size_t)img*NWIN + win)*D + h*HD + tid] = s;
  }
}

// ---------------- 7) attention: build per-query-window KV, apply ------------
__global__ void __launch_bounds__(256) k_attn(int layer){
  int img = blockIdx.x / NWIN, q = blockIdx.x % NWIN;
  int src = (layer == 0) ? img : (img ^ 2); // cross: flip map, keep batch
  __shared__ float KV[NH*HD*HD]; // 32KB
  __shared__ float ks[D];
  __shared__ float buf[2*D];
  __shared__ float pq[D];
  int tid = threadIdx.x;
  for (int i = tid; i < NH*HD*HD; i += 256) KV[i] = g_KVtot[(size_t)src*NH*HD*HD + i];
  ks[tid] = g_kstot[(size_t)src*D + tid];
  __syncthreads();
  for (int k = 0; k < KSEL; k++){
    int w = g_sel[(img*NWIN + q)*KSEL + k];
    buf[tid]     = g_phikr[((size_t)src*NWIN + w)*D + tid];
    buf[D + tid] = g_vr   [((size_t)src*NWIN + w)*D + tid];
    __syncthreads();
    const float* KVW = &g_KVwin[((size_t)(src*NWIN + w))*NH*HD*HD];
    for (int i = tid; i < NH*HD*HD; i += 256){
      int h = i >> 10, d = (i >> 5) & 31, j = i & 31;
      KV[i] += KVW[i] - buf[h*HD + d]*buf[D + h*HD + j];
    }
    ks[tid] += g_kswin[((size_t)src*NWIN + w)*D + tid] - buf[tid];
    __syncthreads();
  }
  int h = tid >> 5, j = tid & 31;
  const float* kvh = &KV[h*HD*HD];
  for (int t = 0; t < WTOK; t++){
    int l = spatial_l(q, t);
    pq[tid] = g_phi_q[((size_t)img*LTOK + l)*D + tid];
    __syncthreads();
    float num = 0.f, den = 0.f;
    #pragma unroll
    for (int d = 0; d < HD; d++){
      float qd = pq[h*HD + d];
      num += qd*kvh[d*HD + j];
      den += qd*ks[h*HD + d];
    }
    g_msg[((size_t)img*LTOK + l)*D + tid] = num / (den + 1e-6f);
    __syncthreads();
  }
}

// ---------------- 8) layernorm (in place) ----------------
__global__ void __launch_bounds__(256) k_ln(float* __restrict__ X,
                                            const float* __restrict__ g,
                                            const float* __restrict__ b){
  size_t row = blockIdx.x;
  int tid = threadIdx.x;
  __shared__ float red[32];
  float x = X[row*D + tid];
  float mu = blockReduceSum(x, red) * (1.f/D);
  float d = x - mu;
  float var = blockReduceSum(d*d, red) * (1.f/D);
  X[row*D + tid] = d*rsqrtf(var + 1e-5f)*g[tid] + b[tid];
}

// ---------------- 9) hcat = [x, msg2] ----------------
__global__ void k_hcat(const float* __restrict__ f0, const float* __restrict__ f1){
  size_t total4 = (size_t)NIMG*LTOK*128;
  for (size_t i = (size_t)blockIdx.x*blockDim.x + threadIdx.x; i < total4;
       i += (size_t)gridDim.x*blockDim.x){
    size_t row = i >> 7; int c4 = (int)(i & 127);
    int img = (int)(row / LTOK); size_t l = row % LTOK;
    float4 v;
    if (c4 < 64){
      const float* F = ((img >> 1) ? f1 : f0) + (((size_t)(img & 1))*LTOK + l)*D;
      v = *(const float4*)&F[c4*4];
    } else {
      v = *(const float4*)&g_msg2[row*D + (size_t)(c4 - 64)*4];
    }
    ((float4*)g_hcat)[i] = v;
  }
}

// ---------------- 10) final: out = x + LN(m2) ----------------
__global__ void __launch_bounds__(256) k_final(const float* __restrict__ f0,
                                               const float* __restrict__ f1,
                                               float* __restrict__ out,
                                               const float* __restrict__ g,
                                               const float* __restrict__ b){
  size_t row = blockIdx.x;
  int tid = threadIdx.x;
  int img = (int)(row / LTOK); size_t l = row % LTOK;
  int m = img >> 1, bb = img & 1;
  __shared__ float red[32];
  float x = g_msg[row*D + tid];
  float mu = blockReduceSum(x, red) * (1.f/D);
  float d = x - mu;
  float var = blockReduceSum(d*d, red) * (1.f/D);
  float msg3 = d*rsqrtf(var + 1e-5f)*g[tid] + b[tid];
  const float* F = (m ? f1 : f0) + ((size_t)bb*LTOK + l)*D;
  out[(size_t)m*2*LTOK*D + ((size_t)bb*LTOK + l)*D + tid] = F[tid] + msg3;
}

// ---------------- host ----------------
extern "C" void kernel_launch(void* const* d_in, const int* in_sizes, int n_in,
                              void* d_out, int out_size){
  (void)in_sizes; (void)n_in; (void)out_size;
  const float* feat0 = (const float*)d_in[0];
  const float* feat1 = (const float*)d_in[1];
  const float* qW    = (const float*)d_in[8];
  const float* kW    = (const float*)d_in[9];
  const float* vW    = (const float*)d_in[10];
  const float* mW    = (const float*)d_in[11];
  const float* mlpW1 = (const float*)d_in[12];
  const float* mlpW2 = (const float*)d_in[13];
  const float* n1g   = (const float*)d_in[14];
  const float* n1b   = (const float*)d_in[15];
  const float* n2g   = (const float*)d_in[16];
  const float* n2b   = (const float*)d_in[17];
  const float* conv_w= (const float*)d_in[18];
  float* out = (float*)d_out;

  float *p_phiq, *p_phik, *p_v, *p_msg, *p_msg2, *p_hcat, *p_hid;
  float *p_rep, *p_phikr, *p_vr;
  cudaGetSymbolAddress((void**)&p_phiq, g_phi_q);
  cudaGetSymbolAddress((void**)&p_phik, g_phi_k);
  cudaGetSymbolAddress((void**)&p_v,    g_v);
  cudaGetSymbolAddress((void**)&p_msg,  g_msg);
  cudaGetSymbolAddress((void**)&p_msg2, g_msg2);
  cudaGetSymbolAddress((void**)&p_hcat, g_hcat);
  cudaGetSymbolAddress((void**)&p_hid,  g_hid);
  cudaGetSymbolAddress((void**)&p_rep,  g_rep);
  cudaGetSymbolAddress((void**)&p_phikr,g_phikr);
  cudaGetSymbolAddress((void**)&p_vr,   g_vr);

  const int Mall = NIMG*LTOK;   // 36864
  const int Mmap = 2*LTOK;      // 18432 (both batches of one map contiguous)
  const int Mrep = NIMG*NWIN;   // 576

  for (int layer = 0; layer < 2; layer++){
    const float* F0 = layer ? out : feat0;
    const float* F1 = layer ? out + (size_t)2*LTOK*D : feat1;
    const float* qWl = qW + (size_t)layer*D*D;
    const float* kWl = kW + (size_t)layer*D*D;
    const float* vWl = vW + (size_t)layer*D*D;
    const float* mWl = mW + (size_t)layer*D*D;
    const float* W1l = mlpW1 + (size_t)layer*2*D*2*D;
    const float* W2l = mlpW2 + (size_t)layer*D*2*D;
    int self = (layer == 0);
    int npairs = self ? NIMG : 2;

    k_rep<<<NIMG*NWIN, 256>>>(F0, F1, conv_w);
    {
      int total = npairs*NWIN*NWIN;
      k_cossim<<<(total + 255)/256, 256>>>(npairs, self);
    }
    k_topk<<<(NIMG*NWIN + 255)/256, 256>>>(self);

    // rep k/v projections as small tensor-core GEMMs (M=576)
    {
      dim3 gr(D/TBN, (Mrep + TBM - 1)/TBM);
      tgemm_nt<1><<<gr, 256>>>(p_rep, kWl, p_phikr, Mrep, D, D); // phi(rep@kW^T)
      tgemm_nt<0><<<gr, 256>>>(p_rep, vWl, p_vr,    Mrep, D, D);
    }
    k_reptot<<<NIMG*NH, 256>>>();

    for (int mm = 0; mm < 2; mm++){
      const float* Fm = mm ? F1 : F0;
      size_t ofs = (size_t)mm*2*LTOK*D;
      dim3 gq(D/TBN, Mmap/TBM);
      tgemm_nt<1><<<gq, 256>>>(Fm, qWl, p_phiq + ofs, Mmap, D, D); // phi(q)
      tgemm_nt<1><<<gq, 256>>>(Fm, kWl, p_phik + ofs, Mmap, D, D); // phi(k)
      tgemm_nt<0><<<gq, 256>>>(Fm, vWl, p_v    + ofs, Mmap, D, D); // v
    }

    k_winagg<<<NIMG*NWIN*NH, 256>>>();
    k_attn<<<NIMG*NWIN, 256>>>(layer);

    { dim3 g(D/TBN, Mall/TBM);
      tgemm_nt<0><<<g, 256>>>(p_msg, mWl, p_msg2, Mall, D, D); }
    k_ln<<<Mall, 256>>>(p_msg2, n1g + layer*D, n1b + layer*D);

    k_hcat<<<4096, 256>>>(F0, F1);
    { dim3 g1(2*D/TBN, Mall/TBM);
      tgemm_nt<2><<<g1, 256>>>(p_hcat, W1l, p_hid, Mall, 2*D, 2*D); } // relu
    { dim3 g2(D/TBN, Mall/TBM);
      tgemm_nt<0><<<g2, 256>>>(p_hid, W2l, p_msg, Mall, D, 2*D); }

    k_final<<<Mall, 256>>>(F0, F1, out, n2g + layer*D, n2b + layer*D);
  }
}

// round 9
// speedup vs baseline: 1.7255x; 1.2411x over previous
#include <cuda_runtime.h>
#include <cuda_bf16.h>
#include <math.h>
#include <stdint.h>

// ---------------- problem constants ----------------
#define NIMG 4        // (map m, batch b) -> img = m*2+b
#define LTOK 9216     // 96*96
#define D 256
#define NH 8
#define HD 32
#define WGRID 12      // 96/8
#define NWIN 144
#define WTOK 64
#define KSEL 8
#define CN 16

// weight-plane buffer offsets (elements)
#define WOQ 0
#define WOK 65536
#define WOV 131072
#define WOM 196608
#define WO1 262144
#define WO2 524288
#define WTOT 655360

// ---------------- scratch (device globals; no allocation allowed) ----------
__device__ float g_phi_q[NIMG*LTOK*D];
__device__ float g_phi_k[NIMG*LTOK*D];
__device__ float g_v    [NIMG*LTOK*D];
__device__ float g_msg  [NIMG*LTOK*D];   // MLP2 output (pre-LN2)
__device__ float g_msg2 [NIMG*LTOK*D];   // mW output / LN1 in place
__device__ float g_repn [NIMG*NWIN*D];
__device__ float g_phikr[NIMG*NWIN*D];
__device__ float g_vr   [NIMG*NWIN*D];
__device__ float g_sim  [NIMG*NWIN*NWIN];
__device__ int   g_sel  [NIMG*NWIN*KSEL];
__device__ float g_KVwin[NIMG*NWIN*NH*HD*HD];
__device__ float g_kswin[NIMG*NWIN*D];
__device__ float g_KVtot[NIMG*NH*HD*HD];
__device__ float g_kstot[NIMG*D];

// bf16 hi/lo operand planes (aligned for uint4 loads)
__device__ __align__(128) __nv_bfloat16 b_feat_hi[NIMG*LTOK*D];
__device__ __align__(128) __nv_bfloat16 b_feat_lo[NIMG*LTOK*D];
__device__ __align__(128) __nv_bfloat16 b_rep_hi [NIMG*NWIN*D];
__device__ __align__(128) __nv_bfloat16 b_rep_lo [NIMG*NWIN*D];
__device__ __align__(128) __nv_bfloat16 b_msg_hi [NIMG*LTOK*D];
__device__ __align__(128) __nv_bfloat16 b_msg_lo [NIMG*LTOK*D];
__device__ __align__(128) __nv_bfloat16 b_hcat_hi[NIMG*LTOK*2*D];
__device__ __align__(128) __nv_bfloat16 b_hcat_lo[NIMG*LTOK*2*D];
__device__ __align__(128) __nv_bfloat16 b_hid_hi [NIMG*LTOK*2*D];
__device__ __align__(128) __nv_bfloat16 b_hid_lo [NIMG*LTOK*2*D];
__device__ __align__(128) __nv_bfloat16 b_w_hi   [WTOT];
__device__ __align__(128) __nv_bfloat16 b_w_lo   [WTOT];

// ---------------- helpers ----------------
__device__ __forceinline__ float phi(float x){ return x > 0.f ? x + 1.f : expf(x); }

__device__ __forceinline__ void split_bf16(float x, __nv_bfloat16& h, __nv_bfloat16& l){
  h = __float2bfloat16(x);
  l = __float2bfloat16(x - __bfloat162float(h));
}

__device__ __forceinline__ float blockReduceSum(float val, float* sbuf){
  __syncthreads();
  int lane = threadIdx.x & 31, wid = threadIdx.x >> 5;
  #pragma unroll
  for (int o = 16; o; o >>= 1) val += __shfl_down_sync(0xffffffffu, val, o);
  if (lane == 0) sbuf[wid] = val;
  __syncthreads();
  float r = (threadIdx.x < (blockDim.x >> 5)) ? sbuf[threadIdx.x] : 0.f;
  if (wid == 0){
    #pragma unroll
    for (int o = 16; o; o >>= 1) r += __shfl_down_sync(0xffffffffu, r, o);
    if (lane == 0) sbuf[0] = r;
  }
  __syncthreads();
  return sbuf[0];
}

__device__ __forceinline__ int spatial_l(int win, int t){
  int wy = win / WGRID, wx = win % WGRID;
  return (wy*8 + (t >> 3))*96 + wx*8 + (t & 7);
}

// ---------------- converters ----------------
__global__ void k_convw(const float* __restrict__ q, const float* __restrict__ k,
                        const float* __restrict__ v, const float* __restrict__ m,
                        const float* __restrict__ w1, const float* __restrict__ w2){
  for (int i = blockIdx.x*blockDim.x + threadIdx.x; i < WTOT; i += gridDim.x*blockDim.x){
    float x;
    if      (i < WOK) x = q[i];
    else if (i < WOV) x = k[i - WOK];
    else if (i < WOM) x = v[i - WOV];
    else if (i < WO1) x = m[i - WOM];
    else if (i < WO2) x = w1[i - WO1];
    else              x = w2[i - WO2];
    split_bf16(x, b_w_hi[i], b_w_lo[i]);
  }
}

__global__ void k_convfeat(const float* __restrict__ f0, const float* __restrict__ f1){
  const int half = 2*LTOK*D;
  for (int i = blockIdx.x*blockDim.x + threadIdx.x; i < NIMG*LTOK*D;
       i += gridDim.x*blockDim.x){
    float x = (i < half) ? f0[i] : f1[i - half];
    split_bf16(x, b_feat_hi[i], b_feat_lo[i]);
  }
}

// ---------------- 1) per-window rep ----------------
__global__ void __launch_bounds__(256) k_rep(const float* __restrict__ f0,
                                             const float* __restrict__ f1,
                                             const float* __restrict__ conv_w){
  int img = blockIdx.x / NWIN, win = blockIdx.x % NWIN;
  int m = img >> 1, b = img & 1;
  const float* F = (m ? f1 : f0) + (size_t)b*LTOK*D;
  __shared__ float cw[CN*D];
  __shared__ float simall[WTOK*CN];
  __shared__ float avg[CN];
  __shared__ float red[32];
  int tid = threadIdx.x;
  for (int i = tid; i < CN*D; i += 256) cw[i] = conv_w[i];
  __syncthreads();
  int warp = tid >> 5, lane = tid & 31;
  for (int p = 0; p < 8; p++){
    int t = warp + p*8;
    int l = spatial_l(win, t);
    const float* fr = F + (size_t)l*D;
    float fv[8];
    #pragma unroll
    for (int i = 0; i < 8; i++) fv[i] = fr[lane + 32*i];
    for (int c = 0; c < CN; c++){
      float s = 0.f;
      #pragma unroll
      for (int i = 0; i < 8; i++) s += fv[i]*cw[c*D + lane + 32*i];
      #pragma unroll
      for (int o = 16; o; o >>= 1) s += __shfl_down_sync(0xffffffffu, s, o);
      if (lane == 0) simall[t*CN + c] = s;
    }
  }
  __syncthreads();
  if (tid < WTOK){
    float mx = -1e30f;
    for (int c = 0; c < CN; c++) mx = fmaxf(mx, simall[tid*CN + c]);
    float s = 0.f, e[CN];
    for (int c = 0; c < CN; c++){ e[c] = expf(simall[tid*CN + c] - mx); s += e[c]; }
    float inv = 1.f/s;
    for (int c = 0; c < CN; c++) simall[tid*CN + c] = e[c]*inv;
  }
  __syncthreads();
  if (tid < CN){
    float s = 0.f;
    for (int t = 0; t < WTOK; t++) s += simall[t*CN + tid];
    avg[tid] = s * (1.f/WTOK);
  }
  __syncthreads();
  float r = 0.f;
  for (int c = 0; c < CN; c++) r += avg[c]*cw[c*D + tid];
  size_t oi = (size_t)(img*NWIN + win)*D + tid;
  split_bf16(r, b_rep_hi[oi], b_rep_lo[oi]);
  float n2 = blockReduceSum(r*r, red);
  float nrm = fmaxf(sqrtf(n2), 1e-8f);
  g_repn[oi] = r / nrm;
}

// ---------------- 2) cosine sim ----------------
__global__ void k_cossim(int npairs, int self){
  long total = (long)npairs*NWIN*NWIN;
  for (long idx = (long)blockIdx.x*blockDim.x + threadIdx.x; idx < total;
       idx += (long)gridDim.x*blockDim.x){
    int p = (int)(idx/(NWIN*NWIN)); int rem = (int)(idx%(NWIN*NWIN));
    int q = rem/NWIN, s = rem%NWIN;
    const float* a = &g_repn[((size_t)p*NWIN + q)*D];
    const float* bb = self ? &g_repn[((size_t)p*NWIN + s)*D]
                           : &g_repn[(((size_t)(2+p))*NWIN + s)*D];
    float acc = 0.f;
    #pragma unroll 4
    for (int k = 0; k < D; k += 4){
      float4 av = *(const float4*)&a[k];
      float4 bv = *(const float4*)&bb[k];
      acc += av.x*bv.x + av.y*bv.y + av.z*bv.z + av.w*bv.w;
    }
    g_sim[idx] = acc;
  }
}

// ---------------- 3) top-K ----------------
__global__ void k_topk(int self){
  int idx = blockIdx.x*blockDim.x + threadIdx.x;
  if (idx >= NIMG*NWIN) return;
  int img = idx/NWIN, q = idx%NWIN;
  size_t base; int sq, ss;
  if (self){ base = (size_t)img*NWIN*NWIN; sq = NWIN; ss = 1; }
  else {
    int b = img & 1, m = img >> 1;
    base = (size_t)b*NWIN*NWIN;
    if (m == 0){ sq = NWIN; ss = 1; } else { sq = 1; ss = NWIN; }
  }
  const float* S = g_sim + base + (size_t)q*sq;
  float vals[NWIN];
  for (int s = 0; s < NWIN; s++) vals[s] = S[(size_t)s*ss];
  for (int k = 0; k < KSEL; k++){
    float best = -1e30f; int bi = 0;
    for (int s = 0; s < NWIN; s++) if (vals[s] > best){ best = vals[s]; bi = s; }
    g_sel[idx*KSEL + k] = bi;
    vals[bi] = -1e30f;
  }
}

// ---------------- 5) totals over all 144 rep rows ----------------
__global__ void __launch_bounds__(256) k_reptot(){
  int img = blockIdx.x >> 3, h = blockIdx.x & 7;
  __shared__ float pk[NWIN*HD];
  __shared__ float vv[NWIN*HD];
  int tid = threadIdx.x;
  for (int i = tid; i < NWIN*HD; i += 256){
    int r = i/HD, d = i%HD;
    size_t off = ((size_t)img*NWIN + r)*D + h*HD + d;
    pk[i] = g_phikr[off]; vv[i] = g_vr[off];
  }
  __syncthreads();
  for (int o = tid; o < HD*HD; o += 256){
    int d = o/HD, j = o%HD;
    float s = 0.f;
    for (int r = 0; r < NWIN; r++) s += pk[r*HD + d]*vv[r*HD + j];
    g_KVtot[((size_t)img*NH + h)*HD*HD + o] = s;
  }
  if (tid < HD){
    float s = 0.f;
    for (int r = 0; r < NWIN; r++) s += pk[r*HD + tid];
    g_kstot[(size_t)img*D + h*HD + tid] = s;
  }
}

// ========== 3xBF16 tensor-core GEMM: C = act(A[MxK] @ B[NxK]^T) =============
// Operands pre-split into bf16 hi/lo planes. fp32 accumulate.
template<int ACT>
__device__ __forceinline__ float actf(float x){
  if (ACT == 1) return x > 0.f ? x + 1.f : expf(x); // phi = elu + 1
  if (ACT == 2) return fmaxf(x, 0.f);               // relu
  return x;
}

__device__ __forceinline__ void mma_bf16(float* d, const uint32_t* a, const uint32_t* b){
  asm volatile(
    "mma.sync.aligned.m16n8k16.row.col.f32.bf16.bf16.f32 "
    "{%0,%1,%2,%3}, {%4,%5,%6,%7}, {%8,%9}, {%0,%1,%2,%3};"
    : "+f"(d[0]), "+f"(d[1]), "+f"(d[2]), "+f"(d[3])
    : "r"(a[0]), "r"(a[1]), "r"(a[2]), "r"(a[3]), "r"(b[0]), "r"(b[1]));
}

#define TBM 128
#define TBN 128
#define TBK 16       // k elements per tile (= 8 u32 words)
#define TST 12       // padded row stride in u32 words (conflict-free for frags)

// OUTMODE 0: fp32 -> C0 (ACT applied), M-guarded.
// OUTMODE 1: hi/lo planes -> Ch/Cl (ACT applied), M multiple of 128.
// OUTMODE 3: fused qkv: N=768; col<256 -> C0 (phi), <512 -> C1 (phi), else C2. Stride 256.
template<int ACT, int OUTMODE>
__global__ void __launch_bounds__(256, 2)
bgemm(const __nv_bfloat16* __restrict__ Ah, const __nv_bfloat16* __restrict__ Al,
      const __nv_bfloat16* __restrict__ Bh, const __nv_bfloat16* __restrict__ Bl,
      float* __restrict__ C0, float* __restrict__ C1, float* __restrict__ C2,
      __nv_bfloat16* __restrict__ Ch, __nv_bfloat16* __restrict__ Cl,
      int M, int N, int K)
{
  __shared__ __align__(16) uint32_t As[2][TBM][TST];
  __shared__ __align__(16) uint32_t Bs[2][TBN][TST];
  const int tid = threadIdx.x;
  const int bm = blockIdx.y*TBM, bn = blockIdx.x*TBN;
  const int warp = tid >> 5, lane = tid & 31;
  const int wm = (warp >> 1)*32, wn = (warp & 1)*64;
  const int grp = lane >> 2, tig = lane & 3;

  float acc[16][4];
  #pragma unroll
  for (int f = 0; f < 16; f++)
    #pragma unroll
    for (int r = 0; r < 4; r++) acc[f][r] = 0.f;

  const int lrow = tid >> 1, lc = tid & 1; // each thread: 1 uint4 (8 halves) per plane
  const bool aok = (bm + lrow) < M;
  const size_t aoff = (size_t)(bm + lrow)*K + lc*8;
  const size_t boff = (size_t)(bn + lrow)*K + lc*8;
  const uint4 z4 = make_uint4(0u,0u,0u,0u);

  uint4 pa0 = aok ? *(const uint4*)(Ah + aoff) : z4;
  uint4 pa1 = aok ? *(const uint4*)(Al + aoff) : z4;
  uint4 pb0 = *(const uint4*)(Bh + boff);
  uint4 pb1 = *(const uint4*)(Bl + boff);

  for (int k0 = 0; k0 < K; k0 += TBK){
    __syncthreads();
    *(uint4*)&As[0][lrow][lc*4] = pa0;
    *(uint4*)&As[1][lrow][lc*4] = pa1;
    *(uint4*)&Bs[0][lrow][lc*4] = pb0;
    *(uint4*)&Bs[1][lrow][lc*4] = pb1;
    __syncthreads();
    if (k0 + TBK < K){
      int kn = k0 + TBK;
      pa0 = aok ? *(const uint4*)(Ah + aoff + kn) : z4;
      pa1 = aok ? *(const uint4*)(Al + aoff + kn) : z4;
      pb0 = *(const uint4*)(Bh + boff + kn);
      pb1 = *(const uint4*)(Bl + boff + kn);
    }
    uint32_t ah[2][4], al[2][4];
    #pragma unroll
    for (int i = 0; i < 2; i++){
      int r = wm + i*16 + grp;
      ah[i][0] = As[0][r    ][tig    ];
      ah[i][1] = As[0][r + 8][tig    ];
      ah[i][2] = As[0][r    ][tig + 4];
      ah[i][3] = As[0][r + 8][tig + 4];
      al[i][0] = As[1][r    ][tig    ];
      al[i][1] = As[1][r + 8][tig    ];
      al[i][2] = As[1][r    ][tig + 4];
      al[i][3] = As[1][r + 8][tig + 4];
    }
    #pragma unroll
    for (int j = 0; j < 8; j++){
      int n = wn + j*8 + grp;
      uint32_t bh[2], bl[2];
      bh[0] = Bs[0][n][tig]; bh[1] = Bs[0][n][tig + 4];
      bl[0] = Bs[1][n][tig]; bl[1] = Bs[1][n][tig + 4];
      #pragma unroll
      for (int i = 0; i < 2; i++){
        mma_bf16(acc[i*8 + j], ah[i], bl);
        mma_bf16(acc[i*8 + j], al[i], bh);
        mma_bf16(acc[i*8 + j], ah[i], bh);
      }
    }
  }

  #pragma unroll
  for (int i = 0; i < 2; i++){
    int r0 = bm + wm + i*16 + grp;
    #pragma unroll
    for (int j = 0; j < 8; j++){
      const float* dd = acc[i*8 + j];
      int cc = wn + j*8 + tig*2;
      if (OUTMODE == 0){
        int c = bn + cc;
        if (r0 < M){
          C0[(size_t)r0*N + c    ] = actf<ACT>(dd[0]);
          C0[(size_t)r0*N + c + 1] = actf<ACT>(dd[1]);
        }
        if (r0 + 8 < M){
          C0[(size_t)(r0+8)*N + c    ] = actf<ACT>(dd[2]);
          C0[(size_t)(r0+8)*N + c + 1] = actf<ACT>(dd[3]);
        }
      } else if (OUTMODE == 1){
        int c = bn + cc;
        #pragma unroll
        for (int rr = 0; rr < 2; rr++){
          float v0 = actf<ACT>(dd[rr*2]), v1 = actf<ACT>(dd[rr*2+1]);
          __nv_bfloat162 h, l;
          h.x = __float2bfloat16(v0); h.y = __float2bfloat16(v1);
          l.x = __float2bfloat16(v0 - __bfloat162float(h.x));
          l.y = __float2bfloat16(v1 - __bfloat162float(h.y));
          size_t o = (size_t)(r0 + rr*8)*N + c;
          *(__nv_bfloat162*)&Ch[o] = h;
          *(__nv_bfloat162*)&Cl[o] = l;
        }
      } else { // OUTMODE 3: fused q/k/v epilogue
        int reg = bn >> 8;                   // 0:q 1:k 2:v
        float* T = (reg == 0) ? C0 : ((reg == 1) ? C1 : C2);
        int c = (bn & 255) + cc;
        float v0 = (reg < 2) ? actf<1>(dd[0]) : dd[0];
        float v1 = (reg < 2) ? actf<1>(dd[1]) : dd[1];
        float v2 = (reg < 2) ? actf<1>(dd[2]) : dd[2];
        float v3 = (reg < 2) ? actf<1>(dd[3]) : dd[3];
        T[(size_t)r0*256 + c    ] = v0;
        T[(size_t)r0*256 + c + 1] = v1;
        T[(size_t)(r0+8)*256 + c    ] = v2;
        T[(size_t)(r0+8)*256 + c + 1] = v3;
      }
    }
  }
}

// ---------------- 6) per-window KV/ksum aggregates ----------------
__global__ void __launch_bounds__(256) k_winagg(){
  int bid = blockIdx.x;
  int h = bid & 7; int wv = bid >> 3;
  int win = wv % NWIN, img = wv / NWIN;
  __shared__ float pk[WTOK*HD];
  __shared__ float vv[WTOK*HD];
  int tid = threadIdx.x;
  for (int i = tid; i < WTOK*HD; i += 256){
    int t = i/HD, d = i%HD;
    int l = spatial_l(win, t);
    size_t off = ((size_t)img*LTOK + l)*D + h*HD + d;
    pk[i] = g_phi_k[off]; vv[i] = g_v[off];
  }
  __syncthreads();
  for (int o = tid; o < HD*HD; o += 256){
    int d = o/HD, j = o%HD;
    float s = 0.f;
    #pragma unroll 8
    for (int t = 0; t < WTOK; t++) s += pk[t*HD + d]*vv[t*HD + j];
    g_KVwin[(((size_t)(img*NWIN + win))*NH + h)*HD*HD + o] = s;
  }
  if (tid < HD){
    float s = 0.f;
    for (int t = 0; t < WTOK; t++) s += pk[t*HD + tid];
    g_kswin[((size_t)img*NWIN + win)*D + h*HD + tid] = s;
  }
}

// ---------------- 7) attention: build KV, apply (warp-local) ----------------
__global__ void __launch_bounds__(256) k_attn(int layer){
  int img = blockIdx.x / NWIN, q = blockIdx.x % NWIN;
  int src = (layer == 0) ? img : (img ^ 2); // cross: flip map, keep batch
  __shared__ float KV[NH*HD*HD]; // 32KB
  __shared__ float ks[D];
  __shared__ float buf[2*D];
  int tid = threadIdx.x;
  for (int i = tid; i < NH*HD*HD; i += 256) KV[i] = g_KVtot[(size_t)src*NH*HD*HD + i];
  ks[tid] = g_kstot[(size_t)src*D + tid];
  __syncthreads();
  for (int k = 0; k < KSEL; k++){
    int w = g_sel[(img*NWIN + q)*KSEL + k];
    buf[tid]     = g_phikr[((size_t)src*NWIN + w)*D + tid];
    buf[D + tid] = g_vr   [((size_t)src*NWIN + w)*D + tid];
    __syncthreads();
    const float* KVW = &g_KVwin[((size_t)(src*NWIN + w))*NH*HD*HD];
    for (int i = tid; i < NH*HD*HD; i += 256){
      int h = i >> 10, d = (i >> 5) & 31, j = i & 31;
      KV[i] += KVW[i] - buf[h*HD + d]*buf[D + h*HD + j];
    }
    ks[tid] += g_kswin[((size_t)src*NWIN + w)*D + tid] - buf[tid];
    __syncthreads();
  }
  // warp-local application: warp = head h, lane = output column j
  int h = tid >> 5, lane = tid & 31;
  float kvreg[32];
  #pragma unroll
  for (int d = 0; d < 32; d++) kvreg[d] = KV[h*HD*HD + d*HD + lane];
  float ksv = ks[h*HD + lane];
  const float* pqb = g_phi_q + (size_t)img*LTOK*D + h*HD + lane;
  for (int t = 0; t < WTOK; t++){
    int l = spatial_l(q, t);
    float pqv = __ldg(pqb + (size_t)l*D);
    float n0 = 0.f, n1 = 0.f, n2 = 0.f, n3 = 0.f;
    #pragma unroll
    for (int d = 0; d < 32; d += 4){
      float p0 = __shfl_sync(0xffffffffu, pqv, d    );
      float p1 = __shfl_sync(0xffffffffu, pqv, d + 1);
      float p2 = __shfl_sync(0xffffffffu, pqv, d + 2);
      float p3 = __shfl_sync(0xffffffffu, pqv, d + 3);
      n0 += p0*kvreg[d];   n1 += p1*kvreg[d+1];
      n2 += p2*kvreg[d+2]; n3 += p3*kvreg[d+3];
    }
    float num = (n0 + n1) + (n2 + n3);
    float dv = pqv*ksv;
    #pragma unroll
    for (int o = 16; o; o >>= 1) dv += __shfl_xor_sync(0xffffffffu, dv, o);
    float r = num / (dv + 1e-6f);
    size_t oi = ((size_t)img*LTOK + l)*D + h*HD + lane;
    split_bf16(r, b_msg_hi[oi], b_msg_lo[oi]);
  }
}

// ---------------- 8) layernorm (in place, fp32) ----------------
__global__ void __launch_bounds__(256) k_ln(float* __restrict__ X,
                                            const float* __restrict__ g,
                                            const float* __restrict__ b){
  size_t row = blockIdx.x;
  int tid = threadIdx.x;
  __shared__ float red[32];
  float x = X[row*D + tid];
  float mu = blockReduceSum(x, red) * (1.f/D);
  float d = x - mu;
  float var = blockReduceSum(d*d, red) * (1.f/D);
  X[row*D + tid] = d*rsqrtf(var + 1e-5f)*g[tid] + b[tid];
}

// ---------------- 9) hcat = [x, msg2] -> bf16 planes ----------------
__global__ void k_hcat(const float* __restrict__ f0, const float* __restrict__ f1,
                       const float* __restrict__ msg2){
  size_t total4 = (size_t)NIMG*LTOK*128;
  for (size_t i = (size_t)blockIdx.x*blockDim.x + threadIdx.x; i < total4;
       i += (size_t)gridDim.x*blockDim.x){
    size_t row = i >> 7; int c4 = (int)(i & 127);
    int img = (int)(row / LTOK); size_t l = row % LTOK;
    float4 v;
    if (c4 < 64){
      const float* F = ((img >> 1) ? f1 : f0) + (((size_t)(img & 1))*LTOK + l)*D;
      v = *(const float4*)&F[c4*4];
    } else {
      v = *(const float4*)&msg2[row*D + (size_t)(c4 - 64)*4];
    }
    size_t o = row*(2*D) + (size_t)c4*4;
    __nv_bfloat162 h01, h23, l01, l23;
    split_bf16(v.x, h01.x, l01.x); split_bf16(v.y, h01.y, l01.y);
    split_bf16(v.z, h23.x, l23.x); split_bf16(v.w, h23.y, l23.y);
    *(__nv_bfloat162*)&b_hcat_hi[o    ] = h01;
    *(__nv_bfloat162*)&b_hcat_hi[o + 2] = h23;
    *(__nv_bfloat162*)&b_hcat_lo[o    ] = l01;
    *(__nv_bfloat162*)&b_hcat_lo[o + 2] = l23;
  }
}

// ---------------- 10) final: out = x + LN(m), + feat planes ----------------
__global__ void __launch_bounds__(256) k_final(const float* __restrict__ f0,
                                               const float* __restrict__ f1,
                                               float* __restrict__ out,
                                               const float* __restrict__ g,
                                               const float* __restrict__ b){
  size_t row = blockIdx.x;
  int tid = threadIdx.x;
  int img = (int)(row / LTOK); size_t l = row % LTOK;
  int m = img >> 1, bb = img & 1;
  __shared__ float red[32];
  float x = g_msg[row*D + tid];
  float mu = blockReduceSum(x, red) * (1.f/D);
  float d = x - mu;
  float var = blockReduceSum(d*d, red) * (1.f/D);
  float msg3 = d*rsqrtf(var + 1e-5f)*g[tid] + b[tid];
  const float* F = (m ? f1 : f0) + ((size_t)bb*LTOK + l)*D;
  size_t oi = (size_t)m*2*LTOK*D + ((size_t)bb*LTOK + l)*D + tid;
  float r = F[tid] + msg3;
  out[oi] = r;
  split_bf16(r, b_feat_hi[oi], b_feat_lo[oi]); // planes for next layer's GEMMs
}

// ---------------- host ----------------
extern "C" void kernel_launch(void* const* d_in, const int* in_sizes, int n_in,
                              void* d_out, int out_size){
  (void)in_sizes; (void)n_in; (void)out_size;
  const float* feat0 = (const float*)d_in[0];
  const float* feat1 = (const float*)d_in[1];
  const float* qW    = (const float*)d_in[8];
  const float* kW    = (const float*)d_in[9];
  const float* vW    = (const float*)d_in[10];
  const float* mW    = (const float*)d_in[11];
  const float* mlpW1 = (const float*)d_in[12];
  const float* mlpW2 = (const float*)d_in[13];
  const float* n1g   = (const float*)d_in[14];
  const float* n1b   = (const float*)d_in[15];
  const float* n2g   = (const float*)d_in[16];
  const float* n2b   = (const float*)d_in[17];
  const float* conv_w= (const float*)d_in[18];
  float* out = (float*)d_out;

  float *p_phiq, *p_phik, *p_v, *p_msg, *p_msg2, *p_phikr, *p_vr;
  __nv_bfloat16 *p_fh, *p_fl, *p_rh, *p_rl, *p_mh, *p_ml, *p_ch, *p_cl,
                *p_hh, *p_hl, *p_wh, *p_wl;
  cudaGetSymbolAddress((void**)&p_phiq, g_phi_q);
  cudaGetSymbolAddress((void**)&p_phik, g_phi_k);
  cudaGetSymbolAddress((void**)&p_v,    g_v);
  cudaGetSymbolAddress((void**)&p_msg,  g_msg);
  cudaGetSymbolAddress((void**)&p_msg2, g_msg2);
  cudaGetSymbolAddress((void**)&p_phikr,g_phikr);
  cudaGetSymbolAddress((void**)&p_vr,   g_vr);
  cudaGetSymbolAddress((void**)&p_fh, b_feat_hi); cudaGetSymbolAddress((void**)&p_fl, b_feat_lo);
  cudaGetSymbolAddress((void**)&p_rh, b_rep_hi);  cudaGetSymbolAddress((void**)&p_rl, b_rep_lo);
  cudaGetSymbolAddress((void**)&p_mh, b_msg_hi);  cudaGetSymbolAddress((void**)&p_ml, b_msg_lo);
  cudaGetSymbolAddress((void**)&p_ch, b_hcat_hi); cudaGetSymbolAddress((void**)&p_cl, b_hcat_lo);
  cudaGetSymbolAddress((void**)&p_hh, b_hid_hi);  cudaGetSymbolAddress((void**)&p_hl, b_hid_lo);
  cudaGetSymbolAddress((void**)&p_wh, b_w_hi);    cudaGetSymbolAddress((void**)&p_wl, b_w_lo);

  const int Mall = NIMG*LTOK;   // 36864
  const int Mmap = 2*LTOK;      // 18432
  const int Mrep = NIMG*NWIN;   // 576

  for (int layer = 0; layer < 2; layer++){
    const float* F0 = layer ? out : feat0;
    const float* F1 = layer ? out + (size_t)2*LTOK*D : feat1;
    int self = (layer == 0);
    int npairs = self ? NIMG : 2;

    k_convw<<<640, 256>>>(qW + (size_t)layer*D*D, kW + (size_t)layer*D*D,
                          vW + (size_t)layer*D*D, mW + (size_t)layer*D*D,
                          mlpW1 + (size_t)layer*2*D*2*D, mlpW2 + (size_t)layer*D*2*D);
    if (layer == 0) k_convfeat<<<4096, 256>>>(feat0, feat1);

    k_rep<<<NIMG*NWIN, 256>>>(F0, F1, conv_w);
    {
      int total = npairs*NWIN*NWIN;
      k_cossim<<<(total + 255)/256, 256>>>(npairs, self);
    }
    k_topk<<<(NIMG*NWIN + 255)/256, 256>>>(self);

    // rep k/v projections (M=576)
    {
      dim3 gr(2, (Mrep + TBM - 1)/TBM);
      bgemm<1,0><<<gr, 256>>>(p_rh, p_rl, p_wh + WOK, p_wl + WOK,
                              p_phikr, nullptr, nullptr, nullptr, nullptr,
                              Mrep, D, D);
      bgemm<0,0><<<gr, 256>>>(p_rh, p_rl, p_wh + WOV, p_wl + WOV,
                              p_vr, nullptr, nullptr, nullptr, nullptr,
                              Mrep, D, D);
    }
    k_reptot<<<NIMG*NH, 256>>>();

    // fused q/k/v projection per map (N=768)
    for (int mm = 0; mm < 2; mm++){
      size_t ofs = (size_t)mm*2*LTOK*D;
      dim3 gq(6, Mmap/TBM);
      bgemm<0,3><<<gq, 256>>>(p_fh + ofs, p_fl + ofs, p_wh + WOQ, p_wl + WOQ,
                              p_phiq + ofs, p_phik + ofs, p_v + ofs, nullptr, nullptr,
                              Mmap, 3*D, D);
    }

    k_winagg<<<NIMG*NWIN*NH, 256>>>();
    k_attn<<<NIMG*NWIN, 256>>>(layer);

    { dim3 g(2, Mall/TBM);
      bgemm<0,0><<<g, 256>>>(p_mh, p_ml, p_wh + WOM, p_wl + WOM,
                             p_msg2, nullptr, nullptr, nullptr, nullptr,
                             Mall, D, D); }
    k_ln<<<Mall, 256>>>(p_msg2, n1g + layer*D, n1b + layer*D);

    k_hcat<<<4096, 256>>>(F0, F1, p_msg2);
    { dim3 g1(4, Mall/TBM);
      bgemm<2,1><<<g1, 256>>>(p_ch, p_cl, p_wh + WO1, p_wl + WO1,
                              nullptr, nullptr, nullptr, p_hh, p_hl,
                              Mall, 2*D, 2*D); } // relu -> hid planes
    { dim3 g2(2, Mall/TBM);
      bgemm<0,0><<<g2, 256>>>(p_hh, p_hl, p_wh + WO2, p_wl + WO2,
                              p_msg, nullptr, nullptr, nullptr, nullptr,
                              Mall, D, 2*D); }

    k_final<<<Mall, 256>>>(F0, F1, out, n2g + layer*D, n2b + layer*D);
  }
}

// round 10
// speedup vs baseline: 2.0401x; 1.1824x over previous
#include <cuda_runtime.h>
#include <cuda_bf16.h>
#include <math.h>
#include <stdint.h>

// ---------------- problem constants ----------------
#define NIMG 4        // (map m, batch b) -> img = m*2+b
#define LTOK 9216     // 96*96
#define D 256
#define NH 8
#define HD 32
#define WGRID 12      // 96/8
#define NWIN 144
#define WTOK 64
#define KSEL 8
#define CN 16
#define NREPAD 640    // rep rows padded to tile multiple (576 -> 640)

// weight-plane buffer offsets (elements)
#define WOQ 0
#define WOK 65536
#define WOV 131072
#define WOM 196608
#define WO1 262144
#define WO2 524288
#define WTOT 655360

// ---------------- scratch (device globals; no allocation allowed) ----------
__device__ float g_phi_q[NIMG*LTOK*D];
__device__ float g_phi_k[NIMG*LTOK*D];
__device__ float g_v    [NIMG*LTOK*D];
__device__ float g_msg  [NIMG*LTOK*D];   // MLP2 output (pre-LN2)
__device__ float g_msg2 [NIMG*LTOK*D];   // mW output (pre-LN1)
__device__ float g_repn [NIMG*NWIN*D];
__device__ float g_phikr[NIMG*NWIN*D];
__device__ float g_vr   [NIMG*NWIN*D];
__device__ float g_sim  [NIMG*NWIN*NWIN];
__device__ int   g_sel  [NIMG*NWIN*KSEL];
__device__ float g_KVwin[NIMG*NWIN*NH*HD*HD];
__device__ float g_kswin[NIMG*NWIN*D];
__device__ float g_KVtot[NIMG*NH*HD*HD];
__device__ float g_kstot[NIMG*D];

// bf16 hi/lo operand planes (aligned for 16B loads). Zero-initialized,
// pad rows (rep 576..639) stay zero forever.
__device__ __align__(128) __nv_bfloat16 b_feat_hi[NIMG*LTOK*D];
__device__ __align__(128) __nv_bfloat16 b_feat_lo[NIMG*LTOK*D];
__device__ __align__(128) __nv_bfloat16 b_rep_hi [NREPAD*D];
__device__ __align__(128) __nv_bfloat16 b_rep_lo [NREPAD*D];
__device__ __align__(128) __nv_bfloat16 b_msg_hi [NIMG*LTOK*D];
__device__ __align__(128) __nv_bfloat16 b_msg_lo [NIMG*LTOK*D];
__device__ __align__(128) __nv_bfloat16 b_hcat_hi[NIMG*LTOK*2*D];
__device__ __align__(128) __nv_bfloat16 b_hcat_lo[NIMG*LTOK*2*D];
__device__ __align__(128) __nv_bfloat16 b_hid_hi [NIMG*LTOK*2*D];
__device__ __align__(128) __nv_bfloat16 b_hid_lo [NIMG*LTOK*2*D];
__device__ __align__(128) __nv_bfloat16 b_w_hi   [WTOT];
__device__ __align__(128) __nv_bfloat16 b_w_lo   [WTOT];

// ---------------- helpers ----------------
__device__ __forceinline__ float phi(float x){ return x > 0.f ? x + 1.f : expf(x); }

__device__ __forceinline__ void split_bf16(float x, __nv_bfloat16& h, __nv_bfloat16& l){
  h = __float2bfloat16(x);
  l = __float2bfloat16(x - __bfloat162float(h));
}

__device__ __forceinline__ float blockReduceSum(float val, float* sbuf){
  __syncthreads();
  int lane = threadIdx.x & 31, wid = threadIdx.x >> 5;
  #pragma unroll
  for (int o = 16; o; o >>= 1) val += __shfl_down_sync(0xffffffffu, val, o);
  if (lane == 0) sbuf[wid] = val;
  __syncthreads();
  float r = (threadIdx.x < (blockDim.x >> 5)) ? sbuf[threadIdx.x] : 0.f;
  if (wid == 0){
    #pragma unroll
    for (int o = 16; o; o >>= 1) r += __shfl_down_sync(0xffffffffu, r, o);
    if (lane == 0) sbuf[0] = r;
  }
  __syncthreads();
  return sbuf[0];
}

__device__ __forceinline__ int spatial_l(int win, int t){
  int wy = win / WGRID, wx = win % WGRID;
  return (wy*8 + (t >> 3))*96 + wx*8 + (t & 7);
}

// ---------------- converters ----------------
__global__ void k_convw(const float* __restrict__ q, const float* __restrict__ k,
                        const float* __restrict__ v, const float* __restrict__ m,
                        const float* __restrict__ w1, const float* __restrict__ w2){
  for (int i = blockIdx.x*blockDim.x + threadIdx.x; i < WTOT; i += gridDim.x*blockDim.x){
    float x;
    if      (i < WOK) x = q[i];
    else if (i < WOV) x = k[i - WOK];
    else if (i < WOM) x = v[i - WOV];
    else if (i < WO1) x = m[i - WOM];
    else if (i < WO2) x = w1[i - WO1];
    else              x = w2[i - WO2];
    split_bf16(x, b_w_hi[i], b_w_lo[i]);
  }
}

// feat planes + hcat feat-half (cols 0..255)
__global__ void k_convfeat(const float* __restrict__ f0, const float* __restrict__ f1){
  const int half = 2*LTOK*D;
  for (int i = blockIdx.x*blockDim.x + threadIdx.x; i < NIMG*LTOK*D;
       i += gridDim.x*blockDim.x){
    float x = (i < half) ? f0[i] : f1[i - half];
    __nv_bfloat16 h, l;
    split_bf16(x, h, l);
    b_feat_hi[i] = h; b_feat_lo[i] = l;
    size_t row = (size_t)(i >> 8); int c = i & 255;
    size_t ho = (row << 9) + c;
    b_hcat_hi[ho] = h; b_hcat_lo[ho] = l;
  }
}

// ---------------- 1) per-window rep ----------------
__global__ void __launch_bounds__(256) k_rep(const float* __restrict__ f0,
                                             const float* __restrict__ f1,
                                             const float* __restrict__ conv_w){
  int img = blockIdx.x / NWIN, win = blockIdx.x % NWIN;
  int m = img >> 1, b = img & 1;
  const float* F = (m ? f1 : f0) + (size_t)b*LTOK*D;
  __shared__ float cw[CN*D];
  __shared__ float simall[WTOK*CN];
  __shared__ float avg[CN];
  __shared__ float red[32];
  int tid = threadIdx.x;
  for (int i = tid; i < CN*D; i += 256) cw[i] = conv_w[i];
  __syncthreads();
  int warp = tid >> 5, lane = tid & 31;
  for (int p = 0; p < 8; p++){
    int t = warp + p*8;
    int l = spatial_l(win, t);
    const float* fr = F + (size_t)l*D;
    float fv[8];
    #pragma unroll
    for (int i = 0; i < 8; i++) fv[i] = fr[lane + 32*i];
    for (int c = 0; c < CN; c++){
      float s = 0.f;
      #pragma unroll
      for (int i = 0; i < 8; i++) s += fv[i]*cw[c*D + lane + 32*i];
      #pragma unroll
      for (int o = 16; o; o >>= 1) s += __shfl_down_sync(0xffffffffu, s, o);
      if (lane == 0) simall[t*CN + c] = s;
    }
  }
  __syncthreads();
  if (tid < WTOK){
    float mx = -1e30f;
    for (int c = 0; c < CN; c++) mx = fmaxf(mx, simall[tid*CN + c]);
    float s = 0.f, e[CN];
    for (int c = 0; c < CN; c++){ e[c] = expf(simall[tid*CN + c] - mx); s += e[c]; }
    float inv = 1.f/s;
    for (int c = 0; c < CN; c++) simall[tid*CN + c] = e[c]*inv;
  }
  __syncthreads();
  if (tid < CN){
    float s = 0.f;
    for (int t = 0; t < WTOK; t++) s += simall[t*CN + tid];
    avg[tid] = s * (1.f/WTOK);
  }
  __syncthreads();
  float r = 0.f;
  for (int c = 0; c < CN; c++) r += avg[c]*cw[c*D + tid];
  size_t oi = (size_t)(img*NWIN + win)*D + tid;
  split_bf16(r, b_rep_hi[oi], b_rep_lo[oi]);
  float n2 = blockReduceSum(r*r, red);
  float nrm = fmaxf(sqrtf(n2), 1e-8f);
  g_repn[oi] = r / nrm;
}

// ---------------- 2) cosine sim ----------------
__global__ void k_cossim(int npairs, int self){
  long total = (long)npairs*NWIN*NWIN;
  for (long idx = (long)blockIdx.x*blockDim.x + threadIdx.x; idx < total;
       idx += (long)gridDim.x*blockDim.x){
    int p = (int)(idx/(NWIN*NWIN)); int rem = (int)(idx%(NWIN*NWIN));
    int q = rem/NWIN, s = rem%NWIN;
    const float* a = &g_repn[((size_t)p*NWIN + q)*D];
    const float* bb = self ? &g_repn[((size_t)p*NWIN + s)*D]
                           : &g_repn[(((size_t)(2+p))*NWIN + s)*D];
    float acc = 0.f;
    #pragma unroll 4
    for (int k = 0; k < D; k += 4){
      float4 av = *(const float4*)&a[k];
      float4 bv = *(const float4*)&bb[k];
      acc += av.x*bv.x + av.y*bv.y + av.z*bv.z + av.w*bv.w;
    }
    g_sim[idx] = acc;
  }
}

// ---------------- 3) top-K (warp per query; stable ties) --------------------
__global__ void k_topk(int self){
  int gw = (blockIdx.x*blockDim.x + threadIdx.x) >> 5;
  int lane = threadIdx.x & 31;
  if (gw >= NIMG*NWIN) return;
  int img = gw/NWIN, q = gw%NWIN;
  size_t base; int sq, ss;
  if (self){ base = (size_t)img*NWIN*NWIN; sq = NWIN; ss = 1; }
  else {
    int b = img & 1, m = img >> 1;
    base = (size_t)b*NWIN*NWIN;
    if (m == 0){ sq = NWIN; ss = 1; } else { sq = 1; ss = NWIN; }
  }
  const float* S = g_sim + base + (size_t)q*sq;
  float v0, v1, v2, v3, v4;
  v0 = S[(size_t)(lane      )*ss];
  v1 = S[(size_t)(lane +  32)*ss];
  v2 = S[(size_t)(lane +  64)*ss];
  v3 = S[(size_t)(lane +  96)*ss];
  v4 = (lane + 128 < NWIN) ? S[(size_t)(lane + 128)*ss] : -1e30f;
  for (int k = 0; k < KSEL; k++){
    float bv = v0; int bi = lane;
    if (v1 > bv){ bv = v1; bi = lane + 32; }
    if (v2 > bv){ bv = v2; bi = lane + 64; }
    if (v3 > bv){ bv = v3; bi = lane + 96; }
    if (v4 > bv){ bv = v4; bi = lane + 128; }
    #pragma unroll
    for (int o = 16; o; o >>= 1){
      float ov = __shfl_xor_sync(0xffffffffu, bv, o);
      int   oi = __shfl_xor_sync(0xffffffffu, bi, o);
      if (ov > bv || (ov == bv && oi < bi)){ bv = ov; bi = oi; }
    }
    if (lane == 0) g_sel[gw*KSEL + k] = bi;
    int wl = bi & 31, wj = bi >> 5;
    if (lane == wl){
      if      (wj == 0) v0 = -1e30f;
      else if (wj == 1) v1 = -1e30f;
      else if (wj == 2) v2 = -1e30f;
      else if (wj == 3) v3 = -1e30f;
      else              v4 = -1e30f;
    }
  }
}

// ---------------- 5) totals over all 144 rep rows ----------------
__global__ void __launch_bounds__(256) k_reptot(){
  int img = blockIdx.x >> 3, h = blockIdx.x & 7;
  __shared__ float pk[NWIN*HD];
  __shared__ float vv[NWIN*HD];
  int tid = threadIdx.x;
  for (int i = tid; i < NWIN*HD; i += 256){
    int r = i/HD, d = i%HD;
    size_t off = ((size_t)img*NWIN + r)*D + h*HD + d;
    pk[i] = g_phikr[off]; vv[i] = g_vr[off];
  }
  __syncthreads();
  for (int o = tid; o < HD*HD; o += 256){
    int d = o/HD, j = o%HD;
    float s = 0.f;
    for (int r = 0; r < NWIN; r++) s += pk[r*HD + d]*vv[r*HD + j];
    g_KVtot[((size_t)img*NH + h)*HD*HD + o] = s;
  }
  if (tid < HD){
    float s = 0.f;
    for (int r = 0; r < NWIN; r++) s += pk[r*HD + tid];
    g_kstot[(size_t)img*D + h*HD + tid] = s;
  }
}

// ====== 3xBF16 GEMM, ldmatrix + cp.async 2-stage: C = act(A @ B^T) ==========
template<int ACT>
__device__ __forceinline__ float actf(float x){
  if (ACT == 1) return x > 0.f ? x + 1.f : expf(x); // phi = elu + 1
  if (ACT == 2) return fmaxf(x, 0.f);               // relu
  return x;
}

__device__ __forceinline__ void mma_bf16(float* d, const uint32_t* a, const uint32_t* b){
  asm volatile(
    "mma.sync.aligned.m16n8k16.row.col.f32.bf16.bf16.f32 "
    "{%0,%1,%2,%3}, {%4,%5,%6,%7}, {%8,%9}, {%0,%1,%2,%3};"
    : "+f"(d[0]), "+f"(d[1]), "+f"(d[2]), "+f"(d[3])
    : "r"(a[0]), "r"(a[1]), "r"(a[2]), "r"(a[3]), "r"(b[0]), "r"(b[1]));
}

__device__ __forceinline__ void ldsm4(uint32_t* r, uint32_t a){
  asm volatile("ldmatrix.sync.aligned.m8n8.x4.shared.b16 {%0,%1,%2,%3}, [%4];"
    : "=r"(r[0]), "=r"(r[1]), "=r"(r[2]), "=r"(r[3]) : "r"(a));
}

__device__ __forceinline__ void cp16(uint32_t s, const void* g){
  asm volatile("cp.async.cg.shared.global [%0], [%1], 16;\n" :: "r"(s), "l"(g));
}
__device__ __forceinline__ void cp_commit(){ asm volatile("cp.async.commit_group;\n"); }
template<int NG> __device__ __forceinline__ void cp_wait(){
  asm volatile("cp.async.wait_group %0;\n" :: "n"(NG));
}

#define BM 128
#define BN 128
#define BK 16
#define SPH 24           // smem row stride in halves (48B; 3 x 16B units -> LDSM conflict-free)
#define PLANE_B 6144     // bytes per plane (128*48)
#define STAGE_B 24576    // bytes per stage (4 planes: Ah, Al, Bh, Bl)

// one cp.async stage: 256 threads x 1 chunk per plane-operand
__device__ __forceinline__ void load_stage(uint32_t sb,
    const __nv_bfloat16* __restrict__ Ah, const __nv_bfloat16* __restrict__ Al,
    const __nv_bfloat16* __restrict__ Bh, const __nv_bfloat16* __restrict__ Bl,
    size_t abase, size_t bbase, int K, int k0, int tid)
{
  int row = tid >> 1, kw = tid & 1;
  uint32_t so = (uint32_t)(row*48 + kw*16);
  size_t go = (size_t)row*K + k0 + kw*8;
  cp16(sb + 0*PLANE_B + so, Ah + abase + go);
  cp16(sb + 1*PLANE_B + so, Al + abase + go);
  cp16(sb + 2*PLANE_B + so, Bh + bbase + go);
  cp16(sb + 3*PLANE_B + so, Bl + bbase + go);
  cp_commit();
}

// OUTMODE 0: fp32 -> C0 (ACT), M-guarded.
// OUTMODE 1: hi/lo planes -> Ch/Cl (ACT), M multiple of 128.
// OUTMODE 3: fused qkv: N=768; region by bn: q(phi)/k(phi)/v. stride 256.
// OUTMODE 4: fused rep kv: N=512; region 0 -> C0 with phi, 1 -> C1. stride 256, M-guarded.
template<int ACT, int OUTMODE>
__global__ void __launch_bounds__(256, 2)
bgemm(const __nv_bfloat16* __restrict__ Ah, const __nv_bfloat16* __restrict__ Al,
      const __nv_bfloat16* __restrict__ Bh, const __nv_bfloat16* __restrict__ Bl,
      float* __restrict__ C0, float* __restrict__ C1, float* __restrict__ C2,
      __nv_bfloat16* __restrict__ Ch, __nv_bfloat16* __restrict__ Cl,
      int M, int N, int K)
{
  __shared__ __align__(16) char smraw[2*STAGE_B]; // 48KB
  uint32_t sb0 = (uint32_t)__cvta_generic_to_shared(smraw);
  const int tid = threadIdx.x;
  const int bm = blockIdx.y*BM, bn = blockIdx.x*BN;
  const int warp = tid >> 5, lane = tid & 31;
  const int wm = (warp >> 1)*32, wn = (warp & 1)*64;
  const int grp = lane >> 2, tig = lane & 3;
  const size_t abase = (size_t)bm*K, bbase = (size_t)bn*K;

  float acc[16][4];
  #pragma unroll
  for (int f = 0; f < 16; f++)
    #pragma unroll
    for (int r = 0; r < 4; r++) acc[f][r] = 0.f;

  const int nk = K/BK;
  load_stage(sb0,           Ah, Al, Bh, Bl, abase, bbase, K, 0,  tid);
  load_stage(sb0 + STAGE_B, Ah, Al, Bh, Bl, abase, bbase, K, BK, tid);

  // ldmatrix lane addresses (bytes, relative to plane base)
  const uint32_t a_lane = (uint32_t)(((wm + (lane & 15))*SPH + (lane >> 4)*8)*2);
  const uint32_t b_lane = (uint32_t)(((wn + (lane & 7) + (lane >> 4)*8)*SPH
                                      + ((lane >> 3) & 1)*8)*2);

  for (int kt = 0; kt < nk; kt++){
    if (kt + 1 < nk) cp_wait<1>(); else cp_wait<0>();
    __syncthreads();
    uint32_t sb = sb0 + (uint32_t)((kt & 1)*STAGE_B);

    uint32_t ah[2][4], al[2][4];
    ldsm4(ah[0], sb + a_lane);
    ldsm4(ah[1], sb + a_lane + 768);           // +16 rows * 48B
    ldsm4(al[0], sb + PLANE_B + a_lane);
    ldsm4(al[1], sb + PLANE_B + a_lane + 768);
    #pragma unroll
    for (int jp = 0; jp < 4; jp++){
      uint32_t bh[4], bl[4];
      ldsm4(bh, sb + 2*PLANE_B + b_lane + jp*768);
      ldsm4(bl, sb + 3*PLANE_B + b_lane + jp*768);
      #pragma unroll
      for (int i = 0; i < 2; i++)
        #pragma unroll
        for (int jj = 0; jj < 2; jj++){
          float* dd = acc[i*8 + jp*2 + jj];
          mma_bf16(dd, ah[i], bl + jj*2);
          mma_bf16(dd, al[i], bh + jj*2);
          mma_bf16(dd, ah[i], bh + jj*2);
        }
    }
    __syncthreads();
    if (kt + 2 < nk)
      load_stage(sb, Ah, Al, Bh, Bl, abase, bbase, K, (kt + 2)*BK, tid);
  }

  #pragma unroll
  for (int i = 0; i < 2; i++){
    int r0 = bm + wm + i*16 + grp;
    #pragma unroll
    for (int j = 0; j < 8; j++){
      const float* dd = acc[i*8 + j];
      int cc = wn + j*8 + tig*2;
      if (OUTMODE == 0){
        int c = bn + cc;
        if (r0 < M){
          C0[(size_t)r0*N + c    ] = actf<ACT>(dd[0]);
          C0[(size_t)r0*N + c + 1] = actf<ACT>(dd[1]);
        }
        if (r0 + 8 < M){
          C0[(size_t)(r0+8)*N + c    ] = actf<ACT>(dd[2]);
          C0[(size_t)(r0+8)*N + c + 1] = actf<ACT>(dd[3]);
        }
      } else if (OUTMODE == 1){
        int c = bn + cc;
        #pragma unroll
        for (int rr = 0; rr < 2; rr++){
          float v0 = actf<ACT>(dd[rr*2]), v1 = actf<ACT>(dd[rr*2+1]);
          __nv_bfloat162 h, l;
          h.x = __float2bfloat16(v0); h.y = __float2bfloat16(v1);
          l.x = __float2bfloat16(v0 - __bfloat162float(h.x));
          l.y = __float2bfloat16(v1 - __bfloat162float(h.y));
          size_t o = (size_t)(r0 + rr*8)*N + c;
          *(__nv_bfloat162*)&Ch[o] = h;
          *(__nv_bfloat162*)&Cl[o] = l;
        }
      } else if (OUTMODE == 3){
        int reg = bn >> 8;                   // 0:q 1:k 2:v
        float* T = (reg == 0) ? C0 : ((reg == 1) ? C1 : C2);
        int c = (bn & 255) + cc;
        float v0 = (reg < 2) ? actf<1>(dd[0]) : dd[0];
        float v1 = (reg < 2) ? actf<1>(dd[1]) : dd[1];
        float v2 = (reg < 2) ? actf<1>(dd[2]) : dd[2];
        float v3 = (reg < 2) ? actf<1>(dd[3]) : dd[3];
        T[(size_t)r0*256 + c    ] = v0;
        T[(size_t)r0*256 + c + 1] = v1;
        T[(size_t)(r0+8)*256 + c    ] = v2;
        T[(size_t)(r0+8)*256 + c + 1] = v3;
      } else { // OUTMODE 4: rep kv
        int reg = bn >> 8;                   // 0: phi(k) -> C0, 1: v -> C1
        float* T = reg ? C1 : C0;
        int c = (bn & 255) + cc;
        float v0 = reg ? dd[0] : actf<1>(dd[0]);
        float v1 = reg ? dd[1] : actf<1>(dd[1]);
        float v2 = reg ? dd[2] : actf<1>(dd[2]);
        float v3 = reg ? dd[3] : actf<1>(dd[3]);
        if (r0 < M){
          T[(size_t)r0*256 + c    ] = v0;
          T[(size_t)r0*256 + c + 1] = v1;
        }
        if (r0 + 8 < M){
          T[(size_t)(r0+8)*256 + c    ] = v2;
          T[(size_t)(r0+8)*256 + c + 1] = v3;
        }
      }
    }
  }
}

// ---------------- 6) per-window KV/ksum aggregates ----------------
__global__ void __launch_bounds__(256) k_winagg(){
  int bid = blockIdx.x;
  int h = bid & 7; int wv = bid >> 3;
  int win = wv % NWIN, img = wv / NWIN;
  __shared__ float pk[WTOK*HD];
  __shared__ float vv[WTOK*HD];
  int tid = threadIdx.x;
  for (int i = tid; i < WTOK*HD; i += 256){
    int t = i/HD, d = i%HD;
    int l = spatial_l(win, t);
    size_t off = ((size_t)img*LTOK + l)*D + h*HD + d;
    pk[i] = g_phi_k[off]; vv[i] = g_v[off];
  }
  __syncthreads();
  for (int o = tid; o < HD*HD; o += 256){
    int d = o/HD, j = o%HD;
    float s = 0.f;
    #pragma unroll 8
    for (int t = 0; t < WTOK; t++) s += pk[t*HD + d]*vv[t*HD + j];
    g_KVwin[(((size_t)(img*NWIN + win))*NH + h)*HD*HD + o] = s;
  }
  if (tid < HD){
    float s = 0.f;
    for (int t = 0; t < WTOK; t++) s += pk[t*HD + tid];
    g_kswin[((size_t)img*NWIN + win)*D + h*HD + tid] = s;
  }
}

// ---------------- 7) attention: build KV, apply (warp-local) ----------------
__global__ void __launch_bounds__(256) k_attn(int layer){
  int img = blockIdx.x / NWIN, q = blockIdx.x % NWIN;
  int src = (layer == 0) ? img : (img ^ 2); // cross: flip map, keep batch
  __shared__ float KV[NH*HD*HD]; // 32KB
  __shared__ float ks[D];
  __shared__ float buf[2*D];
  int tid = threadIdx.x;
  for (int i = tid; i < NH*HD*HD; i += 256) KV[i] = g_KVtot[(size_t)src*NH*HD*HD + i];
  ks[tid] = g_kstot[(size_t)src*D + tid];
  __syncthreads();
  for (int k = 0; k < KSEL; k++){
    int w = g_sel[(img*NWIN + q)*KSEL + k];
    buf[tid]     = g_phikr[((size_t)src*NWIN + w)*D + tid];
    buf[D + tid] = g_vr   [((size_t)src*NWIN + w)*D + tid];
    __syncthreads();
    const float* KVW = &g_KVwin[((size_t)(src*NWIN + w))*NH*HD*HD];
    for (int i = tid; i < NH*HD*HD; i += 256){
      int h = i >> 10, d = (i >> 5) & 31, j = i & 31;
      KV[i] += KVW[i] - buf[h*HD + d]*buf[D + h*HD + j];
    }
    ks[tid] += g_kswin[((size_t)src*NWIN + w)*D + tid] - buf[tid];
    __syncthreads();
  }
  int h = tid >> 5, lane = tid & 31;
  float kvreg[32];
  #pragma unroll
  for (int d = 0; d < 32; d++) kvreg[d] = KV[h*HD*HD + d*HD + lane];
  float ksv = ks[h*HD + lane];
  const float* pqb = g_phi_q + (size_t)img*LTOK*D + h*HD + lane;
  for (int t = 0; t < WTOK; t++){
    int l = spatial_l(q, t);
    float pqv = __ldg(pqb + (size_t)l*D);
    float n0 = 0.f, n1 = 0.f, n2 = 0.f, n3 = 0.f;
    #pragma unroll
    for (int d = 0; d < 32; d += 4){
      float p0 = __shfl_sync(0xffffffffu, pqv, d    );
      float p1 = __shfl_sync(0xffffffffu, pqv, d + 1);
      float p2 = __shfl_sync(0xffffffffu, pqv, d + 2);
      float p3 = __shfl_sync(0xffffffffu, pqv, d + 3);
      n0 += p0*kvreg[d];   n1 += p1*kvreg[d+1];
      n2 += p2*kvreg[d+2]; n3 += p3*kvreg[d+3];
    }
    float num = (n0 + n1) + (n2 + n3);
    float dv = pqv*ksv;
    #pragma unroll
    for (int o = 16; o; o >>= 1) dv += __shfl_xor_sync(0xffffffffu, dv, o);
    float r = num / (dv + 1e-6f);
    size_t oi = ((size_t)img*LTOK + l)*D + h*HD + lane;
    split_bf16(r, b_msg_hi[oi], b_msg_lo[oi]);
  }
}

// ---------------- 8) LN1 fused with hcat msg-half write ----------------
__global__ void __launch_bounds__(256) k_ln_hcat(const float* __restrict__ X,
                                                 const float* __restrict__ g,
                                                 const float* __restrict__ b){
  size_t row = blockIdx.x;
  int tid = threadIdx.x;
  __shared__ float red[32];
  float x = X[row*D + tid];
  float mu = blockReduceSum(x, red) * (1.f/D);
  float d = x - mu;
  float var = blockReduceSum(d*d, red) * (1.f/D);
  float y = d*rsqrtf(var + 1e-5f)*g[tid] + b[tid];
  size_t ho = (row << 9) + 256 + tid;
  split_bf16(y, b_hcat_hi[ho], b_hcat_lo[ho]);
}

// ---------------- 10) final: out = x + LN(m); feat + hcat planes ------------
__global__ void __launch_bounds__(256) k_final(const float* __restrict__ f0,
                                               const float* __restrict__ f1,
                                               float* __restrict__ out,
                                               const float* __restrict__ g,
                                               const float* __restrict__ b){
  size_t row = blockIdx.x;
  int tid = threadIdx.x;
  int img = (int)(row / LTOK); size_t l = row % LTOK;
  int m = img >> 1, bb = img & 1;
  __shared__ float red[32];
  float x = g_msg[row*D + tid];
  float mu = blockReduceSum(x, red) * (1.f/D);
  float d = x - mu;
  float var = blockReduceSum(d*d, red) * (1.f/D);
  float msg3 = d*rsqrtf(var + 1e-5f)*g[tid] + b[tid];
  const float* F = (m ? f1 : f0) + ((size_t)bb*LTOK + l)*D;
  size_t oi = row*D + tid;
  float r = F[tid] + msg3;
  out[oi] = r;
  __nv_bfloat16 h, lo;
  split_bf16(r, h, lo);
  b_feat_hi[oi] = h; b_feat_lo[oi] = lo;
  size_t ho = (row << 9) + tid;
  b_hcat_hi[ho] = h; b_hcat_lo[ho] = lo;
}

// ---------------- host ----------------
extern "C" void kernel_launch(void* const* d_in, const int* in_sizes, int n_in,
                              void* d_out, int out_size){
  (void)in_sizes; (void)n_in; (void)out_size;
  const float* feat0 = (const float*)d_in[0];
  const float* feat1 = (const float*)d_in[1];
  const float* qW    = (const float*)d_in[8];
  const float* kW    = (const float*)d_in[9];
  const float* vW    = (const float*)d_in[10];
  const float* mW    = (const float*)d_in[11];
  const float* mlpW1 = (const float*)d_in[12];
  const float* mlpW2 = (const float*)d_in[13];
  const float* n1g   = (const float*)d_in[14];
  const float* n1b   = (const float*)d_in[15];
  const float* n2g   = (const float*)d_in[16];
  const float* n2b   = (const float*)d_in[17];
  const float* conv_w= (const float*)d_in[18];
  float* out = (float*)d_out;

  float *p_phiq, *p_phik, *p_v, *p_msg, *p_msg2, *p_phikr, *p_vr;
  __nv_bfloat16 *p_fh, *p_fl, *p_rh, *p_rl, *p_mh, *p_ml, *p_ch, *p_cl,
                *p_hh, *p_hl, *p_wh, *p_wl;
  cudaGetSymbolAddress((void**)&p_phiq, g_phi_q);
  cudaGetSymbolAddress((void**)&p_phik, g_phi_k);
  cudaGetSymbolAddress((void**)&p_v,    g_v);
  cudaGetSymbolAddress((void**)&p_msg,  g_msg);
  cudaGetSymbolAddress((void**)&p_msg2, g_msg2);
  cudaGetSymbolAddress((void**)&p_phikr,g_phikr);
  cudaGetSymbolAddress((void**)&p_vr,   g_vr);
  cudaGetSymbolAddress((void**)&p_fh, b_feat_hi); cudaGetSymbolAddress((void**)&p_fl, b_feat_lo);
  cudaGetSymbolAddress((void**)&p_rh, b_rep_hi);  cudaGetSymbolAddress((void**)&p_rl, b_rep_lo);
  cudaGetSymbolAddress((void**)&p_mh, b_msg_hi);  cudaGetSymbolAddress((void**)&p_ml, b_msg_lo);
  cudaGetSymbolAddress((void**)&p_ch, b_hcat_hi); cudaGetSymbolAddress((void**)&p_cl, b_hcat_lo);
  cudaGetSymbolAddress((void**)&p_hh, b_hid_hi);  cudaGetSymbolAddress((void**)&p_hl, b_hid_lo);
  cudaGetSymbolAddress((void**)&p_wh, b_w_hi);    cudaGetSymbolAddress((void**)&p_wl, b_w_lo);

  const int Mall = NIMG*LTOK;   // 36864
  const int Mrep = NIMG*NWIN;   // 576 (buffers padded to 640)

  for (int layer = 0; layer < 2; layer++){
    const float* F0 = layer ? out : feat0;
    const float* F1 = layer ? out + (size_t)2*LTOK*D : feat1;
    int self = (layer == 0);
    int npairs = self ? NIMG : 2;

    k_convw<<<640, 256>>>(qW + (size_t)layer*D*D, kW + (size_t)layer*D*D,
                          vW + (size_t)layer*D*D, mW + (size_t)layer*D*D,
                          mlpW1 + (size_t)layer*2*D*2*D, mlpW2 + (size_t)layer*D*2*D);
    if (layer == 0) k_convfeat<<<4096, 256>>>(feat0, feat1);

    k_rep<<<NIMG*NWIN, 256>>>(F0, F1, conv_w);
    {
      int total = npairs*NWIN*NWIN;
      k_cossim<<<(total + 255)/256, 256>>>(npairs, self);
    }
    k_topk<<<(NIMG*NWIN*32 + 255)/256, 256>>>(self);

    // fused rep k/v projection (N=512, rows padded to 640)
    bgemm<0,4><<<dim3(4, NREPAD/BM), 256>>>(p_rh, p_rl, p_wh + WOK, p_wl + WOK,
                                            p_phikr, p_vr, nullptr, nullptr, nullptr,
                                            Mrep, 512, D);
    k_reptot<<<NIMG*NH, 256>>>();

    // fused q/k/v projection over ALL images (M=36864, N=768)
    bgemm<0,3><<<dim3(6, Mall/BM), 256>>>(p_fh, p_fl, p_wh + WOQ, p_wl + WOQ,
                                          p_phiq, p_phik, p_v, nullptr, nullptr,
                                          Mall, 3*D, D);

    k_winagg<<<NIMG*NWIN*NH, 256>>>();
    k_attn<<<NIMG*NWIN, 256>>>(layer);

    bgemm<0,0><<<dim3(2, Mall/BM), 256>>>(p_mh, p_ml, p_wh + WOM, p_wl + WOM,
                                          p_msg2, nullptr, nullptr, nullptr, nullptr,
                                          Mall, D, D);
    k_ln_hcat<<<Mall, 256>>>(p_msg2, n1g + layer*D, n1b + layer*D);

    bgemm<2,1><<<dim3(4, Mall/BM), 256>>>(p_ch, p_cl, p_wh + WO1, p_wl + WO1,
                                          nullptr, nullptr, nullptr, p_hh, p_hl,
                                          Mall, 2*D, 2*D); // relu -> hid planes
    bgemm<0,0><<<dim3(2, Mall/BM), 256>>>(p_hh, p_hl, p_wh + WO2, p_wl + WO2,
                                          p_msg, nullptr, nullptr, nullptr, nullptr,
                                          Mall, D, 2*D);

    k_final<<<Mall, 256>>>(F0, F1, out, n2g + layer*D, n2b + layer*D);
  }
}

// round 11
// speedup vs baseline: 2.1966x; 1.0767x over previous
#include <cuda_runtime.h>
#include <cuda_bf16.h>
#include <math.h>
#include <stdint.h>

// ---------------- problem constants ----------------
#define NIMG 4        // (map m, batch b) -> img = m*2+b
#define LTOK 9216     // 96*96
#define D 256
#define NH 8
#define HD 32
#define WGRID 12      // 96/8
#define NWIN 144
#define WTOK 64
#define KSEL 8
#define CN 16
#define NREPAD 640    // rep rows padded to tile multiple (576 -> 640)

// weight-plane buffer offsets (elements)
#define WOQ 0
#define WOK 65536
#define WOV 131072
#define WOM 196608
#define WO1 262144
#define WO2 524288
#define WTOT 655360

// ---------------- scratch (device globals; no allocation allowed) ----------
__device__ float g_phi_q[NIMG*LTOK*D];
__device__ float g_phi_k[NIMG*LTOK*D];
__device__ float g_v    [NIMG*LTOK*D];
__device__ float g_msg  [NIMG*LTOK*D];   // MLP2 output (pre-LN2)
__device__ float g_msg2 [NIMG*LTOK*D];   // mW output (pre-LN1)
__device__ float g_repn [NIMG*NWIN*D];
__device__ float g_phikr[NIMG*NWIN*D];
__device__ float g_vr   [NIMG*NWIN*D];
__device__ float g_sim  [NIMG*NWIN*NWIN];
__device__ int   g_sel  [NIMG*NWIN*KSEL];
__device__ float g_KVwin[NIMG*NWIN*NH*HD*HD];
__device__ float g_kswin[NIMG*NWIN*D];
__device__ float g_KVtot[NIMG*NH*HD*HD];
__device__ float g_kstot[NIMG*D];

// bf16 hi/lo operand planes (aligned for 16B loads). Zero-initialized,
// pad rows (rep 576..639) stay zero forever.
__device__ __align__(128) __nv_bfloat16 b_feat_hi[NIMG*LTOK*D];
__device__ __align__(128) __nv_bfloat16 b_feat_lo[NIMG*LTOK*D];
__device__ __align__(128) __nv_bfloat16 b_rep_hi [NREPAD*D];
__device__ __align__(128) __nv_bfloat16 b_rep_lo [NREPAD*D];
__device__ __align__(128) __nv_bfloat16 b_msg_hi [NIMG*LTOK*D];
__device__ __align__(128) __nv_bfloat16 b_msg_lo [NIMG*LTOK*D];
__device__ __align__(128) __nv_bfloat16 b_hcat_hi[NIMG*LTOK*2*D];
__device__ __align__(128) __nv_bfloat16 b_hcat_lo[NIMG*LTOK*2*D];
__device__ __align__(128) __nv_bfloat16 b_hid_hi [NIMG*LTOK*2*D];
__device__ __align__(128) __nv_bfloat16 b_hid_lo [NIMG*LTOK*2*D];
__device__ __align__(128) __nv_bfloat16 b_w_hi   [WTOT];
__device__ __align__(128) __nv_bfloat16 b_w_lo   [WTOT];

// ---------------- helpers ----------------
__device__ __forceinline__ float phi(float x){ return x > 0.f ? x + 1.f : expf(x); }

__device__ __forceinline__ void split_bf16(float x, __nv_bfloat16& h, __nv_bfloat16& l){
  h = __float2bfloat16(x);
  l = __float2bfloat16(x - __bfloat162float(h));
}

__device__ __forceinline__ float blockReduceSum(float val, float* sbuf){
  __syncthreads();
  int lane = threadIdx.x & 31, wid = threadIdx.x >> 5;
  #pragma unroll
  for (int o = 16; o; o >>= 1) val += __shfl_down_sync(0xffffffffu, val, o);
  if (lane == 0) sbuf[wid] = val;
  __syncthreads();
  float r = (threadIdx.x < (blockDim.x >> 5)) ? sbuf[threadIdx.x] : 0.f;
  if (wid == 0){
    #pragma unroll
    for (int o = 16; o; o >>= 1) r += __shfl_down_sync(0xffffffffu, r, o);
    if (lane == 0) sbuf[0] = r;
  }
  __syncthreads();
  return sbuf[0];
}

__device__ __forceinline__ int spatial_l(int win, int t){
  int wy = win / WGRID, wx = win % WGRID;
  return (wy*8 + (t >> 3))*96 + wx*8 + (t & 7);
}

// ---------------- converters ----------------
__global__ void k_convw(const float* __restrict__ q, const float* __restrict__ k,
                        const float* __restrict__ v, const float* __restrict__ m,
                        const float* __restrict__ w1, const float* __restrict__ w2){
  for (int i = blockIdx.x*blockDim.x + threadIdx.x; i < WTOT; i += gridDim.x*blockDim.x){
    float x;
    if      (i < WOK) x = q[i];
    else if (i < WOV) x = k[i - WOK];
    else if (i < WOM) x = v[i - WOV];
    else if (i < WO1) x = m[i - WOM];
    else if (i < WO2) x = w1[i - WO1];
    else              x = w2[i - WO2];
    split_bf16(x, b_w_hi[i], b_w_lo[i]);
  }
}

// feat planes + hcat feat-half (cols 0..255)
__global__ void k_convfeat(const float* __restrict__ f0, const float* __restrict__ f1){
  const int half = 2*LTOK*D;
  for (int i = blockIdx.x*blockDim.x + threadIdx.x; i < NIMG*LTOK*D;
       i += gridDim.x*blockDim.x){
    float x = (i < half) ? f0[i] : f1[i - half];
    __nv_bfloat16 h, l;
    split_bf16(x, h, l);
    b_feat_hi[i] = h; b_feat_lo[i] = l;
    size_t row = (size_t)(i >> 8); int c = i & 255;
    size_t ho = (row << 9) + c;
    b_hcat_hi[ho] = h; b_hcat_lo[ho] = l;
  }
}

// ---------------- 1) per-window rep ----------------
__global__ void __launch_bounds__(256) k_rep(const float* __restrict__ f0,
                                             const float* __restrict__ f1,
                                             const float* __restrict__ conv_w){
  int img = blockIdx.x / NWIN, win = blockIdx.x % NWIN;
  int m = img >> 1, b = img & 1;
  const float* F = (m ? f1 : f0) + (size_t)b*LTOK*D;
  __shared__ float cw[CN*D];
  __shared__ float simall[WTOK*CN];
  __shared__ float avg[CN];
  __shared__ float red[32];
  int tid = threadIdx.x;
  for (int i = tid; i < CN*D; i += 256) cw[i] = conv_w[i];
  __syncthreads();
  int warp = tid >> 5, lane = tid & 31;
  for (int p = 0; p < 8; p++){
    int t = warp + p*8;
    int l = spatial_l(win, t);
    const float* fr = F + (size_t)l*D;
    float fv[8];
    #pragma unroll
    for (int i = 0; i < 8; i++) fv[i] = fr[lane + 32*i];
    for (int c = 0; c < CN; c++){
      float s = 0.f;
      #pragma unroll
      for (int i = 0; i < 8; i++) s += fv[i]*cw[c*D + lane + 32*i];
      #pragma unroll
      for (int o = 16; o; o >>= 1) s += __shfl_down_sync(0xffffffffu, s, o);
      if (lane == 0) simall[t*CN + c] = s;
    }
  }
  __syncthreads();
  if (tid < WTOK){
    float mx = -1e30f;
    for (int c = 0; c < CN; c++) mx = fmaxf(mx, simall[tid*CN + c]);
    float s = 0.f, e[CN];
    for (int c = 0; c < CN; c++){ e[c] = expf(simall[tid*CN + c] - mx); s += e[c]; }
    float inv = 1.f/s;
    for (int c = 0; c < CN; c++) simall[tid*CN + c] = e[c]*inv;
  }
  __syncthreads();
  if (tid < CN){
    float s = 0.f;
    for (int t = 0; t < WTOK; t++) s += simall[t*CN + tid];
    avg[tid] = s * (1.f/WTOK);
  }
  __syncthreads();
  float r = 0.f;
  for (int c = 0; c < CN; c++) r += avg[c]*cw[c*D + tid];
  size_t oi = (size_t)(img*NWIN + win)*D + tid;
  split_bf16(r, b_rep_hi[oi], b_rep_lo[oi]);
  float n2 = blockReduceSum(r*r, red);
  float nrm = fmaxf(sqrtf(n2), 1e-8f);
  g_repn[oi] = r / nrm;
}

// ---------------- 2) cosine sim (2x2 register blocking) ----------------
__global__ void k_cossim(int npairs, int self){
  const int H2 = NWIN/2;                 // 72
  long total = (long)npairs*H2*H2;
  for (long idx = (long)blockIdx.x*blockDim.x + threadIdx.x; idx < total;
       idx += (long)gridDim.x*blockDim.x){
    int p = (int)(idx/(H2*H2)); int rem = (int)(idx%(H2*H2));
    int q = (rem/H2)*2, s = (rem%H2)*2;
    const float* a0 = &g_repn[((size_t)p*NWIN + q)*D];
    const float* a1 = a0 + D;
    const float* b0 = self ? &g_repn[((size_t)p*NWIN + s)*D]
                           : &g_repn[(((size_t)(2+p))*NWIN + s)*D];
    const float* b1 = b0 + D;
    float c00 = 0.f, c01 = 0.f, c10 = 0.f, c11 = 0.f;
    #pragma unroll 4
    for (int k = 0; k < D; k += 4){
      float4 av0 = *(const float4*)&a0[k];
      float4 av1 = *(const float4*)&a1[k];
      float4 bv0 = *(const float4*)&b0[k];
      float4 bv1 = *(const float4*)&b1[k];
      c00 += av0.x*bv0.x + av0.y*bv0.y + av0.z*bv0.z + av0.w*bv0.w;
      c01 += av0.x*bv1.x + av0.y*bv1.y + av0.z*bv1.z + av0.w*bv1.w;
      c10 += av1.x*bv0.x + av1.y*bv0.y + av1.z*bv0.z + av1.w*bv0.w;
      c11 += av1.x*bv1.x + av1.y*bv1.y + av1.z*bv1.z + av1.w*bv1.w;
    }
    size_t ob = (size_t)p*NWIN*NWIN + (size_t)q*NWIN + s;
    g_sim[ob]            = c00;
    g_sim[ob + 1]        = c01;
    g_sim[ob + NWIN]     = c10;
    g_sim[ob + NWIN + 1] = c11;
  }
}

// ---------------- 3) top-K (warp per query; stable ties) --------------------
__global__ void k_topk(int self){
  int gw = (blockIdx.x*blockDim.x + threadIdx.x) >> 5;
  int lane = threadIdx.x & 31;
  if (gw >= NIMG*NWIN) return;
  int img = gw/NWIN, q = gw%NWIN;
  size_t base; int sq, ss;
  if (self){ base = (size_t)img*NWIN*NWIN; sq = NWIN; ss = 1; }
  else {
    int b = img & 1, m = img >> 1;
    base = (size_t)b*NWIN*NWIN;
    if (m == 0){ sq = NWIN; ss = 1; } else { sq = 1; ss = NWIN; }
  }
  const float* S = g_sim + base + (size_t)q*sq;
  float v0, v1, v2, v3, v4;
  v0 = S[(size_t)(lane      )*ss];
  v1 = S[(size_t)(lane +  32)*ss];
  v2 = S[(size_t)(lane +  64)*ss];
  v3 = S[(size_t)(lane +  96)*ss];
  v4 = (lane + 128 < NWIN) ? S[(size_t)(lane + 128)*ss] : -1e30f;
  for (int k = 0; k < KSEL; k++){
    float bv = v0; int bi = lane;
    if (v1 > bv){ bv = v1; bi = lane + 32; }
    if (v2 > bv){ bv = v2; bi = lane + 64; }
    if (v3 > bv){ bv = v3; bi = lane + 96; }
    if (v4 > bv){ bv = v4; bi = lane + 128; }
    #pragma unroll
    for (int o = 16; o; o >>= 1){
      float ov = __shfl_xor_sync(0xffffffffu, bv, o);
      int   oi = __shfl_xor_sync(0xffffffffu, bi, o);
      if (ov > bv || (ov == bv && oi < bi)){ bv = ov; bi = oi; }
    }
    if (lane == 0) g_sel[gw*KSEL + k] = bi;
    int wl = bi & 31, wj = bi >> 5;
    if (lane == wl){
      if      (wj == 0) v0 = -1e30f;
      else if (wj == 1) v1 = -1e30f;
      else if (wj == 2) v2 = -1e30f;
      else if (wj == 3) v3 = -1e30f;
      else              v4 = -1e30f;
    }
  }
}

// ---------------- 5) totals over all 144 rep rows ----------------
__global__ void __launch_bounds__(256) k_reptot(){
  int img = blockIdx.x >> 3, h = blockIdx.x & 7;
  __shared__ float pk[NWIN*HD];
  __shared__ float vv[NWIN*HD];
  int tid = threadIdx.x;
  for (int i = tid; i < NWIN*HD; i += 256){
    int r = i/HD, d = i%HD;
    size_t off = ((size_t)img*NWIN + r)*D + h*HD + d;
    pk[i] = g_phikr[off]; vv[i] = g_vr[off];
  }
  __syncthreads();
  for (int o = tid; o < HD*HD; o += 256){
    int d = o/HD, j = o%HD;
    float s = 0.f;
    for (int r = 0; r < NWIN; r++) s += pk[r*HD + d]*vv[r*HD + j];
    g_KVtot[((size_t)img*NH + h)*HD*HD + o] = s;
  }
  if (tid < HD){
    float s = 0.f;
    for (int r = 0; r < NWIN; r++) s += pk[r*HD + tid];
    g_kstot[(size_t)img*D + h*HD + tid] = s;
  }
}

// ====== 3xBF16 GEMM, ldmatrix + cp.async 3-stage: C = act(A @ B^T) ==========
template<int ACT>
__device__ __forceinline__ float actf(float x){
  if (ACT == 1) return x > 0.f ? x + 1.f : expf(x); // phi = elu + 1
  if (ACT == 2) return fmaxf(x, 0.f);               // relu
  return x;
}

__device__ __forceinline__ void mma_bf16(float* d, const uint32_t* a, const uint32_t* b){
  asm volatile(
    "mma.sync.aligned.m16n8k16.row.col.f32.bf16.bf16.f32 "
    "{%0,%1,%2,%3}, {%4,%5,%6,%7}, {%8,%9}, {%0,%1,%2,%3};"
    : "+f"(d[0]), "+f"(d[1]), "+f"(d[2]), "+f"(d[3])
    : "r"(a[0]), "r"(a[1]), "r"(a[2]), "r"(a[3]), "r"(b[0]), "r"(b[1]));
}

__device__ __forceinline__ void ldsm4(uint32_t* r, uint32_t a){
  asm volatile("ldmatrix.sync.aligned.m8n8.x4.shared.b16 {%0,%1,%2,%3}, [%4];"
    : "=r"(r[0]), "=r"(r[1]), "=r"(r[2]), "=r"(r[3]) : "r"(a));
}

__device__ __forceinline__ void cp16(uint32_t s, const void* g){
  asm volatile("cp.async.cg.shared.global [%0], [%1], 16;\n" :: "r"(s), "l"(g));
}
__device__ __forceinline__ void cp_commit(){ asm volatile("cp.async.commit_group;\n"); }
template<int NG> __device__ __forceinline__ void cp_wait(){
  asm volatile("cp.async.wait_group %0;\n" :: "n"(NG));
}

#define BM 128
#define BN 128
#define BK 16
#define SPH 24           // smem row stride in halves (48B; 3 x 16B units -> LDSM conflict-free)
#define PLANE_B 6144     // bytes per plane (128*48)
#define STAGE_B 24576    // bytes per stage (4 planes: Ah, Al, Bh, Bl)
#define NSTAGE 3
#define SMEM_DYN (NSTAGE*STAGE_B)   // 73728 bytes (dynamic, opt-in)

// one cp.async stage: 256 threads x 1 chunk per plane-operand
__device__ __forceinline__ void load_stage(uint32_t sb,
    const __nv_bfloat16* __restrict__ Ah, const __nv_bfloat16* __restrict__ Al,
    const __nv_bfloat16* __restrict__ Bh, const __nv_bfloat16* __restrict__ Bl,
    size_t abase, size_t bbase, int K, int k0, int tid)
{
  int row = tid >> 1, kw = tid & 1;
  uint32_t so = (uint32_t)(row*48 + kw*16);
  size_t go = (size_t)row*K + k0 + kw*8;
  cp16(sb + 0*PLANE_B + so, Ah + abase + go);
  cp16(sb + 1*PLANE_B + so, Al + abase + go);
  cp16(sb + 2*PLANE_B + so, Bh + bbase + go);
  cp16(sb + 3*PLANE_B + so, Bl + bbase + go);
  cp_commit();
}

// OUTMODE 0: fp32 -> C0 (ACT), M-guarded.
// OUTMODE 1: hi/lo planes -> Ch/Cl (ACT), M multiple of 128.
// OUTMODE 3: fused qkv: N=768; region by bn: q(phi)/k(phi)/v. stride 256.
// OUTMODE 4: fused rep kv: N=512; region 0 -> C0 with phi, 1 -> C1. stride 256, M-guarded.
template<int ACT, int OUTMODE>
__global__ void __launch_bounds__(256, 2)
bgemm(const __nv_bfloat16* __restrict__ Ah, const __nv_bfloat16* __restrict__ Al,
      const __nv_bfloat16* __restrict__ Bh, const __nv_bfloat16* __restrict__ Bl,
      float* __restrict__ C0, float* __restrict__ C1, float* __restrict__ C2,
      __nv_bfloat16* __restrict__ Ch, __nv_bfloat16* __restrict__ Cl,
      int M, int N, int K)
{
  extern __shared__ __align__(16) char smraw[]; // NSTAGE * 24576 dynamic
  uint32_t sb0 = (uint32_t)__cvta_generic_to_shared(smraw);
  const int tid = threadIdx.x;
  const int bm = blockIdx.y*BM, bn = blockIdx.x*BN;
  const int warp = tid >> 5, lane = tid & 31;
  const int wm = (warp >> 1)*32, wn = (warp & 1)*64;
  const int grp = lane >> 2, tig = lane & 3;
  const size_t abase = (size_t)bm*K, bbase = (size_t)bn*K;

  float acc[16][4];
  #pragma unroll
  for (int f = 0; f < 16; f++)
    #pragma unroll
    for (int r = 0; r < 4; r++) acc[f][r] = 0.f;

  const int nk = K/BK;
  load_stage(sb0,           Ah, Al, Bh, Bl, abase, bbase, K, 0,  tid);
  load_stage(sb0 + STAGE_B, Ah, Al, Bh, Bl, abase, bbase, K, BK, tid);

  // ldmatrix lane addresses (bytes, relative to plane base)
  const uint32_t a_lane = (uint32_t)(((wm + (lane & 15))*SPH + (lane >> 4)*8)*2);
  const uint32_t b_lane = (uint32_t)(((wn + (lane & 7) + (lane >> 4)*8)*SPH
                                      + ((lane >> 3) & 1)*8)*2);

  int stg = 0;                 // stage index of tile kt
  for (int kt = 0; kt < nk; kt++){
    if (kt + 1 < nk) cp_wait<1>(); else cp_wait<0>();
    __syncthreads();
    uint32_t sb = sb0 + (uint32_t)(stg*STAGE_B);
    // issue next-next stage load first (buffer (kt+2)%3 == (kt-1)%3, safe post-sync)
    if (kt + 2 < nk){
      int ns = stg + 2; if (ns >= NSTAGE) ns -= NSTAGE;
      load_stage(sb0 + (uint32_t)(ns*STAGE_B), Ah, Al, Bh, Bl,
                 abase, bbase, K, (kt + 2)*BK, tid);
    }

    uint32_t ah[2][4], al[2][4];
    ldsm4(ah[0], sb + a_lane);
    ldsm4(ah[1], sb + a_lane + 768);           // +16 rows * 48B
    ldsm4(al[0], sb + PLANE_B + a_lane);
    ldsm4(al[1], sb + PLANE_B + a_lane + 768);
    #pragma unroll
    for (int jp = 0; jp < 4; jp++){
      uint32_t bh[4], bl[4];
      ldsm4(bh, sb + 2*PLANE_B + b_lane + jp*768);
      ldsm4(bl, sb + 3*PLANE_B + b_lane + jp*768);
      #pragma unroll
      for (int i = 0; i < 2; i++)
        #pragma unroll
        for (int jj = 0; jj < 2; jj++){
          float* dd = acc[i*8 + jp*2 + jj];
          mma_bf16(dd, ah[i], bl + jj*2);
          mma_bf16(dd, al[i], bh + jj*2);
          mma_bf16(dd, ah[i], bh + jj*2);
        }
    }
    if (++stg == NSTAGE) stg = 0;
  }

  #pragma unroll
  for (int i = 0; i < 2; i++){
    int r0 = bm + wm + i*16 + grp;
    #pragma unroll
    for (int j = 0; j < 8; j++){
      const float* dd = acc[i*8 + j];
      int cc = wn + j*8 + tig*2;
      if (OUTMODE == 0){
        int c = bn + cc;
        if (r0 < M){
          C0[(size_t)r0*N + c    ] = actf<ACT>(dd[0]);
          C0[(size_t)r0*N + c + 1] = actf<ACT>(dd[1]);
        }
        if (r0 + 8 < M){
          C0[(size_t)(r0+8)*N + c    ] = actf<ACT>(dd[2]);
          C0[(size_t)(r0+8)*N + c + 1] = actf<ACT>(dd[3]);
        }
      } else if (OUTMODE == 1){
        int c = bn + cc;
        #pragma unroll
        for (int rr = 0; rr < 2; rr++){
          float v0 = actf<ACT>(dd[rr*2]), v1 = actf<ACT>(dd[rr*2+1]);
          __nv_bfloat162 h, l;
          h.x = __float2bfloat16(v0); h.y = __float2bfloat16(v1);
          l.x = __float2bfloat16(v0 - __bfloat162float(h.x));
          l.y = __float2bfloat16(v1 - __bfloat162float(h.y));
          size_t o = (size_t)(r0 + rr*8)*N + c;
          *(__nv_bfloat162*)&Ch[o] = h;
          *(__nv_bfloat162*)&Cl[o] = l;
        }
      } else if (OUTMODE == 3){
        int reg = bn >> 8;                   // 0:q 1:k 2:v
        float* T = (reg == 0) ? C0 : ((reg == 1) ? C1 : C2);
        int c = (bn & 255) + cc;
        float v0 = (reg < 2) ? actf<1>(dd[0]) : dd[0];
        float v1 = (reg < 2) ? actf<1>(dd[1]) : dd[1];
        float v2 = (reg < 2) ? actf<1>(dd[2]) : dd[2];
        float v3 = (reg < 2) ? actf<1>(dd[3]) : dd[3];
        T[(size_t)r0*256 + c    ] = v0;
        T[(size_t)r0*256 + c + 1] = v1;
        T[(size_t)(r0+8)*256 + c    ] = v2;
        T[(size_t)(r0+8)*256 + c + 1] = v3;
      } else { // OUTMODE 4: rep kv
        int reg = bn >> 8;                   // 0: phi(k) -> C0, 1: v -> C1
        float* T = reg ? C1 : C0;
        int c = (bn & 255) + cc;
        float v0 = reg ? dd[0] : actf<1>(dd[0]);
        float v1 = reg ? dd[1] : actf<1>(dd[1]);
        float v2 = reg ? dd[2] : actf<1>(dd[2]);
        float v3 = reg ? dd[3] : actf<1>(dd[3]);
        if (r0 < M){
          T[(size_t)r0*256 + c    ] = v0;
          T[(size_t)r0*256 + c + 1] = v1;
        }
        if (r0 + 8 < M){
          T[(size_t)(r0+8)*256 + c    ] = v2;
          T[(size_t)(r0+8)*256 + c + 1] = v3;
        }
      }
    }
  }
}

// ---------------- 6) per-window KV/ksum aggregates (vectorized) -------------
__global__ void __launch_bounds__(256) k_winagg(){
  int bid = blockIdx.x;
  int h = bid & 7; int wv = bid >> 3;
  int win = wv % NWIN, img = wv / NWIN;
  __shared__ float pk[WTOK*HD];
  __shared__ float vv[WTOK*HD];
  int tid = threadIdx.x;
  // float4 loads: 512 chunks over 256 threads
  #pragma unroll
  for (int i = tid; i < WTOK*HD/4; i += 256){
    int t = i >> 3, d4 = (i & 7)*4;
    int l = spatial_l(win, t);
    size_t off = ((size_t)img*LTOK + l)*D + h*HD + d4;
    *(float4*)&pk[t*HD + d4] = *(const float4*)&g_phi_k[off];
    *(float4*)&vv[t*HD + d4] = *(const float4*)&g_v[off];
  }
  __syncthreads();
  // 4 outputs per thread: d = tid>>3 (broadcast pk), j0 = (tid&7)*4 (LDS.128)
  int d = tid >> 3, j0 = (tid & 7)*4;
  float a0 = 0.f, a1 = 0.f, a2 = 0.f, a3 = 0.f;
  #pragma unroll 8
  for (int t = 0; t < WTOK; t++){
    float p = pk[t*HD + d];
    float4 v4 = *(const float4*)&vv[t*HD + j0];
    a0 += p*v4.x; a1 += p*v4.y; a2 += p*v4.z; a3 += p*v4.w;
  }
  size_t ob = (((size_t)(img*NWIN + win))*NH + h)*HD*HD + (size_t)d*HD + j0;
  *(float4*)&g_KVwin[ob] = make_float4(a0, a1, a2, a3);
  if (tid < HD){
    float s = 0.f;
    for (int t = 0; t < WTOK; t++) s += pk[t*HD + tid];
    g_kswin[((size_t)img*NWIN + win)*D + h*HD + tid] = s;
  }
}

// ---------------- 7) attention: build KV, apply (warp-local) ----------------
__global__ void __launch_bounds__(256) k_attn(int layer){
  int img = blockIdx.x / NWIN, q = blockIdx.x % NWIN;
  int src = (layer == 0) ? img : (img ^ 2); // cross: flip map, keep batch
  __shared__ float KV[NH*HD*HD]; // 32KB
  __shared__ float ks[D];
  __shared__ float buf[2*D];
  int tid = threadIdx.x;
  for (int i = tid; i < NH*HD*HD; i += 256) KV[i] = g_KVtot[(size_t)src*NH*HD*HD + i];
  ks[tid] = g_kstot[(size_t)src*D + tid];
  __syncthreads();
  for (int k = 0; k < KSEL; k++){
    int w = g_sel[(img*NWIN + q)*KSEL + k];
    buf[tid]     = g_phikr[((size_t)src*NWIN + w)*D + tid];
    buf[D + tid] = g_vr   [((size_t)src*NWIN + w)*D + tid];
    __syncthreads();
    const float* KVW = &g_KVwin[((size_t)(src*NWIN + w))*NH*HD*HD];
    for (int i = tid; i < NH*HD*HD; i += 256){
      int h = i >> 10, d = (i >> 5) & 31, j = i & 31;
      KV[i] += KVW[i] - buf[h*HD + d]*buf[D + h*HD + j];
    }
    ks[tid] += g_kswin[((size_t)src*NWIN + w)*D + tid] - buf[tid];
    __syncthreads();
  }
  int h = tid >> 5, lane = tid & 31;
  float kvreg[32];
  #pragma unroll
  for (int d = 0; d < 32; d++) kvreg[d] = KV[h*HD*HD + d*HD + lane];
  float ksv = ks[h*HD + lane];
  const float* pqb = g_phi_q + (size_t)img*LTOK*D + h*HD + lane;
  for (int t = 0; t < WTOK; t++){
    int l = spatial_l(q, t);
    float pqv = __ldg(pqb + (size_t)l*D);
    float n0 = 0.f, n1 = 0.f, n2 = 0.f, n3 = 0.f;
    #pragma unroll
    for (int d = 0; d < 32; d += 4){
      float p0 = __shfl_sync(0xffffffffu, pqv, d    );
      float p1 = __shfl_sync(0xffffffffu, pqv, d + 1);
      float p2 = __shfl_sync(0xffffffffu, pqv, d + 2);
      float p3 = __shfl_sync(0xffffffffu, pqv, d + 3);
      n0 += p0*kvreg[d];   n1 += p1*kvreg[d+1];
      n2 += p2*kvreg[d+2]; n3 += p3*kvreg[d+3];
    }
    float num = (n0 + n1) + (n2 + n3);
    float dv = pqv*ksv;
    #pragma unroll
    for (int o = 16; o; o >>= 1) dv += __shfl_xor_sync(0xffffffffu, dv, o);
    float r = num / (dv + 1e-6f);
    size_t oi = ((size_t)img*LTOK + l)*D + h*HD + lane;
    split_bf16(r, b_msg_hi[oi], b_msg_lo[oi]);
  }
}

// ---------------- 8) LN1 fused with hcat msg-half write ----------------
__global__ void __launch_bounds__(256) k_ln_hcat(const float* __restrict__ X,
                                                 const float* __restrict__ g,
                                                 const float* __restrict__ b){
  size_t row = blockIdx.x;
  int tid = threadIdx.x;
  __shared__ float red[32];
  float x = X[row*D + tid];
  float mu = blockReduceSum(x, red) * (1.f/D);
  float d = x - mu;
  float var = blockReduceSum(d*d, red) * (1.f/D);
  float y = d*rsqrtf(var + 1e-5f)*g[tid] + b[tid];
  size_t ho = (row << 9) + 256 + tid;
  split_bf16(y, b_hcat_hi[ho], b_hcat_lo[ho]);
}

// ---------------- 10) final: out = x + LN(m); feat + hcat planes ------------
__global__ void __launch_bounds__(256) k_final(const float* __restrict__ f0,
                                               const float* __restrict__ f1,
                                               float* __restrict__ out,
                                               const float* __restrict__ g,
                                               const float* __restrict__ b){
  size_t row = blockIdx.x;
  int tid = threadIdx.x;
  int img = (int)(row / LTOK); size_t l = row % LTOK;
  int m = img >> 1, bb = img & 1;
  __shared__ float red[32];
  float x = g_msg[row*D + tid];
  float mu = blockReduceSum(x, red) * (1.f/D);
  float d = x - mu;
  float var = blockReduceSum(d*d, red) * (1.f/D);
  float msg3 = d*rsqrtf(var + 1e-5f)*g[tid] + b[tid];
  const float* F = (m ? f1 : f0) + ((size_t)bb*LTOK + l)*D;
  size_t oi = row*D + tid;
  float r = F[tid] + msg3;
  out[oi] = r;
  __nv_bfloat16 h, lo;
  split_bf16(r, h, lo);
  b_feat_hi[oi] = h; b_feat_lo[oi] = lo;
  size_t ho = (row << 9) + tid;
  b_hcat_hi[ho] = h; b_hcat_lo[ho] = lo;
}

// ---------------- host ----------------
extern "C" void kernel_launch(void* const* d_in, const int* in_sizes, int n_in,
                              void* d_out, int out_size){
  (void)in_sizes; (void)n_in; (void)out_size;
  const float* feat0 = (const float*)d_in[0];
  const float* feat1 = (const float*)d_in[1];
  const float* qW    = (const float*)d_in[8];
  const float* kW    = (const float*)d_in[9];
  const float* vW    = (const float*)d_in[10];
  const float* mW    = (const float*)d_in[11];
  const float* mlpW1 = (const float*)d_in[12];
  const float* mlpW2 = (const float*)d_in[13];
  const float* n1g   = (const float*)d_in[14];
  const float* n1b   = (const float*)d_in[15];
  const float* n2g   = (const float*)d_in[16];
  const float* n2b   = (const float*)d_in[17];
  const float* conv_w= (const float*)d_in[18];
  float* out = (float*)d_out;

  // opt-in dynamic smem (idempotent; host-side attr set, not a stream op)
  cudaFuncSetAttribute((const void*)bgemm<0,0>, cudaFuncAttributeMaxDynamicSharedMemorySize, SMEM_DYN);
  cudaFuncSetAttribute((const void*)bgemm<0,3>, cudaFuncAttributeMaxDynamicSharedMemorySize, SMEM_DYN);
  cudaFuncSetAttribute((const void*)bgemm<0,4>, cudaFuncAttributeMaxDynamicSharedMemorySize, SMEM_DYN);
  cudaFuncSetAttribute((const void*)bgemm<2,1>, cudaFuncAttributeMaxDynamicSharedMemorySize, SMEM_DYN);

  float *p_phiq, *p_phik, *p_v, *p_msg, *p_msg2, *p_phikr, *p_vr;
  __nv_bfloat16 *p_fh, *p_fl, *p_rh, *p_rl, *p_mh, *p_ml, *p_ch, *p_cl,
                *p_hh, *p_hl, *p_wh, *p_wl;
  cudaGetSymbolAddress((void**)&p_phiq, g_phi_q);
  cudaGetSymbolAddress((void**)&p_phik, g_phi_k);
  cudaGetSymbolAddress((void**)&p_v,    g_v);
  cudaGetSymbolAddress((void**)&p_msg,  g_msg);
  cudaGetSymbolAddress((void**)&p_msg2, g_msg2);
  cudaGetSymbolAddress((void**)&p_phikr,g_phikr);
  cudaGetSymbolAddress((void**)&p_vr,   g_vr);
  cudaGetSymbolAddress((void**)&p_fh, b_feat_hi); cudaGetSymbolAddress((void**)&p_fl, b_feat_lo);
  cudaGetSymbolAddress((void**)&p_rh, b_rep_hi);  cudaGetSymbolAddress((void**)&p_rl, b_rep_lo);
  cudaGetSymbolAddress((void**)&p_mh, b_msg_hi);  cudaGetSymbolAddress((void**)&p_ml, b_msg_lo);
  cudaGetSymbolAddress((void**)&p_ch, b_hcat_hi); cudaGetSymbolAddress((void**)&p_cl, b_hcat_lo);
  cudaGetSymbolAddress((void**)&p_hh, b_hid_hi);  cudaGetSymbolAddress((void**)&p_hl, b_hid_lo);
  cudaGetSymbolAddress((void**)&p_wh, b_w_hi);    cudaGetSymbolAddress((void**)&p_wl, b_w_lo);

  const int Mall = NIMG*LTOK;   // 36864
  const int Mrep = NIMG*NWIN;   // 576 (buffers padded to 640)

  for (int layer = 0; layer < 2; layer++){
    const float* F0 = layer ? out : feat0;
    const float* F1 = layer ? out + (size_t)2*LTOK*D : feat1;
    int self = (layer == 0);
    int npairs = self ? NIMG : 2;

    k_convw<<<640, 256>>>(qW + (size_t)layer*D*D, kW + (size_t)layer*D*D,
                          vW + (size_t)layer*D*D, mW + (size_t)layer*D*D,
                          mlpW1 + (size_t)layer*2*D*2*D, mlpW2 + (size_t)layer*D*2*D);
    if (layer == 0) k_convfeat<<<4096, 256>>>(feat0, feat1);

    k_rep<<<NIMG*NWIN, 256>>>(F0, F1, conv_w);
    {
      int total = npairs*(NWIN/2)*(NWIN/2);
      k_cossim<<<(total + 255)/256, 256>>>(npairs, self);
    }
    k_topk<<<(NIMG*NWIN*32 + 255)/256, 256>>>(self);

    // fused rep k/v projection (N=512, rows padded to 640)
    bgemm<0,4><<<dim3(4, NREPAD/BM), 256, SMEM_DYN>>>(p_rh, p_rl, p_wh + WOK, p_wl + WOK,
                                            p_phikr, p_vr, nullptr, nullptr, nullptr,
                                            Mrep, 512, D);
    k_reptot<<<NIMG*NH, 256>>>();

    // fused q/k/v projection over ALL images (M=36864, N=768)
    bgemm<0,3><<<dim3(6, Mall/BM), 256, SMEM_DYN>>>(p_fh, p_fl, p_wh + WOQ, p_wl + WOQ,
                                          p_phiq, p_phik, p_v, nullptr, nullptr,
                                          Mall, 3*D, D);

    k_winagg<<<NIMG*NWIN*NH, 256>>>();
    k_attn<<<NIMG*NWIN, 256>>>(layer);

    bgemm<0,0><<<dim3(2, Mall/BM), 256, SMEM_DYN>>>(p_mh, p_ml, p_wh + WOM, p_wl + WOM,
                                          p_msg2, nullptr, nullptr, nullptr, nullptr,
                                          Mall, D, D);
    k_ln_hcat<<<Mall, 256>>>(p_msg2, n1g + layer*D, n1b + layer*D);

    bgemm<2,1><<<dim3(4, Mall/BM), 256, SMEM_DYN>>>(p_ch, p_cl, p_wh + WO1, p_wl + WO1,
                                          nullptr, nullptr, nullptr, p_hh, p_hl,
                                          Mall, 2*D, 2*D); // relu -> hid planes
    bgemm<0,0><<<dim3(2, Mall/BM), 256, SMEM_DYN>>>(p_hh, p_hl, p_wh + WO2, p_wl + WO2,
                                          p_msg, nullptr, nullptr, nullptr, nullptr,
                                          Mall, D, 2*D);

    k_final<<<Mall, 256>>>(F0, F1, out, n2g + layer*D, n2b + layer*D);
  }
}

// round 14
// speedup vs baseline: 2.2281x; 1.0143x over previous
#include <cuda_runtime.h>
#include <cuda_bf16.h>
#include <math.h>
#include <stdint.h>

// ---------------- problem constants ----------------
#define NIMG 4        // (map m, batch b) -> img = m*2+b
#define LTOK 9216     // 96*96
#define D 256
#define NH 8
#define HD 32
#define WGRID 12      // 96/8
#define NWIN 144
#define WTOK 64
#define KSEL 8
#define CN 16
#define NREPAD 640    // rep rows padded to tile multiple (576 -> 640)

// weight-plane buffer offsets (elements)
#define WOQ 0
#define WOK 65536
#define WOV 131072
#define WOM 196608
#define WO1 262144
#define WO2 524288
#define WTOT 655360

// ---------------- scratch (device globals; no allocation allowed) ----------
__device__ float g_phi_q[NIMG*LTOK*D];
__device__ float g_phi_k[NIMG*LTOK*D];
__device__ float g_v    [NIMG*LTOK*D];
__device__ float g_msg  [NIMG*LTOK*D];   // MLP2 output (pre-LN2)
__device__ float g_msg2 [NIMG*LTOK*D];   // mW output (pre-LN1)
__device__ float g_repn [NIMG*NWIN*D];
__device__ float g_phikr[NIMG*NWIN*D];
__device__ float g_vr   [NIMG*NWIN*D];
__device__ float g_sim  [NIMG*NWIN*NWIN];
__device__ int   g_sel  [NIMG*NWIN*KSEL];
__device__ float g_KVwin[NIMG*NWIN*NH*HD*HD];
__device__ float g_kswin[NIMG*NWIN*D];
__device__ float g_KVtot[NIMG*NH*HD*HD];
__device__ float g_kstot[NIMG*D];

// bf16 hi/lo operand planes (aligned for 16B loads). Zero-initialized,
// pad rows (rep 576..639) stay zero forever.
__device__ __align__(128) __nv_bfloat16 b_feat_hi[NIMG*LTOK*D];
__device__ __align__(128) __nv_bfloat16 b_feat_lo[NIMG*LTOK*D];
__device__ __align__(128) __nv_bfloat16 b_rep_hi [NREPAD*D];
__device__ __align__(128) __nv_bfloat16 b_rep_lo [NREPAD*D];
__device__ __align__(128) __nv_bfloat16 b_msg_hi [NIMG*LTOK*D];
__device__ __align__(128) __nv_bfloat16 b_msg_lo [NIMG*LTOK*D];
__device__ __align__(128) __nv_bfloat16 b_hcat_hi[NIMG*LTOK*2*D];
__device__ __align__(128) __nv_bfloat16 b_hcat_lo[NIMG*LTOK*2*D];
__device__ __align__(128) __nv_bfloat16 b_hid_hi [NIMG*LTOK*2*D];
__device__ __align__(128) __nv_bfloat16 b_hid_lo [NIMG*LTOK*2*D];
__device__ __align__(128) __nv_bfloat16 b_w_hi   [WTOT];
__device__ __align__(128) __nv_bfloat16 b_w_lo   [WTOT];

// ---------------- helpers ----------------
__device__ __forceinline__ float phi(float x){ return x > 0.f ? x + 1.f : expf(x); }

__device__ __forceinline__ void split_bf16(float x, __nv_bfloat16& h, __nv_bfloat16& l){
  h = __float2bfloat16(x);
  l = __float2bfloat16(x - __bfloat162float(h));
}

__device__ __forceinline__ float blockReduceSum(float val, float* sbuf){
  __syncthreads();
  int lane = threadIdx.x & 31, wid = threadIdx.x >> 5;
  #pragma unroll
  for (int o = 16; o; o >>= 1) val += __shfl_down_sync(0xffffffffu, val, o);
  if (lane == 0) sbuf[wid] = val;
  __syncthreads();
  float r = (threadIdx.x < (blockDim.x >> 5)) ? sbuf[threadIdx.x] : 0.f;
  if (wid == 0){
    #pragma unroll
    for (int o = 16; o; o >>= 1) r += __shfl_down_sync(0xffffffffu, r, o);
    if (lane == 0) sbuf[0] = r;
  }
  __syncthreads();
  return sbuf[0];
}

__device__ __forceinline__ int spatial_l(int win, int t){
  int wy = win / WGRID, wx = win % WGRID;
  return (wy*8 + (t >> 3))*96 + wx*8 + (t & 7);
}

// ---------------- converters ----------------
__global__ void k_convw(const float* __restrict__ q, const float* __restrict__ k,
                        const float* __restrict__ v, const float* __restrict__ m,
                        const float* __restrict__ w1, const float* __restrict__ w2){
  for (int i = blockIdx.x*blockDim.x + threadIdx.x; i < WTOT; i += gridDim.x*blockDim.x){
    float x;
    if      (i < WOK) x = q[i];
    else if (i < WOV) x = k[i - WOK];
    else if (i < WOM) x = v[i - WOV];
    else if (i < WO1) x = m[i - WOM];
    else if (i < WO2) x = w1[i - WO1];
    else              x = w2[i - WO2];
    split_bf16(x, b_w_hi[i], b_w_lo[i]);
  }
}

// feat planes + hcat feat-half (cols 0..255)
__global__ void k_convfeat(const float* __restrict__ f0, const float* __restrict__ f1){
  const int half = 2*LTOK*D;
  for (int i = blockIdx.x*blockDim.x + threadIdx.x; i < NIMG*LTOK*D;
       i += gridDim.x*blockDim.x){
    float x = (i < half) ? f0[i] : f1[i - half];
    __nv_bfloat16 h, l;
    split_bf16(x, h, l);
    b_feat_hi[i] = h; b_feat_lo[i] = l;
    size_t row = (size_t)(i >> 8); int c = i & 255;
    size_t ho = (row << 9) + c;
    b_hcat_hi[ho] = h; b_hcat_lo[ho] = l;
  }
}

// ---------------- 1) per-window rep ----------------
__global__ void __launch_bounds__(256) k_rep(const float* __restrict__ f0,
                                             const float* __restrict__ f1,
                                             const float* __restrict__ conv_w){
  int img = blockIdx.x / NWIN, win = blockIdx.x % NWIN;
  int m = img >> 1, b = img & 1;
  const float* F = (m ? f1 : f0) + (size_t)b*LTOK*D;
  __shared__ float cw[CN*D];
  __shared__ float simall[WTOK*CN];
  __shared__ float avg[CN];
  __shared__ float red[32];
  int tid = threadIdx.x;
  for (int i = tid; i < CN*D; i += 256) cw[i] = conv_w[i];
  __syncthreads();
  int warp = tid >> 5, lane = tid & 31;
  for (int p = 0; p < 8; p++){
    int t = warp + p*8;
    int l = spatial_l(win, t);
    const float* fr = F + (size_t)l*D;
    float fv[8];
    #pragma unroll
    for (int i = 0; i < 8; i++) fv[i] = fr[lane + 32*i];
    for (int c = 0; c < CN; c++){
      float s = 0.f;
      #pragma unroll
      for (int i = 0; i < 8; i++) s += fv[i]*cw[c*D + lane + 32*i];
      #pragma unroll
      for (int o = 16; o; o >>= 1) s += __shfl_down_sync(0xffffffffu, s, o);
      if (lane == 0) simall[t*CN + c] = s;
    }
  }
  __syncthreads();
  if (tid < WTOK){
    float mx = -1e30f;
    for (int c = 0; c < CN; c++) mx = fmaxf(mx, simall[tid*CN + c]);
    float s = 0.f, e[CN];
    for (int c = 0; c < CN; c++){ e[c] = expf(simall[tid*CN + c] - mx); s += e[c]; }
    float inv = 1.f/s;
    for (int c = 0; c < CN; c++) simall[tid*CN + c] = e[c]*inv;
  }
  __syncthreads();
  if (tid < CN){
    float s = 0.f;
    for (int t = 0; t < WTOK; t++) s += simall[t*CN + tid];
    avg[tid] = s * (1.f/WTOK);
  }
  __syncthreads();
  float r = 0.f;
  for (int c = 0; c < CN; c++) r += avg[c]*cw[c*D + tid];
  size_t oi = (size_t)(img*NWIN + win)*D + tid;
  split_bf16(r, b_rep_hi[oi], b_rep_lo[oi]);
  float n2 = blockReduceSum(r*r, red);
  float nrm = fmaxf(sqrtf(n2), 1e-8f);
  g_repn[oi] = r / nrm;
}

// ---------------- 2) cosine sim (2x2 register blocking) ----------------
__global__ void k_cossim(int npairs, int self){
  const int H2 = NWIN/2;                 // 72
  long total = (long)npairs*H2*H2;
  for (long idx = (long)blockIdx.x*blockDim.x + threadIdx.x; idx < total;
       idx += (long)gridDim.x*blockDim.x){
    int p = (int)(idx/(H2*H2)); int rem = (int)(idx%(H2*H2));
    int q = (rem/H2)*2, s = (rem%H2)*2;
    const float* a0 = &g_repn[((size_t)p*NWIN + q)*D];
    const float* a1 = a0 + D;
    const float* b0 = self ? &g_repn[((size_t)p*NWIN + s)*D]
                           : &g_repn[(((size_t)(2+p))*NWIN + s)*D];
    const float* b1 = b0 + D;
    float c00 = 0.f, c01 = 0.f, c10 = 0.f, c11 = 0.f;
    #pragma unroll 4
    for (int k = 0; k < D; k += 4){
      float4 av0 = *(const float4*)&a0[k];
      float4 av1 = *(const float4*)&a1[k];
      float4 bv0 = *(const float4*)&b0[k];
      float4 bv1 = *(const float4*)&b1[k];
      c00 += av0.x*bv0.x + av0.y*bv0.y + av0.z*bv0.z + av0.w*bv0.w;
      c01 += av0.x*bv1.x + av0.y*bv1.y + av0.z*bv1.z + av0.w*bv1.w;
      c10 += av1.x*bv0.x + av1.y*bv0.y + av1.z*bv0.z + av1.w*bv0.w;
      c11 += av1.x*bv1.x + av1.y*bv1.y + av1.z*bv1.z + av1.w*bv1.w;
    }
    size_t ob = (size_t)p*NWIN*NWIN + (size_t)q*NWIN + s;
    g_sim[ob]            = c00;
    g_sim[ob + 1]        = c01;
    g_sim[ob + NWIN]     = c10;
    g_sim[ob + NWIN + 1] = c11;
  }
}

// ---------------- 3) top-K (warp per query; stable ties) --------------------
__global__ void k_topk(int self){
  int gw = (blockIdx.x*blockDim.x + threadIdx.x) >> 5;
  int lane = threadIdx.x & 31;
  if (gw >= NIMG*NWIN) return;
  int img = gw/NWIN, q = gw%NWIN;
  size_t base; int sq, ss;
  if (self){ base = (size_t)img*NWIN*NWIN; sq = NWIN; ss = 1; }
  else {
    int b = img & 1, m = img >> 1;
    base = (size_t)b*NWIN*NWIN;
    if (m == 0){ sq = NWIN; ss = 1; } else { sq = 1; ss = NWIN; }
  }
  const float* S = g_sim + base + (size_t)q*sq;
  float v0, v1, v2, v3, v4;
  v0 = S[(size_t)(lane      )*ss];
  v1 = S[(size_t)(lane +  32)*ss];
  v2 = S[(size_t)(lane +  64)*ss];
  v3 = S[(size_t)(lane +  96)*ss];
  v4 = (lane + 128 < NWIN) ? S[(size_t)(lane + 128)*ss] : -1e30f;
  for (int k = 0; k < KSEL; k++){
    float bv = v0; int bi = lane;
    if (v1 > bv){ bv = v1; bi = lane + 32; }
    if (v2 > bv){ bv = v2; bi = lane + 64; }
    if (v3 > bv){ bv = v3; bi = lane + 96; }
    if (v4 > bv){ bv = v4; bi = lane + 128; }
    #pragma unroll
    for (int o = 16; o; o >>= 1){
      float ov = __shfl_xor_sync(0xffffffffu, bv, o);
      int   oi = __shfl_xor_sync(0xffffffffu, bi, o);
      if (ov > bv || (ov == bv && oi < bi)){ bv = ov; bi = oi; }
    }
    if (lane == 0) g_sel[gw*KSEL + k] = bi;
    int wl = bi & 31, wj = bi >> 5;
    if (lane == wl){
      if      (wj == 0) v0 = -1e30f;
      else if (wj == 1) v1 = -1e30f;
      else if (wj == 2) v2 = -1e30f;
      else if (wj == 3) v3 = -1e30f;
      else              v4 = -1e30f;
    }
  }
}

// ---------------- 5) totals over all 144 rep rows ----------------
__global__ void __launch_bounds__(256) k_reptot(){
  int img = blockIdx.x >> 3, h = blockIdx.x & 7;
  __shared__ float pk[NWIN*HD];
  __shared__ float vv[NWIN*HD];
  int tid = threadIdx.x;
  for (int i = tid; i < NWIN*HD; i += 256){
    int r = i/HD, d = i%HD;
    size_t off = ((size_t)img*NWIN + r)*D + h*HD + d;
    pk[i] = g_phikr[off]; vv[i] = g_vr[off];
  }
  __syncthreads();
  for (int o = tid; o < HD*HD; o += 256){
    int d = o/HD, j = o%HD;
    float s = 0.f;
    for (int r = 0; r < NWIN; r++) s += pk[r*HD + d]*vv[r*HD + j];
    g_KVtot[((size_t)img*NH + h)*HD*HD + o] = s;
  }
  if (tid < HD){
    float s = 0.f;
    for (int r = 0; r < NWIN; r++) s += pk[r*HD + tid];
    g_kstot[(size_t)img*D + h*HD + tid] = s;
  }
}

// ====== 3xBF16 GEMM, ldmatrix + cp.async 4-stage: C = act(A @ B^T) ==========
template<int ACT>
__device__ __forceinline__ float actf(float x){
  if (ACT == 1) return x > 0.f ? x + 1.f : expf(x); // phi = elu + 1
  if (ACT == 2) return fmaxf(x, 0.f);               // relu
  return x;
}

__device__ __forceinline__ void mma_bf16(float* d, const uint32_t* a, const uint32_t* b){
  asm volatile(
    "mma.sync.aligned.m16n8k16.row.col.f32.bf16.bf16.f32 "
    "{%0,%1,%2,%3}, {%4,%5,%6,%7}, {%8,%9}, {%0,%1,%2,%3};"
    : "+f"(d[0]), "+f"(d[1]), "+f"(d[2]), "+f"(d[3])
    : "r"(a[0]), "r"(a[1]), "r"(a[2]), "r"(a[3]), "r"(b[0]), "r"(b[1]));
}

__device__ __forceinline__ void ldsm4(uint32_t* r, uint32_t a){
  asm volatile("ldmatrix.sync.aligned.m8n8.x4.shared.b16 {%0,%1,%2,%3}, [%4];"
    : "=r"(r[0]), "=r"(r[1]), "=r"(r[2]), "=r"(r[3]) : "r"(a));
}

__device__ __forceinline__ void cp16(uint32_t s, const void* g){
  asm volatile("cp.async.cg.shared.global [%0], [%1], 16;\n" :: "r"(s), "l"(g));
}
__device__ __forceinline__ void cp_commit(){ asm volatile("cp.async.commit_group;\n"); }
template<int NG> __device__ __forceinline__ void cp_wait(){
  asm volatile("cp.async.wait_group %0;\n" :: "n"(NG));
}

#define BM 128
#define BN 128
#define BK 16
#define SPH 24           // smem row stride in halves (48B; 3 x 16B units -> LDSM conflict-free)
#define PLANE_B 6144     // bytes per plane (128*48)
#define STAGE_B 24576    // bytes per stage (4 planes: Ah, Al, Bh, Bl)
#define NSTAGE 4
#define SMEM_DYN (NSTAGE*STAGE_B)   // 98304 bytes (dynamic, opt-in)

// one cp.async stage: 256 threads x 1 chunk per plane-operand
__device__ __forceinline__ void load_stage(uint32_t sb,
    const __nv_bfloat16* __restrict__ Ah, const __nv_bfloat16* __restrict__ Al,
    const __nv_bfloat16* __restrict__ Bh, const __nv_bfloat16* __restrict__ Bl,
    size_t abase, size_t bbase, int K, int k0, int tid)
{
  int row = tid >> 1, kw = tid & 1;
  uint32_t so = (uint32_t)(row*48 + kw*16);
  size_t go = (size_t)row*K + k0 + kw*8;
  cp16(sb + 0*PLANE_B + so, Ah + abase + go);
  cp16(sb + 1*PLANE_B + so, Al + abase + go);
  cp16(sb + 2*PLANE_B + so, Bh + bbase + go);
  cp16(sb + 3*PLANE_B + so, Bl + bbase + go);
  cp_commit();
}

// OUTMODE 0: fp32 -> C0 (ACT), M-guarded.
// OUTMODE 1: hi/lo planes -> Ch/Cl (ACT), M multiple of 128.
// OUTMODE 3: fused qkv: N=768; region by bn: q(phi)/k(phi)/v. stride 256.
// OUTMODE 4: fused rep kv: N=512; region 0 -> C0 with phi, 1 -> C1. stride 256, M-guarded.
template<int ACT, int OUTMODE>
__global__ void __launch_bounds__(256, 2)
bgemm(const __nv_bfloat16* __restrict__ Ah, const __nv_bfloat16* __restrict__ Al,
      const __nv_bfloat16* __restrict__ Bh, const __nv_bfloat16* __restrict__ Bl,
      float* __restrict__ C0, float* __restrict__ C1, float* __restrict__ C2,
      __nv_bfloat16* __restrict__ Ch, __nv_bfloat16* __restrict__ Cl,
      int M, int N, int K)
{
  extern __shared__ __align__(16) char smraw[]; // NSTAGE * 24576 dynamic
  uint32_t sb0 = (uint32_t)__cvta_generic_to_shared(smraw);
  const int tid = threadIdx.x;
  const int bm = blockIdx.y*BM, bn = blockIdx.x*BN;
  const int warp = tid >> 5, lane = tid & 31;
  const int wm = (warp >> 1)*32, wn = (warp & 1)*64;
  const int grp = lane >> 2, tig = lane & 3;
  const size_t abase = (size_t)bm*K, bbase = (size_t)bn*K;

  float acc[16][4];
  #pragma unroll
  for (int f = 0; f < 16; f++)
    #pragma unroll
    for (int r = 0; r < 4; r++) acc[f][r] = 0.f;

  const int nk = K/BK;   // >= 16 for all our shapes
  load_stage(sb0,             Ah, Al, Bh, Bl, abase, bbase, K, 0,    tid);
  load_stage(sb0 +   STAGE_B, Ah, Al, Bh, Bl, abase, bbase, K, BK,   tid);
  load_stage(sb0 + 2*STAGE_B, Ah, Al, Bh, Bl, abase, bbase, K, 2*BK, tid);

  // ldmatrix lane addresses (bytes, relative to plane base)
  const uint32_t a_lane = (uint32_t)(((wm + (lane & 15))*SPH + (lane >> 4)*8)*2);
  const uint32_t b_lane = (uint32_t)(((wn + (lane & 7) + (lane >> 4)*8)*SPH
                                      + ((lane >> 3) & 1)*8)*2);

  int stg = 0;                 // stage index of tile kt
  for (int kt = 0; kt < nk; kt++){
    int rem = nk - 1 - kt;     // loads pending beyond tile kt (capped at 3)
    if      (rem >= 3) cp_wait<3>();
    else if (rem == 2) cp_wait<2>();
    else if (rem == 1) cp_wait<1>();
    else               cp_wait<0>();
    __syncthreads();
    uint32_t sb = sb0 + (uint32_t)(stg*STAGE_B);
    // issue lookahead load (buffer (kt+3)%4 == (kt-1)%4, consumed last iter)
    if (kt + 3 < nk){
      int ns = stg + 3; if (ns >= NSTAGE) ns -= NSTAGE;
      load_stage(sb0 + (uint32_t)(ns*STAGE_B), Ah, Al, Bh, Bl,
                 abase, bbase, K, (kt + 3)*BK, tid);
    }

    uint32_t ah[2][4], al[2][4];
    ldsm4(ah[0], sb + a_lane);
    ldsm4(ah[1], sb + a_lane + 768);           // +16 rows * 48B
    ldsm4(al[0], sb + PLANE_B + a_lane);
    ldsm4(al[1], sb + PLANE_B + a_lane + 768);
    #pragma unroll
    for (int jp = 0; jp < 4; jp++){
      uint32_t bh[4], bl[4];
      ldsm4(bh, sb + 2*PLANE_B + b_lane + jp*768);
      ldsm4(bl, sb + 3*PLANE_B + b_lane + jp*768);
      #pragma unroll
      for (int i = 0; i < 2; i++)
        #pragma unroll
        for (int jj = 0; jj < 2; jj++){
          float* dd = acc[i*8 + jp*2 + jj];
          mma_bf16(dd, ah[i], bl + jj*2);
          mma_bf16(dd, al[i], bh + jj*2);
          mma_bf16(dd, ah[i], bh + jj*2);
        }
    }
    if (++stg == NSTAGE) stg = 0;
  }

  #pragma unroll
  for (int i = 0; i < 2; i++){
    int r0 = bm + wm + i*16 + grp;
    #pragma unroll
    for (int j = 0; j < 8; j++){
      const float* dd = acc[i*8 + j];
      int cc = wn + j*8 + tig*2;
      if (OUTMODE == 0){
        int c = bn + cc;
        if (r0 < M){
          C0[(size_t)r0*N + c    ] = actf<ACT>(dd[0]);
          C0[(size_t)r0*N + c + 1] = actf<ACT>(dd[1]);
        }
        if (r0 + 8 < M){
          C0[(size_t)(r0+8)*N + c    ] = actf<ACT>(dd[2]);
          C0[(size_t)(r0+8)*N + c + 1] = actf<ACT>(dd[3]);
        }
      } else if (OUTMODE == 1){
        int c = bn + cc;
        #pragma unroll
        for (int rr = 0; rr < 2; rr++){
          float v0 = actf<ACT>(dd[rr*2]), v1 = actf<ACT>(dd[rr*2+1]);
          __nv_bfloat162 h, l;
          h.x = __float2bfloat16(v0); h.y = __float2bfloat16(v1);
          l.x = __float2bfloat16(v0 - __bfloat162float(h.x));
          l.y = __float2bfloat16(v1 - __bfloat162float(h.y));
          size_t o = (size_t)(r0 + rr*8)*N + c;
          *(__nv_bfloat162*)&Ch[o] = h;
          *(__nv_bfloat162*)&Cl[o] = l;
        }
      } else if (OUTMODE == 3){
        int reg = bn >> 8;                   // 0:q 1:k 2:v
        float* T = (reg == 0) ? C0 : ((reg == 1) ? C1 : C2);
        int c = (bn & 255) + cc;
        float v0 = (reg < 2) ? actf<1>(dd[0]) : dd[0];
        float v1 = (reg < 2) ? actf<1>(dd[1]) : dd[1];
        float v2 = (reg < 2) ? actf<1>(dd[2]) : dd[2];
        float v3 = (reg < 2) ? actf<1>(dd[3]) : dd[3];
        T[(size_t)r0*256 + c    ] = v0;
        T[(size_t)r0*256 + c + 1] = v1;
        T[(size_t)(r0+8)*256 + c    ] = v2;
        T[(size_t)(r0+8)*256 + c + 1] = v3;
      } else { // OUTMODE 4: rep kv
        int reg = bn >> 8;                   // 0: phi(k) -> C0, 1: v -> C1
        float* T = reg ? C1 : C0;
        int c = (bn & 255) + cc;
        float v0 = reg ? dd[0] : actf<1>(dd[0]);
        float v1 = reg ? dd[1] : actf<1>(dd[1]);
        float v2 = reg ? dd[2] : actf<1>(dd[2]);
        float v3 = reg ? dd[3] : actf<1>(dd[3]);
        if (r0 < M){
          T[(size_t)r0*256 + c    ] = v0;
          T[(size_t)r0*256 + c + 1] = v1;
        }
        if (r0 + 8 < M){
          T[(size_t)(r0+8)*256 + c    ] = v2;
          T[(size_t)(r0+8)*256 + c + 1] = v3;
        }
      }
    }
  }
}

// ---------------- 6) per-window KV/ksum aggregates (vectorized) -------------
__global__ void __launch_bounds__(256) k_winagg(){
  int bid = blockIdx.x;
  int h = bid & 7; int wv = bid >> 3;
  int win = wv % NWIN, img = wv / NWIN;
  __shared__ float pk[WTOK*HD];
  __shared__ float vv[WTOK*HD];
  int tid = threadIdx.x;
  #pragma unroll
  for (int i = tid; i < WTOK*HD/4; i += 256){
    int t = i >> 3, d4 = (i & 7)*4;
    int l = spatial_l(win, t);
    size_t off = ((size_t)img*LTOK + l)*D + h*HD + d4;
    *(float4*)&pk[t*HD + d4] = *(const float4*)&g_phi_k[off];
    *(float4*)&vv[t*HD + d4] = *(const float4*)&g_v[off];
  }
  __syncthreads();
  int d = tid >> 3, j0 = (tid & 7)*4;
  float a0 = 0.f, a1 = 0.f, a2 = 0.f, a3 = 0.f;
  #pragma unroll 8
  for (int t = 0; t < WTOK; t++){
    float p = pk[t*HD + d];
    float4 v4 = *(const float4*)&vv[t*HD + j0];
    a0 += p*v4.x; a1 += p*v4.y; a2 += p*v4.z; a3 += p*v4.w;
  }
  size_t ob = (((size_t)(img*NWIN + win))*NH + h)*HD*HD + (size_t)d*HD + j0;
  *(float4*)&g_KVwin[ob] = make_float4(a0, a1, a2, a3);
  if (tid < HD){
    float s = 0.f;
    for (int t = 0; t < WTOK; t++) s += pk[t*HD + tid];
    g_kswin[((size_t)img*NWIN + win)*D + h*HD + tid] = s;
  }
}

// ---------------- 7) attention: register-resident KV build + apply ----------
__global__ void __launch_bounds__(256) k_attn(int layer){
  int img = blockIdx.x / NWIN, q = blockIdx.x % NWIN;
  int src = (layer == 0) ? img : (img ^ 2); // cross: flip map, keep batch
  __shared__ float bufpk[KSEL][D]; // 8KB
  __shared__ float bufv [KSEL][D]; // 8KB
  __shared__ int   wsel[KSEL];
  int tid = threadIdx.x;
  if (tid < KSEL) wsel[tid] = g_sel[(img*NWIN + q)*KSEL + tid];
  __syncthreads();
  #pragma unroll
  for (int k = 0; k < KSEL; k++){
    int w = wsel[k];
    bufpk[k][tid] = g_phikr[((size_t)src*NWIN + w)*D + tid];
    bufv [k][tid] = g_vr   [((size_t)src*NWIN + w)*D + tid];
  }
  __syncthreads();

  int h = tid >> 5, lane = tid & 31;
  // init KV column + ksum from totals (order matches reference chain)
  float kvreg[32];
  const float* KVT = g_KVtot + (size_t)src*NH*HD*HD + h*HD*HD;
  #pragma unroll
  for (int d = 0; d < 32; d++) kvreg[d] = KVT[d*HD + lane];
  float ksv = g_kstot[(size_t)src*D + h*HD + lane];
  // accumulate the 8 selected windows (same per-element order as before:
  // kv += KVwin - pk*v, sequentially per k)
  for (int k = 0; k < KSEL; k++){
    int w = wsel[k];
    const float* KVW = g_KVwin + ((size_t)(src*NWIN + w))*NH*HD*HD + h*HD*HD;
    float vj = bufv[k][h*HD + lane];
    #pragma unroll
    for (int d = 0; d < 32; d++)
      kvreg[d] += KVW[d*HD + lane] - bufpk[k][h*HD + d]*vj;
    ksv += g_kswin[((size_t)src*NWIN + w)*D + h*HD + lane] - bufpk[k][h*HD + lane];
  }

  const float* pqb = g_phi_q + (size_t)img*LTOK*D + h*HD + lane;
  for (int t = 0; t < WTOK; t++){
    int l = spatial_l(q, t);
    float pqv = __ldg(pqb + (size_t)l*D);
    float n0 = 0.f, n1 = 0.f, n2 = 0.f, n3 = 0.f;
    #pragma unroll
    for (int d = 0; d < 32; d += 4){
      float p0 = __shfl_sync(0xffffffffu, pqv, d    );
      float p1 = __shfl_sync(0xffffffffu, pqv, d + 1);
      float p2 = __shfl_sync(0xffffffffu, pqv, d + 2);
      float p3 = __shfl_sync(0xffffffffu, pqv, d + 3);
      n0 += p0*kvreg[d];   n1 += p1*kvreg[d+1];
      n2 += p2*kvreg[d+2]; n3 += p3*kvreg[d+3];
    }
    float num = (n0 + n1) + (n2 + n3);
    float dv = pqv*ksv;
    #pragma unroll
    for (int o = 16; o; o >>= 1) dv += __shfl_xor_sync(0xffffffffu, dv, o);
    float r = num / (dv + 1e-6f);
    size_t oi = ((size_t)img*LTOK + l)*D + h*HD + lane;
    split_bf16(r, b_msg_hi[oi], b_msg_lo[oi]);
  }
}

// ---------------- 8) LN1 fused with hcat msg-half write ----------------
__global__ void __launch_bounds__(256) k_ln_hcat(const float* __restrict__ X,
                                                 const float* __restrict__ g,
                                                 const float* __restrict__ b){
  size_t row = blockIdx.x;
  int tid = threadIdx.x;
  __shared__ float red[32];
  float x = X[row*D + tid];
  float mu = blockReduceSum(x, red) * (1.f/D);
  float d = x - mu;
  float var = blockReduceSum(d*d, red) * (1.f/D);
  float y = d*rsqrtf(var + 1e-5f)*g[tid] + b[tid];
  size_t ho = (row << 9) + 256 + tid;
  split_bf16(y, b_hcat_hi[ho], b_hcat_lo[ho]);
}

// ---------------- 10) final: out = x + LN(m); feat + hcat planes ------------
__global__ void __launch_bounds__(256) k_final(const float* __restrict__ f0,
                                               const float* __restrict__ f1,
                                               float* __restrict__ out,
                                               const float* __restrict__ g,
                                               const float* __restrict__ b){
  size_t row = blockIdx.x;
  int tid = threadIdx.x;
  int img = (int)(row / LTOK); size_t l = row % LTOK;
  int m = img >> 1, bb = img & 1;
  __shared__ float red[32];
  float x = g_msg[row*D + tid];
  float mu = blockReduceSum(x, red) * (1.f/D);
  float d = x - mu;
  float var = blockReduceSum(d*d, red) * (1.f/D);
  float msg3 = d*rsqrtf(var + 1e-5f)*g[tid] + b[tid];
  const float* F = (m ? f1 : f0) + ((size_t)bb*LTOK + l)*D;
  size_t oi = row*D + tid;
  float r = F[tid] + msg3;
  out[oi] = r;
  __nv_bfloat16 h, lo;
  split_bf16(r, h, lo);
  b_feat_hi[oi] = h; b_feat_lo[oi] = lo;
  size_t ho = (row << 9) + tid;
  b_hcat_hi[ho] = h; b_hcat_lo[ho] = lo;
}

// ---------------- host ----------------
extern "C" void kernel_launch(void* const* d_in, const int* in_sizes, int n_in,
                              void* d_out, int out_size){
  (void)in_sizes; (void)n_in; (void)out_size;
  const float* feat0 = (const float*)d_in[0];
  const float* feat1 = (const float*)d_in[1];
  const float* qW    = (const float*)d_in[8];
  const float* kW    = (const float*)d_in[9];
  const float* vW    = (const float*)d_in[10];
  const float* mW    = (const float*)d_in[11];
  const float* mlpW1 = (const float*)d_in[12];
  const float* mlpW2 = (const float*)d_in[13];
  const float* n1g   = (const float*)d_in[14];
  const float* n1b   = (const float*)d_in[15];
  const float* n2g   = (const float*)d_in[16];
  const float* n2b   = (const float*)d_in[17];
  const float* conv_w= (const float*)d_in[18];
  float* out = (float*)d_out;

  // opt-in dynamic smem (idempotent; host-side attr set, not a stream op)
  cudaFuncSetAttribute((const void*)bgemm<0,0>, cudaFuncAttributeMaxDynamicSharedMemorySize, SMEM_DYN);
  cudaFuncSetAttribute((const void*)bgemm<0,3>, cudaFuncAttributeMaxDynamicSharedMemorySize, SMEM_DYN);
  cudaFuncSetAttribute((const void*)bgemm<0,4>, cudaFuncAttributeMaxDynamicSharedMemorySize, SMEM_DYN);
  cudaFuncSetAttribute((const void*)bgemm<2,1>, cudaFuncAttributeMaxDynamicSharedMemorySize, SMEM_DYN);

  float *p_phiq, *p_phik, *p_v, *p_msg, *p_msg2, *p_phikr, *p_vr;
  __nv_bfloat16 *p_fh, *p_fl, *p_rh, *p_rl, *p_mh, *p_ml, *p_ch, *p_cl,
                *p_hh, *p_hl, *p_wh, *p_wl;
  cudaGetSymbolAddress((void**)&p_phiq, g_phi_q);
  cudaGetSymbolAddress((void**)&p_phik, g_phi_k);
  cudaGetSymbolAddress((void**)&p_v,    g_v);
  cudaGetSymbolAddress((void**)&p_msg,  g_msg);
  cudaGetSymbolAddress((void**)&p_msg2, g_msg2);
  cudaGetSymbolAddress((void**)&p_phikr,g_phikr);
  cudaGetSymbolAddress((void**)&p_vr,   g_vr);
  cudaGetSymbolAddress((void**)&p_fh, b_feat_hi); cudaGetSymbolAddress((void**)&p_fl, b_feat_lo);
  cudaGetSymbolAddress((void**)&p_rh, b_rep_hi);  cudaGetSymbolAddress((void**)&p_rl, b_rep_lo);
  cudaGetSymbolAddress((void**)&p_mh, b_msg_hi);  cudaGetSymbolAddress((void**)&p_ml, b_msg_lo);
  cudaGetSymbolAddress((void**)&p_ch, b_hcat_hi); cudaGetSymbolAddress((void**)&p_cl, b_hcat_lo);
  cudaGetSymbolAddress((void**)&p_hh, b_hid_hi);  cudaGetSymbolAddress((void**)&p_hl, b_hid_lo);
  cudaGetSymbolAddress((void**)&p_wh, b_w_hi);    cudaGetSymbolAddress((void**)&p_wl, b_w_lo);

  const int Mall = NIMG*LTOK;   // 36864
  const int Mrep = NIMG*NWIN;   // 576 (buffers padded to 640)

  for (int layer = 0; layer < 2; layer++){
    const float* F0 = layer ? out : feat0;
    const float* F1 = layer ? out + (size_t)2*LTOK*D : feat1;
    int self = (layer == 0);
    int npairs = self ? NIMG : 2;

    k_convw<<<640, 256>>>(qW + (size_t)layer*D*D, kW + (size_t)layer*D*D,
                          vW + (size_t)layer*D*D, mW + (size_t)layer*D*D,
                          mlpW1 + (size_t)layer*2*D*2*D, mlpW2 + (size_t)layer*D*2*D);
    if (layer == 0) k_convfeat<<<4096, 256>>>(feat0, feat1);

    k_rep<<<NIMG*NWIN, 256>>>(F0, F1, conv_w);
    {
      int total = npairs*(NWIN/2)*(NWIN/2);
      k_cossim<<<(total + 255)/256, 256>>>(npairs, self);
    }
    k_topk<<<(NIMG*NWIN*32 + 255)/256, 256>>>(self);

    // fused rep k/v projection (N=512, rows padded to 640)
    bgemm<0,4><<<dim3(4, NREPAD/BM), 256, SMEM_DYN>>>(p_rh, p_rl, p_wh + WOK, p_wl + WOK,
                                            p_phikr, p_vr, nullptr, nullptr, nullptr,
                                            Mrep, 512, D);
    k_reptot<<<NIMG*NH, 256>>>();

    // fused q/k/v projection over ALL images (M=36864, N=768)
    bgemm<0,3><<<dim3(6, Mall/BM), 256, SMEM_DYN>>>(p_fh, p_fl, p_wh + WOQ, p_wl + WOQ,
                                          p_phiq, p_phik, p_v, nullptr, nullptr,
                                          Mall, 3*D, D);

    k_winagg<<<NIMG*NWIN*NH, 256>>>();
    k_attn<<<NIMG*NWIN, 256>>>(layer);

    bgemm<0,0><<<dim3(2, Mall/BM), 256, SMEM_DYN>>>(p_mh, p_ml, p_wh + WOM, p_wl + WOM,
                                          p_msg2, nullptr, nullptr, nullptr, nullptr,
                                          Mall, D, D);
    k_ln_hcat<<<Mall, 256>>>(p_msg2, n1g + layer*D, n1b + layer*D);

    bgemm<2,1><<<dim3(4, Mall/BM), 256, SMEM_DYN>>>(p_ch, p_cl, p_wh + WO1, p_wl + WO1,
                                          nullptr, nullptr, nullptr, p_hh, p_hl,
                                          Mall, 2*D, 2*D); // relu -> hid planes
    bgemm<0,0><<<dim3(2, Mall/BM), 256, SMEM_DYN>>>(p_hh, p_hl, p_wh + WO2, p_wl + WO2,
                                          p_msg, nullptr, nullptr, nullptr, nullptr,
                                          Mall, D, 2*D);

    k_final<<<Mall, 256>>>(F0, F1, out, n2g + layer*D, n2b + layer*D);
  }
}

// round 15
// speedup vs baseline: 2.2302x; 1.0009x over previous
#include <cuda_runtime.h>
#include <cuda_bf16.h>
#include <math.h>
#include <stdint.h>

// ---------------- problem constants ----------------
#define NIMG 4        // (map m, batch b) -> img = m*2+b
#define LTOK 9216     // 96*96
#define D 256
#define NH 8
#define HD 32
#define WGRID 12      // 96/8
#define NWIN 144
#define WTOK 64
#define KSEL 8
#define CN 16
#define NREPAD 640    // rep rows padded to tile multiple (576 -> 640)

// weight-plane buffer offsets (elements, per layer)
#define WOQ 0
#define WOK 65536
#define WOV 131072
#define WOM 196608
#define WO1 262144
#define WO2 524288
#define WTOT 655360

// ---------------- scratch (device globals; no allocation allowed) ----------
__device__ float g_phi_q[NIMG*LTOK*D];
__device__ float g_phi_k[NIMG*LTOK*D];
__device__ float g_v    [NIMG*LTOK*D];
__device__ float g_msg  [NIMG*LTOK*D];   // MLP2 output (pre-LN2)
__device__ float g_msg2 [NIMG*LTOK*D];   // mW output (pre-LN1)
__device__ float g_repn [NIMG*NWIN*D];
__device__ float g_phikr[NIMG*NWIN*D];
__device__ float g_vr   [NIMG*NWIN*D];
__device__ float g_sim  [NIMG*NWIN*NWIN];
__device__ int   g_sel  [NIMG*NWIN*KSEL];
__device__ float g_KVwin[NIMG*NWIN*NH*HD*HD];
__device__ float g_kswin[NIMG*NWIN*D];
__device__ float g_KVtot[NIMG*NH*HD*HD];
__device__ float g_kstot[NIMG*D];

// bf16 hi/lo operand planes (aligned for 16B loads). Zero-initialized,
// pad rows (rep 576..639) stay zero forever.
__device__ __align__(128) __nv_bfloat16 b_feat_hi[NIMG*LTOK*D];
__device__ __align__(128) __nv_bfloat16 b_feat_lo[NIMG*LTOK*D];
__device__ __align__(128) __nv_bfloat16 b_rep_hi [NREPAD*D];
__device__ __align__(128) __nv_bfloat16 b_rep_lo [NREPAD*D];
__device__ __align__(128) __nv_bfloat16 b_msg_hi [NIMG*LTOK*D];
__device__ __align__(128) __nv_bfloat16 b_msg_lo [NIMG*LTOK*D];
__device__ __align__(128) __nv_bfloat16 b_hcat_hi[NIMG*LTOK*2*D];
__device__ __align__(128) __nv_bfloat16 b_hcat_lo[NIMG*LTOK*2*D];
__device__ __align__(128) __nv_bfloat16 b_hid_hi [NIMG*LTOK*2*D];
__device__ __align__(128) __nv_bfloat16 b_hid_lo [NIMG*LTOK*2*D];
__device__ __align__(128) __nv_bfloat16 b_w_hi   [2*WTOT];   // both layers
__device__ __align__(128) __nv_bfloat16 b_w_lo   [2*WTOT];

// ---------------- helpers ----------------
__device__ __forceinline__ float phi(float x){ return x > 0.f ? x + 1.f : expf(x); }

__device__ __forceinline__ void split_bf16(float x, __nv_bfloat16& h, __nv_bfloat16& l){
  h = __float2bfloat16(x);
  l = __float2bfloat16(x - __bfloat162float(h));
}

__device__ __forceinline__ float blockReduceSum(float val, float* sbuf){
  __syncthreads();
  int lane = threadIdx.x & 31, wid = threadIdx.x >> 5;
  #pragma unroll
  for (int o = 16; o; o >>= 1) val += __shfl_down_sync(0xffffffffu, val, o);
  if (lane == 0) sbuf[wid] = val;
  __syncthreads();
  float r = (threadIdx.x < (blockDim.x >> 5)) ? sbuf[threadIdx.x] : 0.f;
  if (wid == 0){
    #pragma unroll
    for (int o = 16; o; o >>= 1) r += __shfl_down_sync(0xffffffffu, r, o);
    if (lane == 0) sbuf[0] = r;
  }
  __syncthreads();
  return sbuf[0];
}

__device__ __forceinline__ int spatial_l(int win, int t){
  int wy = win / WGRID, wx = win % WGRID;
  return (wy*8 + (t >> 3))*96 + wx*8 + (t & 7);
}

// ---------------- converters ----------------
// both layers at once: i in [0, 2*WTOT)
__global__ void k_convw(const float* __restrict__ q, const float* __restrict__ k,
                        const float* __restrict__ v, const float* __restrict__ m,
                        const float* __restrict__ w1, const float* __restrict__ w2){
  for (int i = blockIdx.x*blockDim.x + threadIdx.x; i < 2*WTOT;
       i += gridDim.x*blockDim.x){
    int layer = i / WTOT, j = i % WTOT;
    size_t o1 = (size_t)layer*D*D;           // 65536
    size_t o2 = (size_t)layer*2*D*2*D;       // 262144
    size_t o3 = (size_t)layer*D*2*D;         // 131072
    float x;
    if      (j < WOK) x = q[o1 + j];
    else if (j < WOV) x = k[o1 + j - WOK];
    else if (j < WOM) x = v[o1 + j - WOV];
    else if (j < WO1) x = m[o1 + j - WOM];
    else if (j < WO2) x = w1[o2 + j - WO1];
    else              x = w2[o3 + j - WO2];
    split_bf16(x, b_w_hi[i], b_w_lo[i]);
  }
}

// feat planes + hcat feat-half (cols 0..255)
__global__ void k_convfeat(const float* __restrict__ f0, const float* __restrict__ f1){
  const int half = 2*LTOK*D;
  for (int i = blockIdx.x*blockDim.x + threadIdx.x; i < NIMG*LTOK*D;
       i += gridDim.x*blockDim.x){
    float x = (i < half) ? f0[i] : f1[i - half];
    __nv_bfloat16 h, l;
    split_bf16(x, h, l);
    b_feat_hi[i] = h; b_feat_lo[i] = l;
    size_t row = (size_t)(i >> 8); int c = i & 255;
    size_t ho = (row << 9) + c;
    b_hcat_hi[ho] = h; b_hcat_lo[ho] = l;
  }
}

// ---------------- 1) per-window rep ----------------
__global__ void __launch_bounds__(256) k_rep(const float* __restrict__ f0,
                                             const float* __restrict__ f1,
                                             const float* __restrict__ conv_w){
  int img = blockIdx.x / NWIN, win = blockIdx.x % NWIN;
  int m = img >> 1, b = img & 1;
  const float* F = (m ? f1 : f0) + (size_t)b*LTOK*D;
  __shared__ float cw[CN*D];
  __shared__ float simall[WTOK*CN];
  __shared__ float avg[CN];
  __shared__ float red[32];
  int tid = threadIdx.x;
  for (int i = tid; i < CN*D; i += 256) cw[i] = conv_w[i];
  __syncthreads();
  int warp = tid >> 5, lane = tid & 31;
  for (int p = 0; p < 8; p++){
    int t = warp + p*8;
    int l = spatial_l(win, t);
    const float* fr = F + (size_t)l*D;
    float fv[8];
    #pragma unroll
    for (int i = 0; i < 8; i++) fv[i] = fr[lane + 32*i];
    for (int c = 0; c < CN; c++){
      float s = 0.f;
      #pragma unroll
      for (int i = 0; i < 8; i++) s += fv[i]*cw[c*D + lane + 32*i];
      #pragma unroll
      for (int o = 16; o; o >>= 1) s += __shfl_down_sync(0xffffffffu, s, o);
      if (lane == 0) simall[t*CN + c] = s;
    }
  }
  __syncthreads();
  if (tid < WTOK){
    float mx = -1e30f;
    for (int c = 0; c < CN; c++) mx = fmaxf(mx, simall[tid*CN + c]);
    float s = 0.f, e[CN];
    for (int c = 0; c < CN; c++){ e[c] = expf(simall[tid*CN + c] - mx); s += e[c]; }
    float inv = 1.f/s;
    for (int c = 0; c < CN; c++) simall[tid*CN + c] = e[c]*inv;
  }
  __syncthreads();
  if (tid < CN){
    float s = 0.f;
    for (int t = 0; t < WTOK; t++) s += simall[t*CN + tid];
    avg[tid] = s * (1.f/WTOK);
  }
  __syncthreads();
  float r = 0.f;
  for (int c = 0; c < CN; c++) r += avg[c]*cw[c*D + tid];
  size_t oi = (size_t)(img*NWIN + win)*D + tid;
  split_bf16(r, b_rep_hi[oi], b_rep_lo[oi]);
  float n2 = blockReduceSum(r*r, red);
  float nrm = fmaxf(sqrtf(n2), 1e-8f);
  g_repn[oi] = r / nrm;
}

// ---------------- 2) cosine sim (2x2 register blocking) ----------------
__global__ void k_cossim(int npairs, int self){
  const int H2 = NWIN/2;                 // 72
  long total = (long)npairs*H2*H2;
  for (long idx = (long)blockIdx.x*blockDim.x + threadIdx.x; idx < total;
       idx += (long)gridDim.x*blockDim.x){
    int p = (int)(idx/(H2*H2)); int rem = (int)(idx%(H2*H2));
    int q = (rem/H2)*2, s = (rem%H2)*2;
    const float* a0 = &g_repn[((size_t)p*NWIN + q)*D];
    const float* a1 = a0 + D;
    const float* b0 = self ? &g_repn[((size_t)p*NWIN + s)*D]
                           : &g_repn[(((size_t)(2+p))*NWIN + s)*D];
    const float* b1 = b0 + D;
    float c00 = 0.f, c01 = 0.f, c10 = 0.f, c11 = 0.f;
    #pragma unroll 4
    for (int k = 0; k < D; k += 4){
      float4 av0 = *(const float4*)&a0[k];
      float4 av1 = *(const float4*)&a1[k];
      float4 bv0 = *(const float4*)&b0[k];
      float4 bv1 = *(const float4*)&b1[k];
      c00 += av0.x*bv0.x + av0.y*bv0.y + av0.z*bv0.z + av0.w*bv0.w;
      c01 += av0.x*bv1.x + av0.y*bv1.y + av0.z*bv1.z + av0.w*bv1.w;
      c10 += av1.x*bv0.x + av1.y*bv0.y + av1.z*bv0.z + av1.w*bv0.w;
      c11 += av1.x*bv1.x + av1.y*bv1.y + av1.z*bv1.z + av1.w*bv1.w;
    }
    size_t ob = (size_t)p*NWIN*NWIN + (size_t)q*NWIN + s;
    g_sim[ob]            = c00;
    g_sim[ob + 1]        = c01;
    g_sim[ob + NWIN]     = c10;
    g_sim[ob + NWIN + 1] = c11;
  }
}

// ---------------- 3) top-K (warp per query; stable ties) --------------------
__global__ void k_topk(int self){
  int gw = (blockIdx.x*blockDim.x + threadIdx.x) >> 5;
  int lane = threadIdx.x & 31;
  if (gw >= NIMG*NWIN) return;
  int img = gw/NWIN, q = gw%NWIN;
  size_t base; int sq, ss;
  if (self){ base = (size_t)img*NWIN*NWIN; sq = NWIN; ss = 1; }
  else {
    int b = img & 1, m = img >> 1;
    base = (size_t)b*NWIN*NWIN;
    if (m == 0){ sq = NWIN; ss = 1; } else { sq = 1; ss = NWIN; }
  }
  const float* S = g_sim + base + (size_t)q*sq;
  float v0, v1, v2, v3, v4;
  v0 = S[(size_t)(lane      )*ss];
  v1 = S[(size_t)(lane +  32)*ss];
  v2 = S[(size_t)(lane +  64)*ss];
  v3 = S[(size_t)(lane +  96)*ss];
  v4 = (lane + 128 < NWIN) ? S[(size_t)(lane + 128)*ss] : -1e30f;
  for (int k = 0; k < KSEL; k++){
    float bv = v0; int bi = lane;
    if (v1 > bv){ bv = v1; bi = lane + 32; }
    if (v2 > bv){ bv = v2; bi = lane + 64; }
    if (v3 > bv){ bv = v3; bi = lane + 96; }
    if (v4 > bv){ bv = v4; bi = lane + 128; }
    #pragma unroll
    for (int o = 16; o; o >>= 1){
      float ov = __shfl_xor_sync(0xffffffffu, bv, o);
      int   oi = __shfl_xor_sync(0xffffffffu, bi, o);
      if (ov > bv || (ov == bv && oi < bi)){ bv = ov; bi = oi; }
    }
    if (lane == 0) g_sel[gw*KSEL + k] = bi;
    int wl = bi & 31, wj = bi >> 5;
    if (lane == wl){
      if      (wj == 0) v0 = -1e30f;
      else if (wj == 1) v1 = -1e30f;
      else if (wj == 2) v2 = -1e30f;
      else if (wj == 3) v3 = -1e30f;
      else              v4 = -1e30f;
    }
  }
}

// ---------------- 5) totals over all 144 rep rows ----------------
__global__ void __launch_bounds__(256) k_reptot(){
  int img = blockIdx.x >> 3, h = blockIdx.x & 7;
  __shared__ float pk[NWIN*HD];
  __shared__ float vv[NWIN*HD];
  int tid = threadIdx.x;
  for (int i = tid; i < NWIN*HD; i += 256){
    int r = i/HD, d = i%HD;
    size_t off = ((size_t)img*NWIN + r)*D + h*HD + d;
    pk[i] = g_phikr[off]; vv[i] = g_vr[off];
  }
  __syncthreads();
  for (int o = tid; o < HD*HD; o += 256){
    int d = o/HD, j = o%HD;
    float s = 0.f;
    for (int r = 0; r < NWIN; r++) s += pk[r*HD + d]*vv[r*HD + j];
    g_KVtot[((size_t)img*NH + h)*HD*HD + o] = s;
  }
  if (tid < HD){
    float s = 0.f;
    for (int r = 0; r < NWIN; r++) s += pk[r*HD + tid];
    g_kstot[(size_t)img*D + h*HD + tid] = s;
  }
}

// ====== 3xBF16 GEMM, ldmatrix + cp.async 4-stage: C = act(A @ B^T) ==========
template<int ACT>
__device__ __forceinline__ float actf(float x){
  if (ACT == 1) return x > 0.f ? x + 1.f : expf(x); // phi = elu + 1
  if (ACT == 2) return fmaxf(x, 0.f);               // relu
  return x;
}

__device__ __forceinline__ void mma_bf16(float* d, const uint32_t* a, const uint32_t* b){
  asm volatile(
    "mma.sync.aligned.m16n8k16.row.col.f32.bf16.bf16.f32 "
    "{%0,%1,%2,%3}, {%4,%5,%6,%7}, {%8,%9}, {%0,%1,%2,%3};"
    : "+f"(d[0]), "+f"(d[1]), "+f"(d[2]), "+f"(d[3])
    : "r"(a[0]), "r"(a[1]), "r"(a[2]), "r"(a[3]), "r"(b[0]), "r"(b[1]));
}

__device__ __forceinline__ void ldsm4(uint32_t* r, uint32_t a){
  asm volatile("ldmatrix.sync.aligned.m8n8.x4.shared.b16 {%0,%1,%2,%3}, [%4];"
    : "=r"(r[0]), "=r"(r[1]), "=r"(r[2]), "=r"(r[3]) : "r"(a));
}

__device__ __forceinline__ void cp16(uint32_t s, const void* g){
  asm volatile("cp.async.cg.shared.global [%0], [%1], 16;\n" :: "r"(s), "l"(g));
}
__device__ __forceinline__ void cp_commit(){ asm volatile("cp.async.commit_group;\n"); }
template<int NG> __device__ __forceinline__ void cp_wait(){
  asm volatile("cp.async.wait_group %0;\n" :: "n"(NG));
}

#define BM 128
#define BN 128
#define BK 16
#define SPH 24           // smem row stride in halves (48B; 3 x 16B units -> LDSM conflict-free)
#define PLANE_B 6144     // bytes per plane (128*48)
#define STAGE_B 24576    // bytes per stage (4 planes: Ah, Al, Bh, Bl)
#define NSTAGE 4
#define SMEM_DYN (NSTAGE*STAGE_B)   // 98304 bytes (dynamic, opt-in)

// one cp.async stage: 256 threads x 1 chunk per plane-operand
__device__ __forceinline__ void load_stage(uint32_t sb,
    const __nv_bfloat16* __restrict__ Ah, const __nv_bfloat16* __restrict__ Al,
    const __nv_bfloat16* __restrict__ Bh, const __nv_bfloat16* __restrict__ Bl,
    size_t abase, size_t bbase, int K, int k0, int tid)
{
  int row = tid >> 1, kw = tid & 1;
  uint32_t so = (uint32_t)(row*48 + kw*16);
  size_t go = (size_t)row*K + k0 + kw*8;
  cp16(sb + 0*PLANE_B + so, Ah + abase + go);
  cp16(sb + 1*PLANE_B + so, Al + abase + go);
  cp16(sb + 2*PLANE_B + so, Bh + bbase + go);
  cp16(sb + 3*PLANE_B + so, Bl + bbase + go);
  cp_commit();
}

// OUTMODE 0: fp32 -> C0 (ACT), M-guarded.
// OUTMODE 1: hi/lo planes -> Ch/Cl (ACT), M multiple of 128.
// OUTMODE 3: fused qkv: N=768; region by bn: q(phi)/k(phi)/v. stride 256.
// OUTMODE 4: fused rep kv: N=512; region 0 -> C0 with phi, 1 -> C1. stride 256, M-guarded.
template<int ACT, int OUTMODE>
__global__ void __launch_bounds__(256, 2)
bgemm(const __nv_bfloat16* __restrict__ Ah, const __nv_bfloat16* __restrict__ Al,
      const __nv_bfloat16* __restrict__ Bh, const __nv_bfloat16* __restrict__ Bl,
      float* __restrict__ C0, float* __restrict__ C1, float* __restrict__ C2,
      __nv_bfloat16* __restrict__ Ch, __nv_bfloat16* __restrict__ Cl,
      int M, int N, int K)
{
  extern __shared__ __align__(16) char smraw[]; // NSTAGE * 24576 dynamic
  uint32_t sb0 = (uint32_t)__cvta_generic_to_shared(smraw);
  const int tid = threadIdx.x;
  const int bm = blockIdx.y*BM, bn = blockIdx.x*BN;
  const int warp = tid >> 5, lane = tid & 31;
  const int wm = (warp >> 1)*32, wn = (warp & 1)*64;
  const int grp = lane >> 2, tig = lane & 3;
  const size_t abase = (size_t)bm*K, bbase = (size_t)bn*K;

  float acc[16][4];
  #pragma unroll
  for (int f = 0; f < 16; f++)
    #pragma unroll
    for (int r = 0; r < 4; r++) acc[f][r] = 0.f;

  const int nk = K/BK;   // >= 16 for all our shapes
  load_stage(sb0,             Ah, Al, Bh, Bl, abase, bbase, K, 0,    tid);
  load_stage(sb0 +   STAGE_B, Ah, Al, Bh, Bl, abase, bbase, K, BK,   tid);
  load_stage(sb0 + 2*STAGE_B, Ah, Al, Bh, Bl, abase, bbase, K, 2*BK, tid);

  // ldmatrix lane addresses (bytes, relative to plane base)
  const uint32_t a_lane = (uint32_t)(((wm + (lane & 15))*SPH + (lane >> 4)*8)*2);
  const uint32_t b_lane = (uint32_t)(((wn + (lane & 7) + (lane >> 4)*8)*SPH
                                      + ((lane >> 3) & 1)*8)*2);

  int stg = 0;                 // stage index of tile kt
  for (int kt = 0; kt < nk; kt++){
    int rem = nk - 1 - kt;     // loads pending beyond tile kt (capped at 3)
    if      (rem >= 3) cp_wait<3>();
    else if (rem == 2) cp_wait<2>();
    else if (rem == 1) cp_wait<1>();
    else               cp_wait<0>();
    __syncthreads();
    uint32_t sb = sb0 + (uint32_t)(stg*STAGE_B);
    // issue lookahead load (buffer (kt+3)%4 == (kt-1)%4, consumed last iter)
    if (kt + 3 < nk){
      int ns = stg + 3; if (ns >= NSTAGE) ns -= NSTAGE;
      load_stage(sb0 + (uint32_t)(ns*STAGE_B), Ah, Al, Bh, Bl,
                 abase, bbase, K, (kt + 3)*BK, tid);
    }

    uint32_t ah[2][4], al[2][4];
    ldsm4(ah[0], sb + a_lane);
    ldsm4(ah[1], sb + a_lane + 768);           // +16 rows * 48B
    ldsm4(al[0], sb + PLANE_B + a_lane);
    ldsm4(al[1], sb + PLANE_B + a_lane + 768);
    #pragma unroll
    for (int jp = 0; jp < 4; jp++){
      uint32_t bh[4], bl[4];
      ldsm4(bh, sb + 2*PLANE_B + b_lane + jp*768);
      ldsm4(bl, sb + 3*PLANE_B + b_lane + jp*768);
      // term-major: per-accumulator order unchanged (bl, lh, hh) ->
      // bit-identical results, but RAW chain distance 1 -> 4.
      #pragma unroll
      for (int i = 0; i < 2; i++)
        #pragma unroll
        for (int jj = 0; jj < 2; jj++)
          mma_bf16(acc[i*8 + jp*2 + jj], ah[i], bl + jj*2);
      #pragma unroll
      for (int i = 0; i < 2; i++)
        #pragma unroll
        for (int jj = 0; jj < 2; jj++)
          mma_bf16(acc[i*8 + jp*2 + jj], al[i], bh + jj*2);
      #pragma unroll
      for (int i = 0; i < 2; i++)
        #pragma unroll
        for (int jj = 0; jj < 2; jj++)
          mma_bf16(acc[i*8 + jp*2 + jj], ah[i], bh + jj*2);
    }
    if (++stg == NSTAGE) stg = 0;
  }

  #pragma unroll
  for (int i = 0; i < 2; i++){
    int r0 = bm + wm + i*16 + grp;
    #pragma unroll
    for (int j = 0; j < 8; j++){
      const float* dd = acc[i*8 + j];
      int cc = wn + j*8 + tig*2;
      if (OUTMODE == 0){
        int c = bn + cc;
        if (r0 < M){
          C0[(size_t)r0*N + c    ] = actf<ACT>(dd[0]);
          C0[(size_t)r0*N + c + 1] = actf<ACT>(dd[1]);
        }
        if (r0 + 8 < M){
          C0[(size_t)(r0+8)*N + c    ] = actf<ACT>(dd[2]);
          C0[(size_t)(r0+8)*N + c + 1] = actf<ACT>(dd[3]);
        }
      } else if (OUTMODE == 1){
        int c = bn + cc;
        #pragma unroll
        for (int rr = 0; rr < 2; rr++){
          float v0 = actf<ACT>(dd[rr*2]), v1 = actf<ACT>(dd[rr*2+1]);
          __nv_bfloat162 h, l;
          h.x = __float2bfloat16(v0); h.y = __float2bfloat16(v1);
          l.x = __float2bfloat16(v0 - __bfloat162float(h.x));
          l.y = __float2bfloat16(v1 - __bfloat162float(h.y));
          size_t o = (size_t)(r0 + rr*8)*N + c;
          *(__nv_bfloat162*)&Ch[o] = h;
          *(__nv_bfloat162*)&Cl[o] = l;
        }
      } else if (OUTMODE == 3){
        int reg = bn >> 8;                   // 0:q 1:k 2:v
        float* T = (reg == 0) ? C0 : ((reg == 1) ? C1 : C2);
        int c = (bn & 255) + cc;
        float v0 = (reg < 2) ? actf<1>(dd[0]) : dd[0];
        float v1 = (reg < 2) ? actf<1>(dd[1]) : dd[1];
        float v2 = (reg < 2) ? actf<1>(dd[2]) : dd[2];
        float v3 = (reg < 2) ? actf<1>(dd[3]) : dd[3];
        T[(size_t)r0*256 + c    ] = v0;
        T[(size_t)r0*256 + c + 1] = v1;
        T[(size_t)(r0+8)*256 + c    ] = v2;
        T[(size_t)(r0+8)*256 + c + 1] = v3;
      } else { // OUTMODE 4: rep kv
        int reg = bn >> 8;                   // 0: phi(k) -> C0, 1: v -> C1
        float* T = reg ? C1 : C0;
        int c = (bn & 255) + cc;
        float v0 = reg ? dd[0] : actf<1>(dd[0]);
        float v1 = reg ? dd[1] : actf<1>(dd[1]);
        float v2 = reg ? dd[2] : actf<1>(dd[2]);
        float v3 = reg ? dd[3] : actf<1>(dd[3]);
        if (r0 < M){
          T[(size_t)r0*256 + c    ] = v0;
          T[(size_t)r0*256 + c + 1] = v1;
        }
        if (r0 + 8 < M){
          T[(size_t)(r0+8)*256 + c    ] = v2;
          T[(size_t)(r0+8)*256 + c + 1] = v3;
        }
      }
    }
  }
}

// ---------------- 6) per-window KV/ksum aggregates (vectorized) -------------
__global__ void __launch_bounds__(256) k_winagg(){
  int bid = blockIdx.x;
  int h = bid & 7; int wv = bid >> 3;
  int win = wv % NWIN, img = wv / NWIN;
  __shared__ float pk[WTOK*HD];
  __shared__ float vv[WTOK*HD];
  int tid = threadIdx.x;
  #pragma unroll
  for (int i = tid; i < WTOK*HD/4; i += 256){
    int t = i >> 3, d4 = (i & 7)*4;
    int l = spatial_l(win, t);
    size_t off = ((size_t)img*LTOK + l)*D + h*HD + d4;
    *(float4*)&pk[t*HD + d4] = *(const float4*)&g_phi_k[off];
    *(float4*)&vv[t*HD + d4] = *(const float4*)&g_v[off];
  }
  __syncthreads();
  int d = tid >> 3, j0 = (tid & 7)*4;
  float a0 = 0.f, a1 = 0.f, a2 = 0.f, a3 = 0.f;
  #pragma unroll 8
  for (int t = 0; t < WTOK; t++){
    float p = pk[t*HD + d];
    float4 v4 = *(const float4*)&vv[t*HD + j0];
    a0 += p*v4.x; a1 += p*v4.y; a2 += p*v4.z; a3 += p*v4.w;
  }
  size_t ob = (((size_t)(img*NWIN + win))*NH + h)*HD*HD + (size_t)d*HD + j0;
  *(float4*)&g_KVwin[ob] = make_float4(a0, a1, a2, a3);
  if (tid < HD){
    float s = 0.f;
    for (int t = 0; t < WTOK; t++) s += pk[t*HD + tid];
    g_kswin[((size_t)img*NWIN + win)*D + h*HD + tid] = s;
  }
}

// ---------------- 7) attention: register-resident KV build + apply ----------
__global__ void __launch_bounds__(256) k_attn(int layer){
  int img = blockIdx.x / NWIN, q = blockIdx.x % NWIN;
  int src = (layer == 0) ? img : (img ^ 2); // cross: flip map, keep batch
  __shared__ float bufpk[KSEL][D]; // 8KB
  __shared__ float bufv [KSEL][D]; // 8KB
  __shared__ int   wsel[KSEL];
  int tid = threadIdx.x;
  if (tid < KSEL) wsel[tid] = g_sel[(img*NWIN + q)*KSEL + tid];
  __syncthreads();
  #pragma unroll
  for (int k = 0; k < KSEL; k++){
    int w = wsel[k];
    bufpk[k][tid] = g_phikr[((size_t)src*NWIN + w)*D + tid];
    bufv [k][tid] = g_vr   [((size_t)src*NWIN + w)*D + tid];
  }
  __syncthreads();

  int h = tid >> 5, lane = tid & 31;
  // init KV column + ksum from totals (order matches reference chain)
  float kvreg[32];
  const float* KVT = g_KVtot + (size_t)src*NH*HD*HD + h*HD*HD;
  #pragma unroll
  for (int d = 0; d < 32; d++) kvreg[d] = KVT[d*HD + lane];
  float ksv = g_kstot[(size_t)src*D + h*HD + lane];
  // accumulate the 8 selected windows (same per-element order as before:
  // kv += KVwin - pk*v, sequentially per k)
  for (int k = 0; k < KSEL; k++){
    int w = wsel[k];
    const float* KVW = g_KVwin + ((size_t)(src*NWIN + w))*NH*HD*HD + h*HD*HD;
    float vj = bufv[k][h*HD + lane];
    #pragma unroll
    for (int d = 0; d < 32; d++)
      kvreg[d] += KVW[d*HD + lane] - bufpk[k][h*HD + d]*vj;
    ksv += g_kswin[((size_t)src*NWIN + w)*D + h*HD + lane] - bufpk[k][h*HD + lane];
  }

  const float* pqb = g_phi_q + (size_t)img*LTOK*D + h*HD + lane;
  for (int t = 0; t < WTOK; t++){
    int l = spatial_l(q, t);
    float pqv = __ldg(pqb + (size_t)l*D);
    float n0 = 0.f, n1 = 0.f, n2 = 0.f, n3 = 0.f;
    #pragma unroll
    for (int d = 0; d < 32; d += 4){
      float p0 = __shfl_sync(0xffffffffu, pqv, d    );
      float p1 = __shfl_sync(0xffffffffu, pqv, d + 1);
      float p2 = __shfl_sync(0xffffffffu, pqv, d + 2);
      float p3 = __shfl_sync(0xffffffffu, pqv, d + 3);
      n0 += p0*kvreg[d];   n1 += p1*kvreg[d+1];
      n2 += p2*kvreg[d+2]; n3 += p3*kvreg[d+3];
    }
    float num = (n0 + n1) + (n2 + n3);
    float dv = pqv*ksv;
    #pragma unroll
    for (int o = 16; o; o >>= 1) dv += __shfl_xor_sync(0xffffffffu, dv, o);
    float r = num / (dv + 1e-6f);
    size_t oi = ((size_t)img*LTOK + l)*D + h*HD + lane;
    split_bf16(r, b_msg_hi[oi], b_msg_lo[oi]);
  }
}

// ---------------- 8) LN1 fused with hcat msg-half write ----------------
__global__ void __launch_bounds__(256) k_ln_hcat(const float* __restrict__ X,
                                                 const float* __restrict__ g,
                                                 const float* __restrict__ b){
  size_t row = blockIdx.x;
  int tid = threadIdx.x;
  __shared__ float red[32];
  float x = X[row*D + tid];
  float mu = blockReduceSum(x, red) * (1.f/D);
  float d = x - mu;
  float var = blockReduceSum(d*d, red) * (1.f/D);
  float y = d*rsqrtf(var + 1e-5f)*g[tid] + b[tid];
  size_t ho = (row << 9) + 256 + tid;
  split_bf16(y, b_hcat_hi[ho], b_hcat_lo[ho]);
}

// ---------------- 10) final: out = x + LN(m); feat + hcat planes ------------
__global__ void __launch_bounds__(256) k_final(const float* __restrict__ f0,
                                               const float* __restrict__ f1,
                                               float* __restrict__ out,
                                               const float* __restrict__ g,
                                               const float* __restrict__ b){
  size_t row = blockIdx.x;
  int tid = threadIdx.x;
  int img = (int)(row / LTOK); size_t l = row % LTOK;
  int m = img >> 1, bb = img & 1;
  __shared__ float red[32];
  float x = g_msg[row*D + tid];
  float mu = blockReduceSum(x, red) * (1.f/D);
  float d = x - mu;
  float var = blockReduceSum(d*d, red) * (1.f/D);
  float msg3 = d*rsqrtf(var + 1e-5f)*g[tid] + b[tid];
  const float* F = (m ? f1 : f0) + ((size_t)bb*LTOK + l)*D;
  size_t oi = row*D + tid;
  float r = F[tid] + msg3;
  out[oi] = r;
  __nv_bfloat16 h, lo;
  split_bf16(r, h, lo);
  b_feat_hi[oi] = h; b_feat_lo[oi] = lo;
  size_t ho = (row << 9) + tid;
  b_hcat_hi[ho] = h; b_hcat_lo[ho] = lo;
}

// ---------------- host ----------------
extern "C" void kernel_launch(void* const* d_in, const int* in_sizes, int n_in,
                              void* d_out, int out_size){
  (void)in_sizes; (void)n_in; (void)out_size;
  const float* feat0 = (const float*)d_in[0];
  const float* feat1 = (const float*)d_in[1];
  const float* qW    = (const float*)d_in[8];
  const float* kW    = (const float*)d_in[9];
  const float* vW    = (const float*)d_in[10];
  const float* mW    = (const float*)d_in[11];
  const float* mlpW1 = (const float*)d_in[12];
  const float* mlpW2 = (const float*)d_in[13];
  const float* n1g   = (const float*)d_in[14];
  const float* n1b   = (const float*)d_in[15];
  const float* n2g   = (const float*)d_in[16];
  const float* n2b   = (const float*)d_in[17];
  const float* conv_w= (const float*)d_in[18];
  float* out = (float*)d_out;

  // opt-in dynamic smem (idempotent; host-side attr set, not a stream op)
  cudaFuncSetAttribute((const void*)bgemm<0,0>, cudaFuncAttributeMaxDynamicSharedMemorySize, SMEM_DYN);
  cudaFuncSetAttribute((const void*)bgemm<0,3>, cudaFuncAttributeMaxDynamicSharedMemorySize, SMEM_DYN);
  cudaFuncSetAttribute((const void*)bgemm<0,4>, cudaFuncAttributeMaxDynamicSharedMemorySize, SMEM_DYN);
  cudaFuncSetAttribute((const void*)bgemm<2,1>, cudaFuncAttributeMaxDynamicSharedMemorySize, SMEM_DYN);

  float *p_phiq, *p_phik, *p_v, *p_msg, *p_msg2, *p_phikr, *p_vr;
  __nv_bfloat16 *p_fh, *p_fl, *p_rh, *p_rl, *p_mh, *p_ml, *p_ch, *p_cl,
                *p_hh, *p_hl, *p_wh, *p_wl;
  cudaGetSymbolAddress((void**)&p_phiq, g_phi_q);
  cudaGetSymbolAddress((void**)&p_phik, g_phi_k);
  cudaGetSymbolAddress((void**)&p_v,    g_v);
  cudaGetSymbolAddress((void**)&p_msg,  g_msg);
  cudaGetSymbolAddress((void**)&p_msg2, g_msg2);
  cudaGetSymbolAddress((void**)&p_phikr,g_phikr);
  cudaGetSymbolAddress((void**)&p_vr,   g_vr);
  cudaGetSymbolAddress((void**)&p_fh, b_feat_hi); cudaGetSymbolAddress((void**)&p_fl, b_feat_lo);
  cudaGetSymbolAddress((void**)&p_rh, b_rep_hi);  cudaGetSymbolAddress((void**)&p_rl, b_rep_lo);
  cudaGetSymbolAddress((void**)&p_mh, b_msg_hi);  cudaGetSymbolAddress((void**)&p_ml, b_msg_lo);
  cudaGetSymbolAddress((void**)&p_ch, b_hcat_hi); cudaGetSymbolAddress((void**)&p_cl, b_hcat_lo);
  cudaGetSymbolAddress((void**)&p_hh, b_hid_hi);  cudaGetSymbolAddress((void**)&p_hl, b_hid_lo);
  cudaGetSymbolAddress((void**)&p_wh, b_w_hi);    cudaGetSymbolAddress((void**)&p_wl, b_w_lo);

  const int Mall = NIMG*LTOK;   // 36864
  const int Mrep = NIMG*NWIN;   // 576 (buffers padded to 640)

  // convert BOTH layers' weights once
  k_convw<<<1280, 256>>>(qW, kW, vW, mW, mlpW1, mlpW2);

  for (int layer = 0; layer < 2; layer++){
    const float* F0 = layer ? out : feat0;
    const float* F1 = layer ? out + (size_t)2*LTOK*D : feat1;
    int self = (layer == 0);
    int npairs = self ? NIMG : 2;
    const size_t wofs = (size_t)layer*WTOT;

    if (layer == 0) k_convfeat<<<4096, 256>>>(feat0, feat1);

    k_rep<<<NIMG*NWIN, 256>>>(F0, F1, conv_w);
    {
      int total = npairs*(NWIN/2)*(NWIN/2);
      k_cossim<<<(total + 255)/256, 256>>>(npairs, self);
    }
    k_topk<<<(NIMG*NWIN*32 + 255)/256, 256>>>(self);

    // fused rep k/v projection (N=512, rows padded to 640)
    bgemm<0,4><<<dim3(4, NREPAD/BM), 256, SMEM_DYN>>>(p_rh, p_rl,
                                            p_wh + wofs + WOK, p_wl + wofs + WOK,
                                            p_phikr, p_vr, nullptr, nullptr, nullptr,
                                            Mrep, 512, D);
    k_reptot<<<NIMG*NH, 256>>>();

    // fused q/k/v projection over ALL images (M=36864, N=768)
    bgemm<0,3><<<dim3(6, Mall/BM), 256, SMEM_DYN>>>(p_fh, p_fl,
                                          p_wh + wofs + WOQ, p_wl + wofs + WOQ,
                                          p_phiq, p_phik, p_v, nullptr, nullptr,
                                          Mall, 3*D, D);

    k_winagg<<<NIMG*NWIN*NH, 256>>>();
    k_attn<<<NIMG*NWIN, 256>>>(layer);

    bgemm<0,0><<<dim3(2, Mall/BM), 256, SMEM_DYN>>>(p_mh, p_ml,
                                          p_wh + wofs + WOM, p_wl + wofs + WOM,
                                          p_msg2, nullptr, nullptr, nullptr, nullptr,
                                          Mall, D, D);
    k_ln_hcat<<<Mall, 256>>>(p_msg2, n1g + layer*D, n1b + layer*D);

    bgemm<2,1><<<dim3(4, Mall/BM), 256, SMEM_DYN>>>(p_ch, p_cl,
                                          p_wh + wofs + WO1, p_wl + wofs + WO1,
                                          nullptr, nullptr, nullptr, p_hh, p_hl,
                                          Mall, 2*D, 2*D); // relu -> hid planes
    bgemm<0,0><<<dim3(2, Mall/BM), 256, SMEM_DYN>>>(p_hh, p_hl,
                                          p_wh + wofs + WO2, p_wl + wofs + WO2,
                                          p_msg, nullptr, nullptr, nullptr, nullptr,
                                          Mall, D, 2*D);

    k_final<<<Mall, 256>>>(F0, F1, out, n2g + layer*D, n2b + layer*D);
  }
}

// round 16
// speedup vs baseline: 2.3768x; 1.0658x over previous
#include <cuda_runtime.h>
#include <cuda_bf16.h>
#include <math.h>
#include <stdint.h>

// ---------------- problem constants ----------------
#define NIMG 4        // (map m, batch b) -> img = m*2+b
#define LTOK 9216     // 96*96
#define D 256
#define NH 8
#define HD 32
#define WGRID 12      // 96/8
#define NWIN 144
#define WTOK 64
#define KSEL 8
#define CN 16
#define NREPAD 640    // rep rows padded to tile multiple (576 -> 640)

// weight-plane buffer offsets (elements, per layer)
#define WOQ 0
#define WOK 65536
#define WOV 131072
#define WOM 196608
#define WO1 262144
#define WO2 524288
#define WTOT 655360

// ---------------- scratch (device globals; no allocation allowed) ----------
__device__ float g_phi_q[NIMG*LTOK*D];
__device__ float g_phi_k[NIMG*LTOK*D];
__device__ float g_v    [NIMG*LTOK*D];
__device__ float g_repn [NIMG*NWIN*D];
__device__ float g_phikr[NIMG*NWIN*D];
__device__ float g_vr   [NIMG*NWIN*D];
__device__ float g_sim  [NIMG*NWIN*NWIN];
__device__ int   g_sel  [NIMG*NWIN*KSEL];
__device__ float g_KVwin[NIMG*NWIN*NH*HD*HD];
__device__ float g_kswin[NIMG*NWIN*D];
__device__ float g_KVtot[NIMG*NH*HD*HD];
__device__ float g_kstot[NIMG*D];

// bf16 hi/lo operand planes (aligned for 16B loads). Zero-initialized,
// pad rows (rep 576..639) stay zero forever.
__device__ __align__(128) __nv_bfloat16 b_feat_hi[NIMG*LTOK*D];
__device__ __align__(128) __nv_bfloat16 b_feat_lo[NIMG*LTOK*D];
__device__ __align__(128) __nv_bfloat16 b_rep_hi [NREPAD*D];
__device__ __align__(128) __nv_bfloat16 b_rep_lo [NREPAD*D];
__device__ __align__(128) __nv_bfloat16 b_msg_hi [NIMG*LTOK*D];
__device__ __align__(128) __nv_bfloat16 b_msg_lo [NIMG*LTOK*D];
__device__ __align__(128) __nv_bfloat16 b_hcat_hi[NIMG*LTOK*2*D];
__device__ __align__(128) __nv_bfloat16 b_hcat_lo[NIMG*LTOK*2*D];
__device__ __align__(128) __nv_bfloat16 b_hid_hi [NIMG*LTOK*2*D];
__device__ __align__(128) __nv_bfloat16 b_hid_lo [NIMG*LTOK*2*D];
__device__ __align__(128) __nv_bfloat16 b_w_hi   [2*WTOT];   // both layers
__device__ __align__(128) __nv_bfloat16 b_w_lo   [2*WTOT];

// ---------------- helpers ----------------
__device__ __forceinline__ float phi(float x){ return x > 0.f ? x + 1.f : expf(x); }

__device__ __forceinline__ void split_bf16(float x, __nv_bfloat16& h, __nv_bfloat16& l){
  h = __float2bfloat16(x);
  l = __float2bfloat16(x - __bfloat162float(h));
}

__device__ __forceinline__ float blockReduceSum(float val, float* sbuf){
  __syncthreads();
  int lane = threadIdx.x & 31, wid = threadIdx.x >> 5;
  #pragma unroll
  for (int o = 16; o; o >>= 1) val += __shfl_down_sync(0xffffffffu, val, o);
  if (lane == 0) sbuf[wid] = val;
  __syncthreads();
  float r = (threadIdx.x < (blockDim.x >> 5)) ? sbuf[threadIdx.x] : 0.f;
  if (wid == 0){
    #pragma unroll
    for (int o = 16; o; o >>= 1) r += __shfl_down_sync(0xffffffffu, r, o);
    if (lane == 0) sbuf[0] = r;
  }
  __syncthreads();
  return sbuf[0];
}

__device__ __forceinline__ int spatial_l(int win, int t){
  int wy = win / WGRID, wx = win % WGRID;
  return (wy*8 + (t >> 3))*96 + wx*8 + (t & 7);
}

// ---------------- converters ----------------
// both layers at once: i in [0, 2*WTOT)
__global__ void k_convw(const float* __restrict__ q, const float* __restrict__ k,
                        const float* __restrict__ v, const float* __restrict__ m,
                        const float* __restrict__ w1, const float* __restrict__ w2){
  for (int i = blockIdx.x*blockDim.x + threadIdx.x; i < 2*WTOT;
       i += gridDim.x*blockDim.x){
    int layer = i / WTOT, j = i % WTOT;
    size_t o1 = (size_t)layer*D*D;           // 65536
    size_t o2 = (size_t)layer*2*D*2*D;       // 262144
    size_t o3 = (size_t)layer*D*2*D;         // 131072
    float x;
    if      (j < WOK) x = q[o1 + j];
    else if (j < WOV) x = k[o1 + j - WOK];
    else if (j < WOM) x = v[o1 + j - WOV];
    else if (j < WO1) x = m[o1 + j - WOM];
    else if (j < WO2) x = w1[o2 + j - WO1];
    else              x = w2[o3 + j - WO2];
    split_bf16(x, b_w_hi[i], b_w_lo[i]);
  }
}

// feat planes + hcat feat-half (cols 0..255)
__global__ void k_convfeat(const float* __restrict__ f0, const float* __restrict__ f1){
  const int half = 2*LTOK*D;
  for (int i = blockIdx.x*blockDim.x + threadIdx.x; i < NIMG*LTOK*D;
       i += gridDim.x*blockDim.x){
    float x = (i < half) ? f0[i] : f1[i - half];
    __nv_bfloat16 h, l;
    split_bf16(x, h, l);
    b_feat_hi[i] = h; b_feat_lo[i] = l;
    size_t row = (size_t)(i >> 8); int c = i & 255;
    size_t ho = (row << 9) + c;
    b_hcat_hi[ho] = h; b_hcat_lo[ho] = l;
  }
}

// ---------------- 1) per-window rep ----------------
__global__ void __launch_bounds__(256) k_rep(const float* __restrict__ f0,
                                             const float* __restrict__ f1,
                                             const float* __restrict__ conv_w){
  int img = blockIdx.x / NWIN, win = blockIdx.x % NWIN;
  int m = img >> 1, b = img & 1;
  const float* F = (m ? f1 : f0) + (size_t)b*LTOK*D;
  __shared__ float cw[CN*D];
  __shared__ float simall[WTOK*CN];
  __shared__ float avg[CN];
  __shared__ float red[32];
  int tid = threadIdx.x;
  for (int i = tid; i < CN*D; i += 256) cw[i] = conv_w[i];
  __syncthreads();
  int warp = tid >> 5, lane = tid & 31;
  for (int p = 0; p < 8; p++){
    int t = warp + p*8;
    int l = spatial_l(win, t);
    const float* fr = F + (size_t)l*D;
    float fv[8];
    #pragma unroll
    for (int i = 0; i < 8; i++) fv[i] = fr[lane + 32*i];
    for (int c = 0; c < CN; c++){
      float s = 0.f;
      #pragma unroll
      for (int i = 0; i < 8; i++) s += fv[i]*cw[c*D + lane + 32*i];
      #pragma unroll
      for (int o = 16; o; o >>= 1) s += __shfl_down_sync(0xffffffffu, s, o);
      if (lane == 0) simall[t*CN + c] = s;
    }
  }
  __syncthreads();
  if (tid < WTOK){
    float mx = -1e30f;
    for (int c = 0; c < CN; c++) mx = fmaxf(mx, simall[tid*CN + c]);
    float s = 0.f, e[CN];
    for (int c = 0; c < CN; c++){ e[c] = expf(simall[tid*CN + c] - mx); s += e[c]; }
    float inv = 1.f/s;
    for (int c = 0; c < CN; c++) simall[tid*CN + c] = e[c]*inv;
  }
  __syncthreads();
  if (tid < CN){
    float s = 0.f;
    for (int t = 0; t < WTOK; t++) s += simall[t*CN + tid];
    avg[tid] = s * (1.f/WTOK);
  }
  __syncthreads();
  float r = 0.f;
  for (int c = 0; c < CN; c++) r += avg[c]*cw[c*D + tid];
  size_t oi = (size_t)(img*NWIN + win)*D + tid;
  split_bf16(r, b_rep_hi[oi], b_rep_lo[oi]);
  float n2 = blockReduceSum(r*r, red);
  float nrm = fmaxf(sqrtf(n2), 1e-8f);
  g_repn[oi] = r / nrm;
}

// ---------------- 2) cosine sim (2x2 register blocking) ----------------
__global__ void k_cossim(int npairs, int self){
  const int H2 = NWIN/2;                 // 72
  long total = (long)npairs*H2*H2;
  for (long idx = (long)blockIdx.x*blockDim.x + threadIdx.x; idx < total;
       idx += (long)gridDim.x*blockDim.x){
    int p = (int)(idx/(H2*H2)); int rem = (int)(idx%(H2*H2));
    int q = (rem/H2)*2, s = (rem%H2)*2;
    const float* a0 = &g_repn[((size_t)p*NWIN + q)*D];
    const float* a1 = a0 + D;
    const float* b0 = self ? &g_repn[((size_t)p*NWIN + s)*D]
                           : &g_repn[(((size_t)(2+p))*NWIN + s)*D];
    const float* b1 = b0 + D;
    float c00 = 0.f, c01 = 0.f, c10 = 0.f, c11 = 0.f;
    #pragma unroll 4
    for (int k = 0; k < D; k += 4){
      float4 av0 = *(const float4*)&a0[k];
      float4 av1 = *(const float4*)&a1[k];
      float4 bv0 = *(const float4*)&b0[k];
      float4 bv1 = *(const float4*)&b1[k];
      c00 += av0.x*bv0.x + av0.y*bv0.y + av0.z*bv0.z + av0.w*bv0.w;
      c01 += av0.x*bv1.x + av0.y*bv1.y + av0.z*bv1.z + av0.w*bv1.w;
      c10 += av1.x*bv0.x + av1.y*bv0.y + av1.z*bv0.z + av1.w*bv0.w;
      c11 += av1.x*bv1.x + av1.y*bv1.y + av1.z*bv1.z + av1.w*bv1.w;
    }
    size_t ob = (size_t)p*NWIN*NWIN + (size_t)q*NWIN + s;
    g_sim[ob]            = c00;
    g_sim[ob + 1]        = c01;
    g_sim[ob + NWIN]     = c10;
    g_sim[ob + NWIN + 1] = c11;
  }
}

// ---------------- 3) top-K (warp per query; stable ties) --------------------
__global__ void k_topk(int self){
  int gw = (blockIdx.x*blockDim.x + threadIdx.x) >> 5;
  int lane = threadIdx.x & 31;
  if (gw >= NIMG*NWIN) return;
  int img = gw/NWIN, q = gw%NWIN;
  size_t base; int sq, ss;
  if (self){ base = (size_t)img*NWIN*NWIN; sq = NWIN; ss = 1; }
  else {
    int b = img & 1, m = img >> 1;
    base = (size_t)b*NWIN*NWIN;
    if (m == 0){ sq = NWIN; ss = 1; } else { sq = 1; ss = NWIN; }
  }
  const float* S = g_sim + base + (size_t)q*sq;
  float v0, v1, v2, v3, v4;
  v0 = S[(size_t)(lane      )*ss];
  v1 = S[(size_t)(lane +  32)*ss];
  v2 = S[(size_t)(lane +  64)*ss];
  v3 = S[(size_t)(lane +  96)*ss];
  v4 = (lane + 128 < NWIN) ? S[(size_t)(lane + 128)*ss] : -1e30f;
  for (int k = 0; k < KSEL; k++){
    float bv = v0; int bi = lane;
    if (v1 > bv){ bv = v1; bi = lane + 32; }
    if (v2 > bv){ bv = v2; bi = lane + 64; }
    if (v3 > bv){ bv = v3; bi = lane + 96; }
    if (v4 > bv){ bv = v4; bi = lane + 128; }
    #pragma unroll
    for (int o = 16; o; o >>= 1){
      float ov = __shfl_xor_sync(0xffffffffu, bv, o);
      int   oi = __shfl_xor_sync(0xffffffffu, bi, o);
      if (ov > bv || (ov == bv && oi < bi)){ bv = ov; bi = oi; }
    }
    if (lane == 0) g_sel[gw*KSEL + k] = bi;
    int wl = bi & 31, wj = bi >> 5;
    if (lane == wl){
      if      (wj == 0) v0 = -1e30f;
      else if (wj == 1) v1 = -1e30f;
      else if (wj == 2) v2 = -1e30f;
      else if (wj == 3) v3 = -1e30f;
      else              v4 = -1e30f;
    }
  }
}

// ---------------- 5) totals over all 144 rep rows ----------------
__global__ void __launch_bounds__(256) k_reptot(){
  int img = blockIdx.x >> 3, h = blockIdx.x & 7;
  __shared__ float pk[NWIN*HD];
  __shared__ float vv[NWIN*HD];
  int tid = threadIdx.x;
  for (int i = tid; i < NWIN*HD; i += 256){
    int r = i/HD, d = i%HD;
    size_t off = ((size_t)img*NWIN + r)*D + h*HD + d;
    pk[i] = g_phikr[off]; vv[i] = g_vr[off];
  }
  __syncthreads();
  for (int o = tid; o < HD*HD; o += 256){
    int d = o/HD, j = o%HD;
    float s = 0.f;
    for (int r = 0; r < NWIN; r++) s += pk[r*HD + d]*vv[r*HD + j];
    g_KVtot[((size_t)img*NH + h)*HD*HD + o] = s;
  }
  if (tid < HD){
    float s = 0.f;
    for (int r = 0; r < NWIN; r++) s += pk[r*HD + tid];
    g_kstot[(size_t)img*D + h*HD + tid] = s;
  }
}

// ====== 3xBF16 GEMM, ldmatrix + cp.async 4-stage: C = act(A @ B^T) ==========
template<int ACT>
__device__ __forceinline__ float actf(float x){
  if (ACT == 1) return x > 0.f ? x + 1.f : expf(x); // phi = elu + 1
  if (ACT == 2) return fmaxf(x, 0.f);               // relu
  return x;
}

__device__ __forceinline__ void mma_bf16(float* d, const uint32_t* a, const uint32_t* b){
  asm volatile(
    "mma.sync.aligned.m16n8k16.row.col.f32.bf16.bf16.f32 "
    "{%0,%1,%2,%3}, {%4,%5,%6,%7}, {%8,%9}, {%0,%1,%2,%3};"
    : "+f"(d[0]), "+f"(d[1]), "+f"(d[2]), "+f"(d[3])
    : "r"(a[0]), "r"(a[1]), "r"(a[2]), "r"(a[3]), "r"(b[0]), "r"(b[1]));
}

__device__ __forceinline__ void ldsm4(uint32_t* r, uint32_t a){
  asm volatile("ldmatrix.sync.aligned.m8n8.x4.shared.b16 {%0,%1,%2,%3}, [%4];"
    : "=r"(r[0]), "=r"(r[1]), "=r"(r[2]), "=r"(r[3]) : "r"(a));
}

__device__ __forceinline__ void cp16(uint32_t s, const void* g){
  asm volatile("cp.async.cg.shared.global [%0], [%1], 16;\n" :: "r"(s), "l"(g));
}
__device__ __forceinline__ void cp_commit(){ asm volatile("cp.async.commit_group;\n"); }
template<int NG> __device__ __forceinline__ void cp_wait(){
  asm volatile("cp.async.wait_group %0;\n" :: "n"(NG));
}

#define BM 128
#define BN 128
#define BK 16
#define SPH 24           // smem row stride in halves (48B; 3 x 16B units -> LDSM conflict-free)
#define PLANE_B 6144     // bytes per plane (128*48)
#define STAGE_B 24576    // bytes per stage (4 planes: Ah, Al, Bh, Bl)
#define NSTAGE 4
#define SMEM_DYN (NSTAGE*STAGE_B)   // 98304 bytes (dynamic, opt-in)

// one cp.async stage: 256 threads x 1 chunk per plane-operand
__device__ __forceinline__ void load_stage(uint32_t sb,
    const __nv_bfloat16* __restrict__ Ah, const __nv_bfloat16* __restrict__ Al,
    const __nv_bfloat16* __restrict__ Bh, const __nv_bfloat16* __restrict__ Bl,
    size_t abase, size_t bbase, int K, int k0, int tid)
{
  int row = tid >> 1, kw = tid & 1;
  uint32_t so = (uint32_t)(row*48 + kw*16);
  size_t go = (size_t)row*K + k0 + kw*8;
  cp16(sb + 0*PLANE_B + so, Ah + abase + go);
  cp16(sb + 1*PLANE_B + so, Al + abase + go);
  cp16(sb + 2*PLANE_B + so, Bh + bbase + go);
  cp16(sb + 3*PLANE_B + so, Bl + bbase + go);
  cp_commit();
}

// OUTMODE 1: hi/lo planes -> Ch/Cl (ACT), M multiple of 128.
// OUTMODE 3: fused qkv: N=768; region by bn: q(phi)/k(phi)/v. stride 256.
// OUTMODE 4: fused rep kv: N=512; region 0 -> C0 with phi, 1 -> C1. stride 256, M-guarded.
template<int ACT, int OUTMODE>
__global__ void __launch_bounds__(256, 2)
bgemm(const __nv_bfloat16* __restrict__ Ah, const __nv_bfloat16* __restrict__ Al,
      const __nv_bfloat16* __restrict__ Bh, const __nv_bfloat16* __restrict__ Bl,
      float* __restrict__ C0, float* __restrict__ C1, float* __restrict__ C2,
      __nv_bfloat16* __restrict__ Ch, __nv_bfloat16* __restrict__ Cl,
      int M, int N, int K)
{
  extern __shared__ __align__(16) char smraw[]; // NSTAGE * 24576 dynamic
  uint32_t sb0 = (uint32_t)__cvta_generic_to_shared(smraw);
  const int tid = threadIdx.x;
  const int bm = blockIdx.y*BM, bn = blockIdx.x*BN;
  const int warp = tid >> 5, lane = tid & 31;
  const int wm = (warp >> 1)*32, wn = (warp & 1)*64;
  const int grp = lane >> 2, tig = lane & 3;
  const size_t abase = (size_t)bm*K, bbase = (size_t)bn*K;

  float acc[16][4];
  #pragma unroll
  for (int f = 0; f < 16; f++)
    #pragma unroll
    for (int r = 0; r < 4; r++) acc[f][r] = 0.f;

  const int nk = K/BK;   // >= 16 for all our shapes
  load_stage(sb0,             Ah, Al, Bh, Bl, abase, bbase, K, 0,    tid);
  load_stage(sb0 +   STAGE_B, Ah, Al, Bh, Bl, abase, bbase, K, BK,   tid);
  load_stage(sb0 + 2*STAGE_B, Ah, Al, Bh, Bl, abase, bbase, K, 2*BK, tid);

  // ldmatrix lane addresses (bytes, relative to plane base)
  const uint32_t a_lane = (uint32_t)(((wm + (lane & 15))*SPH + (lane >> 4)*8)*2);
  const uint32_t b_lane = (uint32_t)(((wn + (lane & 7) + (lane >> 4)*8)*SPH
                                      + ((lane >> 3) & 1)*8)*2);

  int stg = 0;                 // stage index of tile kt
  for (int kt = 0; kt < nk; kt++){
    int rem = nk - 1 - kt;     // loads pending beyond tile kt (capped at 3)
    if      (rem >= 3) cp_wait<3>();
    else if (rem == 2) cp_wait<2>();
    else if (rem == 1) cp_wait<1>();
    else               cp_wait<0>();
    __syncthreads();
    uint32_t sb = sb0 + (uint32_t)(stg*STAGE_B);
    if (kt + 3 < nk){
      int ns = stg + 3; if (ns >= NSTAGE) ns -= NSTAGE;
      load_stage(sb0 + (uint32_t)(ns*STAGE_B), Ah, Al, Bh, Bl,
                 abase, bbase, K, (kt + 3)*BK, tid);
    }

    uint32_t ah[2][4], al[2][4];
    ldsm4(ah[0], sb + a_lane);
    ldsm4(ah[1], sb + a_lane + 768);           // +16 rows * 48B
    ldsm4(al[0], sb + PLANE_B + a_lane);
    ldsm4(al[1], sb + PLANE_B + a_lane + 768);
    #pragma unroll
    for (int jp = 0; jp < 4; jp++){
      uint32_t bh[4], bl[4];
      ldsm4(bh, sb + 2*PLANE_B + b_lane + jp*768);
      ldsm4(bl, sb + 3*PLANE_B + b_lane + jp*768);
      #pragma unroll
      for (int i = 0; i < 2; i++)
        #pragma unroll
        for (int jj = 0; jj < 2; jj++)
          mma_bf16(acc[i*8 + jp*2 + jj], ah[i], bl + jj*2);
      #pragma unroll
      for (int i = 0; i < 2; i++)
        #pragma unroll
        for (int jj = 0; jj < 2; jj++)
          mma_bf16(acc[i*8 + jp*2 + jj], al[i], bh + jj*2);
      #pragma unroll
      for (int i = 0; i < 2; i++)
        #pragma unroll
        for (int jj = 0; jj < 2; jj++)
          mma_bf16(acc[i*8 + jp*2 + jj], ah[i], bh + jj*2);
    }
    if (++stg == NSTAGE) stg = 0;
  }

  #pragma unroll
  for (int i = 0; i < 2; i++){
    int r0 = bm + wm + i*16 + grp;
    #pragma unroll
    for (int j = 0; j < 8; j++){
      const float* dd = acc[i*8 + j];
      int cc = wn + j*8 + tig*2;
      if (OUTMODE == 1){
        int c = bn + cc;
        #pragma unroll
        for (int rr = 0; rr < 2; rr++){
          float v0 = actf<ACT>(dd[rr*2]), v1 = actf<ACT>(dd[rr*2+1]);
          __nv_bfloat162 h, l;
          h.x = __float2bfloat16(v0); h.y = __float2bfloat16(v1);
          l.x = __float2bfloat16(v0 - __bfloat162float(h.x));
          l.y = __float2bfloat16(v1 - __bfloat162float(h.y));
          size_t o = (size_t)(r0 + rr*8)*N + c;
          *(__nv_bfloat162*)&Ch[o] = h;
          *(__nv_bfloat162*)&Cl[o] = l;
        }
      } else if (OUTMODE == 3){
        int reg = bn >> 8;                   // 0:q 1:k 2:v
        float* T = (reg == 0) ? C0 : ((reg == 1) ? C1 : C2);
        int c = (bn & 255) + cc;
        float v0 = (reg < 2) ? actf<1>(dd[0]) : dd[0];
        float v1 = (reg < 2) ? actf<1>(dd[1]) : dd[1];
        float v2 = (reg < 2) ? actf<1>(dd[2]) : dd[2];
        float v3 = (reg < 2) ? actf<1>(dd[3]) : dd[3];
        T[(size_t)r0*256 + c    ] = v0;
        T[(size_t)r0*256 + c + 1] = v1;
        T[(size_t)(r0+8)*256 + c    ] = v2;
        T[(size_t)(r0+8)*256 + c + 1] = v3;
      } else { // OUTMODE 4: rep kv
        int reg = bn >> 8;                   // 0: phi(k) -> C0, 1: v -> C1
        float* T = reg ? C1 : C0;
        int c = (bn & 255) + cc;
        float v0 = reg ? dd[0] : actf<1>(dd[0]);
        float v1 = reg ? dd[1] : actf<1>(dd[1]);
        float v2 = reg ? dd[2] : actf<1>(dd[2]);
        float v3 = reg ? dd[3] : actf<1>(dd[3]);
        if (r0 < M){
          T[(size_t)r0*256 + c    ] = v0;
          T[(size_t)r0*256 + c + 1] = v1;
        }
        if (r0 + 8 < M){
          T[(size_t)(r0+8)*256 + c    ] = v2;
          T[(size_t)(r0+8)*256 + c + 1] = v3;
        }
      }
    }
  }
}

// ====== bgemm2: 64x256 tile GEMM + fused row LayerNorm epilogue =============
// N fixed = 256 (full rows per block). LNMODE 1: Y=LN(acc)->hcat msg-half.
// LNMODE 2: r=F+LN(acc)->out + feat planes + hcat feat-half.
#define BM2 64
#define BN2 256
#define PLA2 3072u      // A plane bytes (64*48)
#define PLB2 12288u     // B plane bytes (256*48)
#define STAGE2 30720u   // 2*PLA2 + 2*PLB2
#define NST2 3
#define SMEM2 (NST2*STAGE2)   // 92160

__device__ __forceinline__ void load_stage2(uint32_t sb,
    const __nv_bfloat16* __restrict__ Ah, const __nv_bfloat16* __restrict__ Al,
    const __nv_bfloat16* __restrict__ Bh, const __nv_bfloat16* __restrict__ Bl,
    size_t abase, int K, int k0, int tid)
{
  if (tid < 128){
    int row = tid >> 1, kw = tid & 1;
    uint32_t so = (uint32_t)(row*48 + kw*16);
    size_t go = (size_t)row*K + k0 + kw*8;
    cp16(sb + so, Ah + abase + go);
    cp16(sb + PLA2 + so, Al + abase + go);
  }
  #pragma unroll
  for (int c = 0; c < 2; c++){
    int idx = tid*2 + c;
    int row = idx >> 1, kw = idx & 1;
    uint32_t so = (uint32_t)(row*48 + kw*16);
    size_t go = (size_t)row*K + k0 + kw*8;
    cp16(sb + 2*PLA2 + so, Bh + go);
    cp16(sb + 2*PLA2 + PLB2 + so, Bl + go);
  }
  cp_commit();
}

template<int LNMODE>
__global__ void __launch_bounds__(256, 2)
bgemm2(const __nv_bfloat16* __restrict__ Ah, const __nv_bfloat16* __restrict__ Al,
       const __nv_bfloat16* __restrict__ Bh, const __nv_bfloat16* __restrict__ Bl,
       const float* __restrict__ f0, const float* __restrict__ f1,
       float* __restrict__ outp,
       const float* __restrict__ G, const float* __restrict__ Bt,
       int K)
{
  extern __shared__ __align__(16) char smraw[]; // NST2*STAGE2 dynamic
  uint32_t sb0 = (uint32_t)__cvta_generic_to_shared(smraw);
  const int tid = threadIdx.x;
  const int bm = blockIdx.y*BM2;
  const int warp = tid >> 5, lane = tid & 31;
  const int wm = (warp >> 2)*32, wn = (warp & 3)*64;
  const int grp = lane >> 2, tig = lane & 3;
  const size_t abase = (size_t)bm*K;

  float acc[16][4];
  #pragma unroll
  for (int f = 0; f < 16; f++)
    #pragma unroll
    for (int r = 0; r < 4; r++) acc[f][r] = 0.f;

  const int nk = K/BK;
  load_stage2(sb0,          Ah, Al, Bh, Bl, abase, K, 0,  tid);
  load_stage2(sb0 + STAGE2, Ah, Al, Bh, Bl, abase, K, BK, tid);

  const uint32_t a_lane = (uint32_t)(((wm + (lane & 15))*SPH + (lane >> 4)*8)*2);
  const uint32_t b_lane = (uint32_t)(((wn + (lane & 7) + (lane >> 4)*8)*SPH
                                      + ((lane >> 3) & 1)*8)*2);

  int stg = 0;
  for (int kt = 0; kt < nk; kt++){
    if (kt + 1 < nk) cp_wait<1>(); else cp_wait<0>();
    __syncthreads();
    uint32_t sb = sb0 + (uint32_t)(stg*STAGE2);
    if (kt + 2 < nk){
      int ns = stg + 2; if (ns >= NST2) ns -= NST2;
      load_stage2(sb0 + (uint32_t)(ns*STAGE2), Ah, Al, Bh, Bl,
                  abase, K, (kt + 2)*BK, tid);
    }
    uint32_t ah[2][4], al[2][4];
    ldsm4(ah[0], sb + a_lane);
    ldsm4(ah[1], sb + a_lane + 768);
    ldsm4(al[0], sb + PLA2 + a_lane);
    ldsm4(al[1], sb + PLA2 + a_lane + 768);
    #pragma unroll
    for (int jp = 0; jp < 4; jp++){
      uint32_t bh[4], bl[4];
      ldsm4(bh, sb + 2*PLA2 + b_lane + jp*768);
      ldsm4(bl, sb + 2*PLA2 + PLB2 + b_lane + jp*768);
      #pragma unroll
      for (int i = 0; i < 2; i++)
        #pragma unroll
        for (int jj = 0; jj < 2; jj++){
          float* dd = acc[i*8 + jp*2 + jj];
          mma_bf16(dd, ah[i], bl + jj*2);
          mma_bf16(dd, al[i], bh + jj*2);
          mma_bf16(dd, ah[i], bh + jj*2);
        }
    }
    if (++stg == NST2) stg = 0;
  }

  // ---- fused LN epilogue ----
  __syncthreads();                     // all warps done with smem stages
  float* sf  = (float*)smraw;          // 64 x 260 fp32 tile
  float* sg  = sf + 64*260;
  float* sbv = sg + 256;
  sg[tid]  = G[tid];
  sbv[tid] = Bt[tid];
  #pragma unroll
  for (int i = 0; i < 2; i++){
    int rl = wm + i*16 + grp;
    #pragma unroll
    for (int j = 0; j < 8; j++){
      const float* dd = acc[i*8 + j];
      int c = wn + j*8 + tig*2;
      sf[rl*260 + c]       = dd[0];
      sf[rl*260 + c + 1]   = dd[1];
      sf[(rl+8)*260 + c]     = dd[2];
      sf[(rl+8)*260 + c + 1] = dd[3];
    }
  }
  __syncthreads();

  #pragma unroll
  for (int rr = 0; rr < 8; rr++){
    int r = warp*8 + rr;
    size_t grow = (size_t)(bm + r);
    float v[8];
    float s = 0.f;
    #pragma unroll
    for (int k = 0; k < 8; k++){ v[k] = sf[r*260 + lane + k*32]; s += v[k]; }
    #pragma unroll
    for (int o = 16; o; o >>= 1) s += __shfl_xor_sync(0xffffffffu, s, o);
    float mu = s * (1.f/256.f);
    float s2 = 0.f;
    #pragma unroll
    for (int k = 0; k < 8; k++){ v[k] -= mu; s2 += v[k]*v[k]; }
    #pragma unroll
    for (int o = 16; o; o >>= 1) s2 += __shfl_xor_sync(0xffffffffu, s2, o);
    float rs = rsqrtf(s2*(1.f/256.f) + 1e-5f);
    #pragma unroll
    for (int k = 0; k < 8; k++){
      int c = lane + k*32;
      float y = v[k]*rs*sg[c] + sbv[c];
      if (LNMODE == 1){
        size_t ho = (grow << 9) + 256 + c;
        split_bf16(y, b_hcat_hi[ho], b_hcat_lo[ho]);
      } else {
        float Fv = (grow < (size_t)2*LTOK)
                 ? f0[grow*256 + c]
                 : f1[(grow - (size_t)2*LTOK)*256 + c];
        float rv = Fv + y;
        size_t oi = grow*256 + c;
        outp[oi] = rv;
        __nv_bfloat16 h, lo;
        split_bf16(rv, h, lo);
        b_feat_hi[oi] = h; b_feat_lo[oi] = lo;
        size_t ho = (grow << 9) + c;
        b_hcat_hi[ho] = h; b_hcat_lo[ho] = lo;
      }
    }
  }
}

// ---------------- 6) per-window KV/ksum aggregates (vectorized) -------------
__global__ void __launch_bounds__(256) k_winagg(){
  int bid = blockIdx.x;
  int h = bid & 7; int wv = bid >> 3;
  int win = wv % NWIN, img = wv / NWIN;
  __shared__ float pk[WTOK*HD];
  __shared__ float vv[WTOK*HD];
  int tid = threadIdx.x;
  #pragma unroll
  for (int i = tid; i < WTOK*HD/4; i += 256){
    int t = i >> 3, d4 = (i & 7)*4;
    int l = spatial_l(win, t);
    size_t off = ((size_t)img*LTOK + l)*D + h*HD + d4;
    *(float4*)&pk[t*HD + d4] = *(const float4*)&g_phi_k[off];
    *(float4*)&vv[t*HD + d4] = *(const float4*)&g_v[off];
  }
  __syncthreads();
  int d = tid >> 3, j0 = (tid & 7)*4;
  float a0 = 0.f, a1 = 0.f, a2 = 0.f, a3 = 0.f;
  #pragma unroll 8
  for (int t = 0; t < WTOK; t++){
    float p = pk[t*HD + d];
    float4 v4 = *(const float4*)&vv[t*HD + j0];
    a0 += p*v4.x; a1 += p*v4.y; a2 += p*v4.z; a3 += p*v4.w;
  }
  size_t ob = (((size_t)(img*NWIN + win))*NH + h)*HD*HD + (size_t)d*HD + j0;
  *(float4*)&g_KVwin[ob] = make_float4(a0, a1, a2, a3);
  if (tid < HD){
    float s = 0.f;
    for (int t = 0; t < WTOK; t++) s += pk[t*HD + tid];
    g_kswin[((size_t)img*NWIN + win)*D + h*HD + tid] = s;
  }
}

// ---------------- 7) attention: register-resident KV build + apply ----------
__global__ void __launch_bounds__(256) k_attn(int layer){
  int img = blockIdx.x / NWIN, q = blockIdx.x % NWIN;
  int src = (layer == 0) ? img : (img ^ 2); // cross: flip map, keep batch
  __shared__ float bufpk[KSEL][D]; // 8KB
  __shared__ float bufv [KSEL][D]; // 8KB
  __shared__ int   wsel[KSEL];
  int tid = threadIdx.x;
  if (tid < KSEL) wsel[tid] = g_sel[(img*NWIN + q)*KSEL + tid];
  __syncthreads();
  #pragma unroll
  for (int k = 0; k < KSEL; k++){
    int w = wsel[k];
    bufpk[k][tid] = g_phikr[((size_t)src*NWIN + w)*D + tid];
    bufv [k][tid] = g_vr   [((size_t)src*NWIN + w)*D + tid];
  }
  __syncthreads();

  int h = tid >> 5, lane = tid & 31;
  float kvreg[32];
  const float* KVT = g_KVtot + (size_t)src*NH*HD*HD + h*HD*HD;
  #pragma unroll
  for (int d = 0; d < 32; d++) kvreg[d] = KVT[d*HD + lane];
  float ksv = g_kstot[(size_t)src*D + h*HD + lane];
  for (int k = 0; k < KSEL; k++){
    int w = wsel[k];
    const float* KVW = g_KVwin + ((size_t)(src*NWIN + w))*NH*HD*HD + h*HD*HD;
    float vj = bufv[k][h*HD + lane];
    #pragma unroll
    for (int d = 0; d < 32; d++)
      kvreg[d] += KVW[d*HD + lane] - bufpk[k][h*HD + d]*vj;
    ksv += g_kswin[((size_t)src*NWIN + w)*D + h*HD + lane] - bufpk[k][h*HD + lane];
  }

  const float* pqb = g_phi_q + (size_t)img*LTOK*D + h*HD + lane;
  for (int t = 0; t < WTOK; t++){
    int l = spatial_l(q, t);
    float pqv = __ldg(pqb + (size_t)l*D);
    float n0 = 0.f, n1 = 0.f, n2 = 0.f, n3 = 0.f;
    #pragma unroll
    for (int d = 0; d < 32; d += 4){
      float p0 = __shfl_sync(0xffffffffu, pqv, d    );
      float p1 = __shfl_sync(0xffffffffu, pqv, d + 1);
      float p2 = __shfl_sync(0xffffffffu, pqv, d + 2);
      float p3 = __shfl_sync(0xffffffffu, pqv, d + 3);
      n0 += p0*kvreg[d];   n1 += p1*kvreg[d+1];
      n2 += p2*kvreg[d+2]; n3 += p3*kvreg[d+3];
    }
    float num = (n0 + n1) + (n2 + n3);
    float dv = pqv*ksv;
    #pragma unroll
    for (int o = 16; o; o >>= 1) dv += __shfl_xor_sync(0xffffffffu, dv, o);
    float r = num / (dv + 1e-6f);
    size_t oi = ((size_t)img*LTOK + l)*D + h*HD + lane;
    split_bf16(r, b_msg_hi[oi], b_msg_lo[oi]);
  }
}

// ---------------- host ----------------
extern "C" void kernel_launch(void* const* d_in, const int* in_sizes, int n_in,
                              void* d_out, int out_size){
  (void)in_sizes; (void)n_in; (void)out_size;
  const float* feat0 = (const float*)d_in[0];
  const float* feat1 = (const float*)d_in[1];
  const float* qW    = (const float*)d_in[8];
  const float* kW    = (const float*)d_in[9];
  const float* vW    = (const float*)d_in[10];
  const float* mW    = (const float*)d_in[11];
  const float* mlpW1 = (const float*)d_in[12];
  const float* mlpW2 = (const float*)d_in[13];
  const float* n1g   = (const float*)d_in[14];
  const float* n1b   = (const float*)d_in[15];
  const float* n2g   = (const float*)d_in[16];
  const float* n2b   = (const float*)d_in[17];
  const float* conv_w= (const float*)d_in[18];
  float* out = (float*)d_out;

  cudaFuncSetAttribute((const void*)bgemm<0,3>, cudaFuncAttributeMaxDynamicSharedMemorySize, SMEM_DYN);
  cudaFuncSetAttribute((const void*)bgemm<0,4>, cudaFuncAttributeMaxDynamicSharedMemorySize, SMEM_DYN);
  cudaFuncSetAttribute((const void*)bgemm<2,1>, cudaFuncAttributeMaxDynamicSharedMemorySize, SMEM_DYN);
  cudaFuncSetAttribute((const void*)bgemm2<1>, cudaFuncAttributeMaxDynamicSharedMemorySize, SMEM2);
  cudaFuncSetAttribute((const void*)bgemm2<2>, cudaFuncAttributeMaxDynamicSharedMemorySize, SMEM2);

  float *p_phiq, *p_phik, *p_v, *p_phikr, *p_vr;
  __nv_bfloat16 *p_fh, *p_fl, *p_rh, *p_rl, *p_mh, *p_ml, *p_ch, *p_cl,
                *p_hh, *p_hl, *p_wh, *p_wl;
  cudaGetSymbolAddress((void**)&p_phiq, g_phi_q);
  cudaGetSymbolAddress((void**)&p_phik, g_phi_k);
  cudaGetSymbolAddress((void**)&p_v,    g_v);
  cudaGetSymbolAddress((void**)&p_phikr,g_phikr);
  cudaGetSymbolAddress((void**)&p_vr,   g_vr);
  cudaGetSymbolAddress((void**)&p_fh, b_feat_hi); cudaGetSymbolAddress((void**)&p_fl, b_feat_lo);
  cudaGetSymbolAddress((void**)&p_rh, b_rep_hi);  cudaGetSymbolAddress((void**)&p_rl, b_rep_lo);
  cudaGetSymbolAddress((void**)&p_mh, b_msg_hi);  cudaGetSymbolAddress((void**)&p_ml, b_msg_lo);
  cudaGetSymbolAddress((void**)&p_ch, b_hcat_hi); cudaGetSymbolAddress((void**)&p_cl, b_hcat_lo);
  cudaGetSymbolAddress((void**)&p_hh, b_hid_hi);  cudaGetSymbolAddress((void**)&p_hl, b_hid_lo);
  cudaGetSymbolAddress((void**)&p_wh, b_w_hi);    cudaGetSymbolAddress((void**)&p_wl, b_w_lo);

  const int Mall = NIMG*LTOK;   // 36864
  const int Mrep = NIMG*NWIN;   // 576 (buffers padded to 640)

  // convert BOTH layers' weights once
  k_convw<<<1280, 256>>>(qW, kW, vW, mW, mlpW1, mlpW2);

  for (int layer = 0; layer < 2; layer++){
    const float* F0 = layer ? out : feat0;
    const float* F1 = layer ? out + (size_t)2*LTOK*D : feat1;
    int self = (layer == 0);
    int npairs = self ? NIMG : 2;
    const size_t wofs = (size_t)layer*WTOT;

    if (layer == 0) k_convfeat<<<4096, 256>>>(feat0, feat1);

    k_rep<<<NIMG*NWIN, 256>>>(F0, F1, conv_w);
    {
      int total = npairs*(NWIN/2)*(NWIN/2);
      k_cossim<<<(total + 255)/256, 256>>>(npairs, self);
    }
    k_topk<<<(NIMG*NWIN*32 + 255)/256, 256>>>(self);

    // fused rep k/v projection (N=512, rows padded to 640)
    bgemm<0,4><<<dim3(4, NREPAD/BM), 256, SMEM_DYN>>>(p_rh, p_rl,
                                            p_wh + wofs + WOK, p_wl + wofs + WOK,
                                            p_phikr, p_vr, nullptr, nullptr, nullptr,
                                            Mrep, 512, D);
    k_reptot<<<NIMG*NH, 256>>>();

    // fused q/k/v projection over ALL images (M=36864, N=768)
    bgemm<0,3><<<dim3(6, Mall/BM), 256, SMEM_DYN>>>(p_fh, p_fl,
                                          p_wh + wofs + WOQ, p_wl + wofs + WOQ,
                                          p_phiq, p_phik, p_v, nullptr, nullptr,
                                          Mall, 3*D, D);

    k_winagg<<<NIMG*NWIN*NH, 256>>>();
    k_attn<<<NIMG*NWIN, 256>>>(layer);

    // mW GEMM + LN1 + hcat msg-half (fused)
    bgemm2<1><<<dim3(1, Mall/BM2), 256, SMEM2>>>(p_mh, p_ml,
                                          p_wh + wofs + WOM, p_wl + wofs + WOM,
                                          nullptr, nullptr, nullptr,
                                          n1g + layer*D, n1b + layer*D, D);

    // MLP1 (relu -> hid planes)
    bgemm<2,1><<<dim3(4, Mall/BM), 256, SMEM_DYN>>>(p_ch, p_cl,
                                          p_wh + wofs + WO1, p_wl + wofs + WO1,
                                          nullptr, nullptr, nullptr, p_hh, p_hl,
                                          Mall, 2*D, 2*D);
    // MLP2 GEMM + LN2 + residual + out/feat/hcat planes (fused)
    bgemm2<2><<<dim3(1, Mall/BM2), 256, SMEM2>>>(p_hh, p_hl,
                                          p_wh + wofs + WO2, p_wl + wofs + WO2,
                                          F0, F1, out,
                                          n2g + layer*D, n2b + layer*D, 2*D);
  }
}